// round 2
// baseline (speedup 1.0000x reference)
#include <cuda_runtime.h>
#include <math.h>

#define TT 2048
#define DM 768
#define NH 12
#define DH 64
#define DHID 3072

// ---------------- scratch (device globals; no allocation) ----------------
__device__ float g_h[TT * DM];
__device__ float g_q[TT * DM];
__device__ float g_k[TT * DM];
__device__ float g_q2[TT * DM];
__device__ float g_k2[TT * DM];
__device__ float g_v[TT * DM];
__device__ float g_z[TT * DM];
__device__ float g_x1[TT * DM];
__device__ float g_h2[TT * DM];
__device__ float g_hidden[TT * DHID];

// ---------------- RMSNorm ----------------
__global__ void rmsnorm_kernel(const float* __restrict__ x, float* __restrict__ o) {
    int row = blockIdx.x;
    const float* xr = x + row * DM;
    float s = 0.f;
    for (int i = threadIdx.x; i < DM; i += blockDim.x) {
        float v = xr[i];
        s += v * v;
    }
    __shared__ float red[32];
    for (int off = 16; off; off >>= 1) s += __shfl_down_sync(0xffffffffu, s, off);
    if ((threadIdx.x & 31) == 0) red[threadIdx.x >> 5] = s;
    __syncthreads();
    if (threadIdx.x < 32) {
        s = (threadIdx.x < (blockDim.x >> 5)) ? red[threadIdx.x] : 0.f;
        for (int off = 16; off; off >>= 1) s += __shfl_down_sync(0xffffffffu, s, off);
        if (threadIdx.x == 0) red[0] = rsqrtf(s / (float)DM + 1e-6f);
    }
    __syncthreads();
    float scale = red[0];
    for (int i = threadIdx.x; i < DM; i += blockDim.x) o[row * DM + i] = xr[i] * scale;
}

// ---------------- GEMM NT: C[M,N] = A[M,K] @ B[N,K]^T (+res +bias) ----------------
// BM=BN=64, BK=16, 256 threads, 4x4 microtile per thread.
__global__ void gemm_nt(const float* __restrict__ A, const float* __restrict__ B,
                        float* __restrict__ C, int M, int N, int K,
                        const float* __restrict__ res, const float* __restrict__ bias) {
    __shared__ float As[16][68];
    __shared__ float Bs[16][68];
    int bm = blockIdx.y * 64, bn = blockIdx.x * 64;
    int tid = threadIdx.x;
    int ty = tid >> 4, tx = tid & 15;
    float acc[4][4] = {};
    for (int k0 = 0; k0 < K; k0 += 16) {
        #pragma unroll
        for (int i = tid; i < 64 * 16; i += 256) {
            int m = i >> 4, kk = i & 15;
            As[kk][m] = A[(size_t)(bm + m) * K + k0 + kk];
        }
        #pragma unroll
        for (int i = tid; i < 64 * 16; i += 256) {
            int n = i >> 4, kk = i & 15;
            Bs[kk][n] = B[(size_t)(bn + n) * K + k0 + kk];
        }
        __syncthreads();
        #pragma unroll
        for (int kk = 0; kk < 16; kk++) {
            float a[4], b[4];
            #pragma unroll
            for (int i = 0; i < 4; i++) a[i] = As[kk][ty * 4 + i];
            #pragma unroll
            for (int j = 0; j < 4; j++) b[j] = Bs[kk][tx * 4 + j];
            #pragma unroll
            for (int i = 0; i < 4; i++)
                #pragma unroll
                for (int j = 0; j < 4; j++) acc[i][j] += a[i] * b[j];
        }
        __syncthreads();
    }
    #pragma unroll
    for (int i = 0; i < 4; i++) {
        int m = bm + ty * 4 + i;
        #pragma unroll
        for (int j = 0; j < 4; j++) {
            int n = bn + tx * 4 + j;
            float val = acc[i][j];
            if (res) val += res[(size_t)m * N + n];
            if (bias) val += bias[n];
            C[(size_t)m * N + n] = val;
        }
    }
}

// ---------------- fused dual GEMM + gate: C = (A@B1^T) * (A@B2^T) ----------------
__global__ void gemm_nt_dual(const float* __restrict__ A, const float* __restrict__ B1,
                             const float* __restrict__ B2, float* __restrict__ C,
                             int M, int N, int K) {
    __shared__ float As[16][68];
    __shared__ float B1s[16][68];
    __shared__ float B2s[16][68];
    int bm = blockIdx.y * 64, bn = blockIdx.x * 64;
    int tid = threadIdx.x;
    int ty = tid >> 4, tx = tid & 15;
    float acc1[4][4] = {};
    float acc2[4][4] = {};
    for (int k0 = 0; k0 < K; k0 += 16) {
        #pragma unroll
        for (int i = tid; i < 64 * 16; i += 256) {
            int m = i >> 4, kk = i & 15;
            As[kk][m] = A[(size_t)(bm + m) * K + k0 + kk];
            B1s[kk][m] = B1[(size_t)(bn + m) * K + k0 + kk];
            B2s[kk][m] = B2[(size_t)(bn + m) * K + k0 + kk];
        }
        __syncthreads();
        #pragma unroll
        for (int kk = 0; kk < 16; kk++) {
            float a[4], b1[4], b2[4];
            #pragma unroll
            for (int i = 0; i < 4; i++) a[i] = As[kk][ty * 4 + i];
            #pragma unroll
            for (int j = 0; j < 4; j++) { b1[j] = B1s[kk][tx * 4 + j]; b2[j] = B2s[kk][tx * 4 + j]; }
            #pragma unroll
            for (int i = 0; i < 4; i++)
                #pragma unroll
                for (int j = 0; j < 4; j++) {
                    acc1[i][j] += a[i] * b1[j];
                    acc2[i][j] += a[i] * b2[j];
                }
        }
        __syncthreads();
    }
    #pragma unroll
    for (int i = 0; i < 4; i++) {
        int m = bm + ty * 4 + i;
        #pragma unroll
        for (int j = 0; j < 4; j++) {
            int n = bn + tx * 4 + j;
            C[(size_t)m * N + n] = acc1[i][j] * acc2[i][j];
        }
    }
}

// ---------------- RoPE (in place on q,k,q2,k2) ----------------
__global__ void rope_kernel(float* __restrict__ q, float* __restrict__ k,
                            float* __restrict__ q2, float* __restrict__ k2) {
    int idx = blockIdx.x * blockDim.x + threadIdx.x;
    if (idx >= TT * 32) return;
    int t = idx >> 5, i = idx & 31;
    float inv = powf(10000.f, -(float)(2 * i) / 64.f);
    float ang = (float)t * inv;
    float c = cosf(ang), s = sinf(ang);
    #pragma unroll
    for (int h = 0; h < NH; h++) {
        int base = t * DM + h * DH;
        {
            float a = q[base + i], b = q[base + 32 + i];
            q[base + i] = a * c + b * s;
            q[base + 32 + i] = -a * s + b * c;
        }
        {
            float a = k[base + i], b = k[base + 32 + i];
            k[base + i] = a * c + b * s;
            k[base + 32 + i] = -a * s + b * c;
        }
        {
            float a = q2[base + i], b = q2[base + 32 + i];
            q2[base + i] = a * c + b * s;
            q2[base + 32 + i] = -a * s + b * c;
        }
        {
            float a = k2[base + i], b = k2[base + 32 + i];
            k2[base + i] = a * c + b * s;
            k2[base + 32 + i] = -a * s + b * c;
        }
    }
}

// ---------------- attention: z = causal[(qk^T/Dh)*(q2k2^T/Dh)] @ v ----------------
#define SSTR 68
#define ATTN_SMEM (6 * 64 * SSTR * 4)
__global__ void attn_kernel(const float* __restrict__ q, const float* __restrict__ k,
                            const float* __restrict__ q2, const float* __restrict__ k2,
                            const float* __restrict__ v, float* __restrict__ z) {
    extern __shared__ float sm[];
    float* qs = sm;                  // 64 x SSTR
    float* q2s = qs + 64 * SSTR;
    float* ks = q2s + 64 * SSTR;
    float* k2s = ks + 64 * SSTR;
    float* vs = k2s + 64 * SSTR;
    float* ps = vs + 64 * SSTR;
    int hd = blockIdx.y;
    int qt = blockIdx.x;
    int tid = threadIdx.x;
    int ty = tid >> 4, tx = tid & 15;

    for (int i = tid; i < 64 * 64; i += 256) {
        int r = i >> 6, d = i & 63;
        int gidx = (qt * 64 + r) * DM + hd * DH + d;
        qs[r * SSTR + d] = q[gidx];
        q2s[r * SSTR + d] = q2[gidx];
    }
    float zacc[4][4] = {};
    for (int st = 0; st <= qt; st++) {
        __syncthreads();
        for (int i = tid; i < 64 * 64; i += 256) {
            int r = i >> 6, d = i & 63;
            int gidx = (st * 64 + r) * DM + hd * DH + d;
            ks[r * SSTR + d] = k[gidx];
            k2s[r * SSTR + d] = k2[gidx];
            vs[r * SSTR + d] = v[gidx];
        }
        __syncthreads();
        // P = (qs.ks^T)*(q2s.k2s^T)/4096, causal-masked
        float s1a[4][4] = {};
        float s2a[4][4] = {};
        #pragma unroll 8
        for (int d = 0; d < 64; d++) {
            float a1[4], a2[4], b1[4], b2[4];
            #pragma unroll
            for (int i = 0; i < 4; i++) {
                a1[i] = qs[(ty * 4 + i) * SSTR + d];
                a2[i] = q2s[(ty * 4 + i) * SSTR + d];
            }
            #pragma unroll
            for (int j = 0; j < 4; j++) {
                b1[j] = ks[(tx * 4 + j) * SSTR + d];
                b2[j] = k2s[(tx * 4 + j) * SSTR + d];
            }
            #pragma unroll
            for (int i = 0; i < 4; i++)
                #pragma unroll
                for (int j = 0; j < 4; j++) {
                    s1a[i][j] += a1[i] * b1[j];
                    s2a[i][j] += a2[i] * b2[j];
                }
        }
        #pragma unroll
        for (int i = 0; i < 4; i++)
            #pragma unroll
            for (int j = 0; j < 4; j++) {
                int qr = ty * 4 + i, sc = tx * 4 + j;
                float p = s1a[i][j] * s2a[i][j] * (1.f / 4096.f);
                if (st == qt && sc > qr) p = 0.f;
                ps[qr * SSTR + sc] = p;
            }
        __syncthreads();
        // zacc += P @ V
        #pragma unroll 8
        for (int kk = 0; kk < 64; kk++) {
            float pv[4], vv[4];
            #pragma unroll
            for (int i = 0; i < 4; i++) pv[i] = ps[(ty * 4 + i) * SSTR + kk];
            #pragma unroll
            for (int j = 0; j < 4; j++) vv[j] = vs[kk * SSTR + tx * 4 + j];
            #pragma unroll
            for (int i = 0; i < 4; i++)
                #pragma unroll
                for (int j = 0; j < 4; j++) zacc[i][j] += pv[i] * vv[j];
        }
    }
    #pragma unroll
    for (int i = 0; i < 4; i++)
        #pragma unroll
        for (int j = 0; j < 4; j++) {
            int r = qt * 64 + ty * 4 + i, d = tx * 4 + j;
            z[r * DM + hd * DH + d] = zacc[i][j];
        }
}

// ---------------- launch ----------------
extern "C" void kernel_launch(void* const* d_in, const int* in_sizes, int n_in,
                              void* d_out, int out_size) {
    const float* x = (const float*)d_in[0];
    const float* Wq = (const float*)d_in[1];
    const float* Wk = (const float*)d_in[2];
    const float* Wq2 = (const float*)d_in[3];
    const float* Wk2 = (const float*)d_in[4];
    const float* Wv = (const float*)d_in[5];
    const float* Wo = (const float*)d_in[6];
    const float* Wp1 = (const float*)d_in[7];
    const float* Wp2 = (const float*)d_in[8];
    const float* Wd = (const float*)d_in[9];
    const float* bd = (const float*)d_in[10];

    float *h, *q, *k, *q2, *k2, *v, *z, *x1, *h2, *hidden;
    cudaGetSymbolAddress((void**)&h, g_h);
    cudaGetSymbolAddress((void**)&q, g_q);
    cudaGetSymbolAddress((void**)&k, g_k);
    cudaGetSymbolAddress((void**)&q2, g_q2);
    cudaGetSymbolAddress((void**)&k2, g_k2);
    cudaGetSymbolAddress((void**)&v, g_v);
    cudaGetSymbolAddress((void**)&z, g_z);
    cudaGetSymbolAddress((void**)&x1, g_x1);
    cudaGetSymbolAddress((void**)&h2, g_h2);
    cudaGetSymbolAddress((void**)&hidden, g_hidden);

    cudaFuncSetAttribute(attn_kernel, cudaFuncAttributeMaxDynamicSharedMemorySize, ATTN_SMEM);

    // 1. rmsnorm
    rmsnorm_kernel<<<TT, 256>>>(x, h);

    // 2. five projections
    dim3 g12(DM / 64, TT / 64);
    gemm_nt<<<g12, 256>>>(h, Wq, q, TT, DM, DM, nullptr, nullptr);
    gemm_nt<<<g12, 256>>>(h, Wk, k, TT, DM, DM, nullptr, nullptr);
    gemm_nt<<<g12, 256>>>(h, Wq2, q2, TT, DM, DM, nullptr, nullptr);
    gemm_nt<<<g12, 256>>>(h, Wk2, k2, TT, DM, DM, nullptr, nullptr);
    gemm_nt<<<g12, 256>>>(h, Wv, v, TT, DM, DM, nullptr, nullptr);

    // 3. rope
    rope_kernel<<<(TT * 32 + 255) / 256, 256>>>(q, k, q2, k2);

    // 4. attention
    attn_kernel<<<dim3(TT / 64, NH), 256, ATTN_SMEM>>>(q, k, q2, k2, v, z);

    // 5. Wo + residual
    gemm_nt<<<g12, 256>>>(z, Wo, x1, TT, DM, DM, x, nullptr);

    // 6. rmsnorm 2
    rmsnorm_kernel<<<TT, 256>>>(x1, h2);

    // 7. gated MLP up (fused dual GEMM + multiply)
    gemm_nt_dual<<<dim3(DHID / 64, TT / 64), 256>>>(h2, Wp1, Wp2, hidden, TT, DHID, DM);

    // 8. down proj + residual + bias -> out
    gemm_nt<<<g12, 256>>>(hidden, Wd, (float*)d_out, TT, DM, DHID, x1, bd);
}

// round 3
// speedup vs baseline: 3.9796x; 3.9796x over previous
#include <cuda_runtime.h>
#include <cstdint>
#include <math.h>

#define TT 2048
#define DM 768
#define NH 12
#define DH 64
#define DHID 3072

// ---------------- scratch ----------------
__device__ float g_h[TT * DM];
__device__ float g_q[TT * DM];
__device__ float g_k[TT * DM];
__device__ float g_q2[TT * DM];
__device__ float g_k2[TT * DM];
__device__ float g_v[TT * DM];
__device__ float g_z[TT * DM];
__device__ float g_x1[TT * DM];
__device__ float g_h2[TT * DM];
__device__ float g_hidden[TT * DHID];

// ---------------- helpers ----------------
__device__ __forceinline__ uint32_t f2tf(float x) {
    uint32_t u;
    asm("cvt.rna.tf32.f32 %0, %1;" : "=r"(u) : "f"(x));
    return u;
}
__device__ __forceinline__ uint4 f4tf(float4 v) {
    uint4 r;
    r.x = f2tf(v.x); r.y = f2tf(v.y); r.z = f2tf(v.z); r.w = f2tf(v.w);
    return r;
}
__device__ __forceinline__ void mma8(float* d, const uint32_t* a, const uint32_t* b) {
    asm volatile(
        "mma.sync.aligned.m16n8k8.row.col.f32.tf32.tf32.f32 "
        "{%0,%1,%2,%3},{%4,%5,%6,%7},{%8,%9},{%0,%1,%2,%3};\n"
        : "+f"(d[0]), "+f"(d[1]), "+f"(d[2]), "+f"(d[3])
        : "r"(a[0]), "r"(a[1]), "r"(a[2]), "r"(a[3]), "r"(b[0]), "r"(b[1]));
}

// ---------------- RMSNorm ----------------
__global__ void rmsnorm_kernel(const float* __restrict__ x, float* __restrict__ o) {
    int row = blockIdx.x;
    const float* xr = x + row * DM;
    float s = 0.f;
    for (int i = threadIdx.x; i < DM; i += blockDim.x) { float v = xr[i]; s += v * v; }
    __shared__ float red[32];
    for (int off = 16; off; off >>= 1) s += __shfl_down_sync(0xffffffffu, s, off);
    if ((threadIdx.x & 31) == 0) red[threadIdx.x >> 5] = s;
    __syncthreads();
    if (threadIdx.x < 32) {
        s = (threadIdx.x < (blockDim.x >> 5)) ? red[threadIdx.x] : 0.f;
        for (int off = 16; off; off >>= 1) s += __shfl_down_sync(0xffffffffu, s, off);
        if (threadIdx.x == 0) red[0] = rsqrtf(s / (float)DM + 1e-6f);
    }
    __syncthreads();
    float scale = red[0];
    for (int i = threadIdx.x; i < DM; i += blockDim.x) o[row * DM + i] = xr[i] * scale;
}

// ---------------- generic tf32 GEMM NT: C = A[M,K] @ B[N,K]^T (+res +bias) ----------------
// BM=128 BN=64 BK=32, 256 threads, 8 warps (4x2), warp tile 32x32.
#define SA 36
__global__ __launch_bounds__(256) void gemm_tf32(
    const float* __restrict__ A, const float* __restrict__ B, float* __restrict__ C,
    int M, int N, int K, const float* __restrict__ res, const float* __restrict__ bias) {
    __shared__ uint32_t As[128 * SA];
    __shared__ uint32_t Bs[64 * SA];
    int bm = blockIdx.y * 128, bn = blockIdx.x * 64;
    int tid = threadIdx.x, wid = tid >> 5, lane = tid & 31;
    int g = lane >> 2, t = lane & 3;
    int wm = (wid & 3) * 32, wn = (wid >> 2) * 32;
    float acc[2][4][4] = {};
    for (int k0 = 0; k0 < K; k0 += 32) {
        #pragma unroll
        for (int i = tid; i < 1024; i += 256) {
            int r = i >> 3, kv = (i & 7) * 4;
            float4 v = *(const float4*)(A + (size_t)(bm + r) * K + k0 + kv);
            *(uint4*)(As + r * SA + kv) = f4tf(v);
        }
        #pragma unroll
        for (int i = tid; i < 512; i += 256) {
            int r = i >> 3, kv = (i & 7) * 4;
            float4 v = *(const float4*)(B + (size_t)(bn + r) * K + k0 + kv);
            *(uint4*)(Bs + r * SA + kv) = f4tf(v);
        }
        __syncthreads();
        #pragma unroll
        for (int kk = 0; kk < 4; kk++) {
            int kb = kk * 8;
            uint32_t af[2][4], bf[4][2];
            #pragma unroll
            for (int mt = 0; mt < 2; mt++) {
                int r0 = wm + mt * 16 + g;
                af[mt][0] = As[r0 * SA + kb + t];
                af[mt][1] = As[(r0 + 8) * SA + kb + t];
                af[mt][2] = As[r0 * SA + kb + t + 4];
                af[mt][3] = As[(r0 + 8) * SA + kb + t + 4];
            }
            #pragma unroll
            for (int nt = 0; nt < 4; nt++) {
                int c0 = wn + nt * 8 + g;
                bf[nt][0] = Bs[c0 * SA + kb + t];
                bf[nt][1] = Bs[c0 * SA + kb + t + 4];
            }
            #pragma unroll
            for (int mt = 0; mt < 2; mt++)
                #pragma unroll
                for (int nt = 0; nt < 4; nt++) mma8(acc[mt][nt], af[mt], bf[nt]);
        }
        __syncthreads();
    }
    #pragma unroll
    for (int mt = 0; mt < 2; mt++)
        #pragma unroll
        for (int nt = 0; nt < 4; nt++)
            #pragma unroll
            for (int rg = 0; rg < 4; rg++) {
                int r = bm + wm + mt * 16 + g + ((rg >= 2) ? 8 : 0);
                int c = bn + wn + nt * 8 + 2 * t + (rg & 1);
                float val = acc[mt][nt][rg];
                if (res) val += res[(size_t)r * N + c];
                if (bias) val += bias[c];
                C[(size_t)r * N + c] = val;
            }
}

// ---------------- fused 5-projection GEMM ----------------
struct P5 { const float* B[5]; float* C[5]; };
__global__ __launch_bounds__(256) void gemm_proj(const float* __restrict__ A, P5 p) {
    __shared__ uint32_t As[128 * SA];
    __shared__ uint32_t Bs[64 * SA];
    int widx = blockIdx.x / 12;
    int bn = (blockIdx.x % 12) * 64;
    const float* B = p.B[widx];
    float* C = p.C[widx];
    int bm = blockIdx.y * 128;
    int tid = threadIdx.x, wid = tid >> 5, lane = tid & 31;
    int g = lane >> 2, t = lane & 3;
    int wm = (wid & 3) * 32, wn = (wid >> 2) * 32;
    float acc[2][4][4] = {};
    for (int k0 = 0; k0 < DM; k0 += 32) {
        #pragma unroll
        for (int i = tid; i < 1024; i += 256) {
            int r = i >> 3, kv = (i & 7) * 4;
            float4 v = *(const float4*)(A + (size_t)(bm + r) * DM + k0 + kv);
            *(uint4*)(As + r * SA + kv) = f4tf(v);
        }
        #pragma unroll
        for (int i = tid; i < 512; i += 256) {
            int r = i >> 3, kv = (i & 7) * 4;
            float4 v = *(const float4*)(B + (size_t)(bn + r) * DM + k0 + kv);
            *(uint4*)(Bs + r * SA + kv) = f4tf(v);
        }
        __syncthreads();
        #pragma unroll
        for (int kk = 0; kk < 4; kk++) {
            int kb = kk * 8;
            uint32_t af[2][4], bf[4][2];
            #pragma unroll
            for (int mt = 0; mt < 2; mt++) {
                int r0 = wm + mt * 16 + g;
                af[mt][0] = As[r0 * SA + kb + t];
                af[mt][1] = As[(r0 + 8) * SA + kb + t];
                af[mt][2] = As[r0 * SA + kb + t + 4];
                af[mt][3] = As[(r0 + 8) * SA + kb + t + 4];
            }
            #pragma unroll
            for (int nt = 0; nt < 4; nt++) {
                int c0 = wn + nt * 8 + g;
                bf[nt][0] = Bs[c0 * SA + kb + t];
                bf[nt][1] = Bs[c0 * SA + kb + t + 4];
            }
            #pragma unroll
            for (int mt = 0; mt < 2; mt++)
                #pragma unroll
                for (int nt = 0; nt < 4; nt++) mma8(acc[mt][nt], af[mt], bf[nt]);
        }
        __syncthreads();
    }
    #pragma unroll
    for (int mt = 0; mt < 2; mt++)
        #pragma unroll
        for (int nt = 0; nt < 4; nt++)
            #pragma unroll
            for (int rg = 0; rg < 4; rg++) {
                int r = bm + wm + mt * 16 + g + ((rg >= 2) ? 8 : 0);
                int c = bn + wn + nt * 8 + 2 * t + (rg & 1);
                C[(size_t)r * DM + c] = acc[mt][nt][rg];
            }
}

// ---------------- dual gated GEMM: C = (A@B1^T) * (A@B2^T) ----------------
__global__ __launch_bounds__(256) void gemm_dual(
    const float* __restrict__ A, const float* __restrict__ B1, const float* __restrict__ B2,
    float* __restrict__ C, int M, int N, int K) {
    __shared__ uint32_t As[128 * SA];
    __shared__ uint32_t B1s[64 * SA];
    __shared__ uint32_t B2s[64 * SA];
    int bm = blockIdx.y * 128, bn = blockIdx.x * 64;
    int tid = threadIdx.x, wid = tid >> 5, lane = tid & 31;
    int g = lane >> 2, t = lane & 3;
    int wm = (wid & 3) * 32, wn = (wid >> 2) * 32;
    float acc1[2][4][4] = {};
    float acc2[2][4][4] = {};
    for (int k0 = 0; k0 < K; k0 += 32) {
        #pragma unroll
        for (int i = tid; i < 1024; i += 256) {
            int r = i >> 3, kv = (i & 7) * 4;
            float4 v = *(const float4*)(A + (size_t)(bm + r) * K + k0 + kv);
            *(uint4*)(As + r * SA + kv) = f4tf(v);
        }
        #pragma unroll
        for (int i = tid; i < 512; i += 256) {
            int r = i >> 3, kv = (i & 7) * 4;
            float4 v1 = *(const float4*)(B1 + (size_t)(bn + r) * K + k0 + kv);
            float4 v2 = *(const float4*)(B2 + (size_t)(bn + r) * K + k0 + kv);
            *(uint4*)(B1s + r * SA + kv) = f4tf(v1);
            *(uint4*)(B2s + r * SA + kv) = f4tf(v2);
        }
        __syncthreads();
        #pragma unroll
        for (int kk = 0; kk < 4; kk++) {
            int kb = kk * 8;
            uint32_t af[2][4], bf1[4][2], bf2[4][2];
            #pragma unroll
            for (int mt = 0; mt < 2; mt++) {
                int r0 = wm + mt * 16 + g;
                af[mt][0] = As[r0 * SA + kb + t];
                af[mt][1] = As[(r0 + 8) * SA + kb + t];
                af[mt][2] = As[r0 * SA + kb + t + 4];
                af[mt][3] = As[(r0 + 8) * SA + kb + t + 4];
            }
            #pragma unroll
            for (int nt = 0; nt < 4; nt++) {
                int c0 = wn + nt * 8 + g;
                bf1[nt][0] = B1s[c0 * SA + kb + t];
                bf1[nt][1] = B1s[c0 * SA + kb + t + 4];
                bf2[nt][0] = B2s[c0 * SA + kb + t];
                bf2[nt][1] = B2s[c0 * SA + kb + t + 4];
            }
            #pragma unroll
            for (int mt = 0; mt < 2; mt++)
                #pragma unroll
                for (int nt = 0; nt < 4; nt++) {
                    mma8(acc1[mt][nt], af[mt], bf1[nt]);
                    mma8(acc2[mt][nt], af[mt], bf2[nt]);
                }
        }
        __syncthreads();
    }
    #pragma unroll
    for (int mt = 0; mt < 2; mt++)
        #pragma unroll
        for (int nt = 0; nt < 4; nt++)
            #pragma unroll
            for (int rg = 0; rg < 4; rg++) {
                int r = bm + wm + mt * 16 + g + ((rg >= 2) ? 8 : 0);
                int c = bn + wn + nt * 8 + 2 * t + (rg & 1);
                C[(size_t)r * N + c] = acc1[mt][nt][rg] * acc2[mt][nt][rg];
            }
}

// ---------------- RoPE ----------------
__global__ void rope_kernel(float* __restrict__ q, float* __restrict__ k,
                            float* __restrict__ q2, float* __restrict__ k2) {
    int idx = blockIdx.x * blockDim.x + threadIdx.x;
    if (idx >= TT * 32) return;
    int t = idx >> 5, i = idx & 31;
    float inv = powf(10000.f, -(float)(2 * i) / 64.f);
    float ang = (float)t * inv;
    float c = cosf(ang), s = sinf(ang);
    #pragma unroll
    for (int h = 0; h < NH; h++) {
        int base = t * DM + h * DH;
        { float a = q[base + i],  b = q[base + 32 + i];  q[base + i]  = a*c + b*s; q[base + 32 + i]  = -a*s + b*c; }
        { float a = k[base + i],  b = k[base + 32 + i];  k[base + i]  = a*c + b*s; k[base + 32 + i]  = -a*s + b*c; }
        { float a = q2[base + i], b = q2[base + 32 + i]; q2[base + i] = a*c + b*s; q2[base + 32 + i] = -a*s + b*c; }
        { float a = k2[base + i], b = k2[base + 32 + i]; k2[base + i] = a*c + b*s; k2[base + 32 + i] = -a*s + b*c; }
    }
}

// ---------------- attention (tf32 mma) ----------------
#define AST 76
#define VST 72
#define ATT_SMEM ((5 * 64 * AST + 64 * VST) * 4)
__global__ __launch_bounds__(256) void attn_tf32(
    const float* __restrict__ q, const float* __restrict__ k,
    const float* __restrict__ q2, const float* __restrict__ k2,
    const float* __restrict__ v, float* __restrict__ z) {
    extern __shared__ uint32_t sm[];
    uint32_t* Qs  = sm;
    uint32_t* Q2s = Qs + 64 * AST;
    uint32_t* Ks  = Q2s + 64 * AST;
    uint32_t* K2s = Ks + 64 * AST;
    uint32_t* Ps  = K2s + 64 * AST;
    uint32_t* Vs  = Ps + 64 * AST;

    int hd = blockIdx.y;
    int qt = (int)gridDim.x - 1 - (int)blockIdx.x;  // big tiles first
    int tid = threadIdx.x, wid = tid >> 5, lane = tid & 31;
    int g = lane >> 2, t = lane & 3;
    int wm = (wid & 3) * 16;   // 4 row groups of 16
    int wn = (wid >> 2) * 32;  // 2 col halves of 32

    #pragma unroll
    for (int i = tid; i < 1024; i += 256) {
        int r = i >> 4, dv = (i & 15) * 4;
        int gidx = (qt * 64 + r) * DM + hd * DH + dv;
        *(uint4*)(Qs + r * AST + dv)  = f4tf(*(const float4*)(q + gidx));
        *(uint4*)(Q2s + r * AST + dv) = f4tf(*(const float4*)(q2 + gidx));
    }
    float zacc[4][4] = {};
    for (int st = 0; st <= qt; st++) {
        __syncthreads();
        #pragma unroll
        for (int i = tid; i < 1024; i += 256) {
            int r = i >> 4, dv = (i & 15) * 4;
            int gidx = (st * 64 + r) * DM + hd * DH + dv;
            *(uint4*)(Ks + r * AST + dv)  = f4tf(*(const float4*)(k + gidx));
            *(uint4*)(K2s + r * AST + dv) = f4tf(*(const float4*)(k2 + gidx));
            *(uint4*)(Vs + r * VST + dv)  = f4tf(*(const float4*)(v + gidx));
        }
        __syncthreads();
        float s1[4][4] = {}, s2[4][4] = {};
        #pragma unroll
        for (int kk = 0; kk < 8; kk++) {
            int kb = kk * 8;
            uint32_t aq[4], aq2[4];
            int r0 = wm + g;
            aq[0]  = Qs[r0 * AST + kb + t];       aq[1]  = Qs[(r0 + 8) * AST + kb + t];
            aq[2]  = Qs[r0 * AST + kb + t + 4];   aq[3]  = Qs[(r0 + 8) * AST + kb + t + 4];
            aq2[0] = Q2s[r0 * AST + kb + t];      aq2[1] = Q2s[(r0 + 8) * AST + kb + t];
            aq2[2] = Q2s[r0 * AST + kb + t + 4];  aq2[3] = Q2s[(r0 + 8) * AST + kb + t + 4];
            #pragma unroll
            for (int nt = 0; nt < 4; nt++) {
                int c0 = wn + nt * 8 + g;
                uint32_t bk[2], bk2[2];
                bk[0]  = Ks[c0 * AST + kb + t];   bk[1]  = Ks[c0 * AST + kb + t + 4];
                bk2[0] = K2s[c0 * AST + kb + t];  bk2[1] = K2s[c0 * AST + kb + t + 4];
                mma8(s1[nt], aq, bk);
                mma8(s2[nt], aq2, bk2);
            }
        }
        #pragma unroll
        for (int nt = 0; nt < 4; nt++)
            #pragma unroll
            for (int rg = 0; rg < 4; rg++) {
                int qr = wm + g + ((rg >= 2) ? 8 : 0);
                int sc = wn + nt * 8 + 2 * t + (rg & 1);
                float p = s1[nt][rg] * s2[nt][rg] * (1.f / 4096.f);
                if (st == qt && sc > qr) p = 0.f;
                Ps[qr * AST + sc] = f2tf(p);
            }
        __syncthreads();
        #pragma unroll
        for (int kk = 0; kk < 8; kk++) {
            int kb = kk * 8;
            uint32_t ap[4];
            int r0 = wm + g;
            ap[0] = Ps[r0 * AST + kb + t];      ap[1] = Ps[(r0 + 8) * AST + kb + t];
            ap[2] = Ps[r0 * AST + kb + t + 4];  ap[3] = Ps[(r0 + 8) * AST + kb + t + 4];
            #pragma unroll
            for (int nt = 0; nt < 4; nt++) {
                int c = wn + nt * 8 + g;
                uint32_t bv[2];
                bv[0] = Vs[(kb + t) * VST + c];
                bv[1] = Vs[(kb + t + 4) * VST + c];
                mma8(zacc[nt], ap, bv);
            }
        }
    }
    #pragma unroll
    for (int nt = 0; nt < 4; nt++)
        #pragma unroll
        for (int rg = 0; rg < 4; rg++) {
            int r = qt * 64 + wm + g + ((rg >= 2) ? 8 : 0);
            int c = hd * DH + wn + nt * 8 + 2 * t + (rg & 1);
            z[r * DM + c] = zacc[nt][rg];
        }
}

// ---------------- launch ----------------
extern "C" void kernel_launch(void* const* d_in, const int* in_sizes, int n_in,
                              void* d_out, int out_size) {
    const float* x = (const float*)d_in[0];
    const float* Wq = (const float*)d_in[1];
    const float* Wk = (const float*)d_in[2];
    const float* Wq2 = (const float*)d_in[3];
    const float* Wk2 = (const float*)d_in[4];
    const float* Wv = (const float*)d_in[5];
    const float* Wo = (const float*)d_in[6];
    const float* Wp1 = (const float*)d_in[7];
    const float* Wp2 = (const float*)d_in[8];
    const float* Wd = (const float*)d_in[9];
    const float* bd = (const float*)d_in[10];

    float *h, *q, *k, *q2, *k2, *v, *z, *x1, *h2, *hidden;
    cudaGetSymbolAddress((void**)&h, g_h);
    cudaGetSymbolAddress((void**)&q, g_q);
    cudaGetSymbolAddress((void**)&k, g_k);
    cudaGetSymbolAddress((void**)&q2, g_q2);
    cudaGetSymbolAddress((void**)&k2, g_k2);
    cudaGetSymbolAddress((void**)&v, g_v);
    cudaGetSymbolAddress((void**)&z, g_z);
    cudaGetSymbolAddress((void**)&x1, g_x1);
    cudaGetSymbolAddress((void**)&h2, g_h2);
    cudaGetSymbolAddress((void**)&hidden, g_hidden);

    cudaFuncSetAttribute(attn_tf32, cudaFuncAttributeMaxDynamicSharedMemorySize, ATT_SMEM);

    // 1. rmsnorm
    rmsnorm_kernel<<<TT, 256>>>(x, h);

    // 2. fused 5 projections (tf32 mma)
    P5 p5;
    p5.B[0] = Wq; p5.B[1] = Wk; p5.B[2] = Wq2; p5.B[3] = Wk2; p5.B[4] = Wv;
    p5.C[0] = q;  p5.C[1] = k;  p5.C[2] = q2;  p5.C[3] = k2;  p5.C[4] = v;
    gemm_proj<<<dim3(60, TT / 128), 256>>>(h, p5);

    // 3. rope
    rope_kernel<<<(TT * 32 + 255) / 256, 256>>>(q, k, q2, k2);

    // 4. attention (tf32 mma)
    attn_tf32<<<dim3(TT / 64, NH), 256, ATT_SMEM>>>(q, k, q2, k2, v, z);

    // 5. Wo + residual
    gemm_tf32<<<dim3(DM / 64, TT / 128), 256>>>(z, Wo, x1, TT, DM, DM, x, nullptr);

    // 6. rmsnorm 2
    rmsnorm_kernel<<<TT, 256>>>(x1, h2);

    // 7. gated MLP up
    gemm_dual<<<dim3(DHID / 64, TT / 128), 256>>>(h2, Wp1, Wp2, hidden, TT, DHID, DM);

    // 8. down proj + residual + bias
    gemm_tf32<<<dim3(DM / 64, TT / 128), 256>>>(hidden, Wd, (float*)d_out, TT, DM, DHID, x1, bd);
}

// round 4
// speedup vs baseline: 4.6992x; 1.1808x over previous
#include <cuda_runtime.h>
#include <cstdint>
#include <math.h>

#define TT 2048
#define DM 768
#define NH 12
#define DH 64
#define DHID 3072
#define SA 36

// ---------------- scratch ----------------
__device__ float g_h[TT * DM];
__device__ float g_q[TT * DM];
__device__ float g_k[TT * DM];
__device__ float g_q2[TT * DM];
__device__ float g_k2[TT * DM];
__device__ float g_v[TT * DM];
__device__ float g_z[TT * DM];
__device__ float g_x1[TT * DM];
__device__ float g_h2[TT * DM];
__device__ float g_hidden[TT * DHID];

// ---------------- helpers ----------------
__device__ __forceinline__ void cpa(uint32_t dst, const float* src) {
    asm volatile("cp.async.ca.shared.global [%0], [%1], 16;" :: "r"(dst), "l"(src));
}
__device__ __forceinline__ void cpcommit() { asm volatile("cp.async.commit_group;"); }
template <int N> __device__ __forceinline__ void cpwait() {
    asm volatile("cp.async.wait_group %0;" :: "n"(N));
}
__device__ __forceinline__ void mma8(float* d, const uint32_t* a, const uint32_t* b) {
    asm volatile(
        "mma.sync.aligned.m16n8k8.row.col.f32.tf32.tf32.f32 "
        "{%0,%1,%2,%3},{%4,%5,%6,%7},{%8,%9},{%0,%1,%2,%3};\n"
        : "+f"(d[0]), "+f"(d[1]), "+f"(d[2]), "+f"(d[3])
        : "r"(a[0]), "r"(a[1]), "r"(a[2]), "r"(a[3]), "r"(b[0]), "r"(b[1]));
}

// ---------------- RMSNorm ----------------
__global__ void rmsnorm_kernel(const float* __restrict__ x, float* __restrict__ o) {
    int row = blockIdx.x;
    const float* xr = x + row * DM;
    float s = 0.f;
    for (int i = threadIdx.x; i < DM; i += blockDim.x) { float v = xr[i]; s += v * v; }
    __shared__ float red[32];
    for (int off = 16; off; off >>= 1) s += __shfl_down_sync(0xffffffffu, s, off);
    if ((threadIdx.x & 31) == 0) red[threadIdx.x >> 5] = s;
    __syncthreads();
    if (threadIdx.x < 32) {
        s = (threadIdx.x < (blockDim.x >> 5)) ? red[threadIdx.x] : 0.f;
        for (int off = 16; off; off >>= 1) s += __shfl_down_sync(0xffffffffu, s, off);
        if (threadIdx.x == 0) red[0] = rsqrtf(s / (float)DM + 1e-6f);
    }
    __syncthreads();
    float scale = red[0];
    for (int i = threadIdx.x; i < DM; i += blockDim.x) o[row * DM + i] = xr[i] * scale;
}

// ---------------- pipelined tf32 GEMM NT: C = A[M,K] @ B[N,K]^T (+res +bias) ----------------
// BM=128 BN=64 BK=32, 2-stage cp.async, 256 threads, warp tile 32x32.
#define GEMM_SMEM ((2 * 128 * SA + 2 * 64 * SA) * 4)
__global__ __launch_bounds__(256) void gemm_pipe(
    const float* __restrict__ A, const float* __restrict__ B, float* __restrict__ C,
    int M, int N, int K, const float* __restrict__ res, const float* __restrict__ bias) {
    extern __shared__ uint32_t sm[];
    uint32_t* As = sm;                  // [2][128*SA]
    uint32_t* Bs = sm + 2 * 128 * SA;   // [2][64*SA]
    uint32_t sb = (uint32_t)__cvta_generic_to_shared(sm);
    int bm = blockIdx.y * 128, bn = blockIdx.x * 64;
    int tid = threadIdx.x, wid = tid >> 5, lane = tid & 31;
    int g = lane >> 2, t = lane & 3;
    int wm = (wid & 3) * 32, wn = (wid >> 2) * 32;
    const float* Ab = A + (size_t)bm * K;
    const float* Bb = B + (size_t)bn * K;
    float acc[2][4][4] = {};

    // prolog: stage 0
    {
        uint32_t ab = sb;
        #pragma unroll
        for (int i = tid; i < 1024; i += 256) { int r = i >> 3, kv = (i & 7) * 4;
            cpa(ab + (r * SA + kv) * 4, Ab + (size_t)r * K + kv); }
        uint32_t bb = sb + (2 * 128 * SA) * 4;
        #pragma unroll
        for (int i = tid; i < 512; i += 256) { int r = i >> 3, kv = (i & 7) * 4;
            cpa(bb + (r * SA + kv) * 4, Bb + (size_t)r * K + kv); }
        cpcommit();
    }
    int nk = K >> 5;
    for (int it = 0; it < nk; it++) {
        int cur = it & 1;
        if (it + 1 < nk) {
            int k0 = (it + 1) << 5, nxt = cur ^ 1;
            uint32_t ab = sb + (nxt * 128 * SA) * 4;
            #pragma unroll
            for (int i = tid; i < 1024; i += 256) { int r = i >> 3, kv = (i & 7) * 4;
                cpa(ab + (r * SA + kv) * 4, Ab + (size_t)r * K + k0 + kv); }
            uint32_t bb = sb + (2 * 128 * SA + nxt * 64 * SA) * 4;
            #pragma unroll
            for (int i = tid; i < 512; i += 256) { int r = i >> 3, kv = (i & 7) * 4;
                cpa(bb + (r * SA + kv) * 4, Bb + (size_t)r * K + k0 + kv); }
            cpcommit();
            cpwait<1>();
        } else cpwait<0>();
        __syncthreads();
        const uint32_t* Ac = As + cur * 128 * SA;
        const uint32_t* Bc = Bs + cur * 64 * SA;
        #pragma unroll
        for (int kk = 0; kk < 4; kk++) {
            int kb = kk * 8;
            uint32_t af[2][4], bf[4][2];
            #pragma unroll
            for (int mt = 0; mt < 2; mt++) {
                int r0 = wm + mt * 16 + g;
                af[mt][0] = Ac[r0 * SA + kb + t];
                af[mt][1] = Ac[(r0 + 8) * SA + kb + t];
                af[mt][2] = Ac[r0 * SA + kb + t + 4];
                af[mt][3] = Ac[(r0 + 8) * SA + kb + t + 4];
            }
            #pragma unroll
            for (int nt = 0; nt < 4; nt++) {
                int c0 = wn + nt * 8 + g;
                bf[nt][0] = Bc[c0 * SA + kb + t];
                bf[nt][1] = Bc[c0 * SA + kb + t + 4];
            }
            #pragma unroll
            for (int mt = 0; mt < 2; mt++)
                #pragma unroll
                for (int nt = 0; nt < 4; nt++) mma8(acc[mt][nt], af[mt], bf[nt]);
        }
        __syncthreads();
    }
    #pragma unroll
    for (int mt = 0; mt < 2; mt++)
        #pragma unroll
        for (int nt = 0; nt < 4; nt++) {
            int c = bn + wn + nt * 8 + 2 * t;
            #pragma unroll
            for (int half = 0; half < 2; half++) {
                int r = bm + wm + mt * 16 + g + half * 8;
                float2 v = make_float2(acc[mt][nt][half * 2], acc[mt][nt][half * 2 + 1]);
                if (res) { float2 rr = *(const float2*)(res + (size_t)r * N + c); v.x += rr.x; v.y += rr.y; }
                if (bias) { v.x += bias[c]; v.y += bias[c + 1]; }
                *(float2*)(C + (size_t)r * N + c) = v;
            }
        }
}

// ---------------- fused 5-projection pipelined GEMM ----------------
struct P5 { const float* B[5]; float* C[5]; };
__global__ __launch_bounds__(256) void gemm_proj(const float* __restrict__ A, P5 p) {
    extern __shared__ uint32_t sm[];
    uint32_t* As = sm;
    uint32_t* Bs = sm + 2 * 128 * SA;
    uint32_t sb = (uint32_t)__cvta_generic_to_shared(sm);
    int widx = blockIdx.x / 12;
    int bn = (blockIdx.x % 12) * 64;
    const float* B = p.B[widx];
    float* C = p.C[widx];
    int bm = blockIdx.y * 128;
    int tid = threadIdx.x, wid = tid >> 5, lane = tid & 31;
    int g = lane >> 2, t = lane & 3;
    int wm = (wid & 3) * 32, wn = (wid >> 2) * 32;
    const float* Ab = A + (size_t)bm * DM;
    const float* Bb = B + (size_t)bn * DM;
    float acc[2][4][4] = {};
    {
        uint32_t ab = sb;
        #pragma unroll
        for (int i = tid; i < 1024; i += 256) { int r = i >> 3, kv = (i & 7) * 4;
            cpa(ab + (r * SA + kv) * 4, Ab + (size_t)r * DM + kv); }
        uint32_t bb = sb + (2 * 128 * SA) * 4;
        #pragma unroll
        for (int i = tid; i < 512; i += 256) { int r = i >> 3, kv = (i & 7) * 4;
            cpa(bb + (r * SA + kv) * 4, Bb + (size_t)r * DM + kv); }
        cpcommit();
    }
    int nk = DM >> 5;
    for (int it = 0; it < nk; it++) {
        int cur = it & 1;
        if (it + 1 < nk) {
            int k0 = (it + 1) << 5, nxt = cur ^ 1;
            uint32_t ab = sb + (nxt * 128 * SA) * 4;
            #pragma unroll
            for (int i = tid; i < 1024; i += 256) { int r = i >> 3, kv = (i & 7) * 4;
                cpa(ab + (r * SA + kv) * 4, Ab + (size_t)r * DM + k0 + kv); }
            uint32_t bb = sb + (2 * 128 * SA + nxt * 64 * SA) * 4;
            #pragma unroll
            for (int i = tid; i < 512; i += 256) { int r = i >> 3, kv = (i & 7) * 4;
                cpa(bb + (r * SA + kv) * 4, Bb + (size_t)r * DM + k0 + kv); }
            cpcommit();
            cpwait<1>();
        } else cpwait<0>();
        __syncthreads();
        const uint32_t* Ac = As + cur * 128 * SA;
        const uint32_t* Bc = Bs + cur * 64 * SA;
        #pragma unroll
        for (int kk = 0; kk < 4; kk++) {
            int kb = kk * 8;
            uint32_t af[2][4], bf[4][2];
            #pragma unroll
            for (int mt = 0; mt < 2; mt++) {
                int r0 = wm + mt * 16 + g;
                af[mt][0] = Ac[r0 * SA + kb + t];
                af[mt][1] = Ac[(r0 + 8) * SA + kb + t];
                af[mt][2] = Ac[r0 * SA + kb + t + 4];
                af[mt][3] = Ac[(r0 + 8) * SA + kb + t + 4];
            }
            #pragma unroll
            for (int nt = 0; nt < 4; nt++) {
                int c0 = wn + nt * 8 + g;
                bf[nt][0] = Bc[c0 * SA + kb + t];
                bf[nt][1] = Bc[c0 * SA + kb + t + 4];
            }
            #pragma unroll
            for (int mt = 0; mt < 2; mt++)
                #pragma unroll
                for (int nt = 0; nt < 4; nt++) mma8(acc[mt][nt], af[mt], bf[nt]);
        }
        __syncthreads();
    }
    #pragma unroll
    for (int mt = 0; mt < 2; mt++)
        #pragma unroll
        for (int nt = 0; nt < 4; nt++) {
            int c = bn + wn + nt * 8 + 2 * t;
            #pragma unroll
            for (int half = 0; half < 2; half++) {
                int r = bm + wm + mt * 16 + g + half * 8;
                *(float2*)(C + (size_t)r * DM + c) =
                    make_float2(acc[mt][nt][half * 2], acc[mt][nt][half * 2 + 1]);
            }
        }
}

// ---------------- dual gated pipelined GEMM: C = (A@B1^T)*(A@B2^T) ----------------
#define DUAL_SMEM ((2 * 128 * SA + 4 * 64 * SA) * 4)
__global__ __launch_bounds__(256) void gemm_dual(
    const float* __restrict__ A, const float* __restrict__ B1, const float* __restrict__ B2,
    float* __restrict__ C, int M, int N, int K) {
    extern __shared__ uint32_t sm[];
    uint32_t* As = sm;
    uint32_t* B1s = sm + 2 * 128 * SA;
    uint32_t* B2s = B1s + 2 * 64 * SA;
    uint32_t sb = (uint32_t)__cvta_generic_to_shared(sm);
    int bm = blockIdx.y * 128, bn = blockIdx.x * 64;
    int tid = threadIdx.x, wid = tid >> 5, lane = tid & 31;
    int g = lane >> 2, t = lane & 3;
    int wm = (wid & 3) * 32, wn = (wid >> 2) * 32;
    const float* Ab = A + (size_t)bm * K;
    const float* B1b = B1 + (size_t)bn * K;
    const float* B2b = B2 + (size_t)bn * K;
    float acc1[2][4][4] = {};
    float acc2[2][4][4] = {};
    {
        uint32_t ab = sb;
        #pragma unroll
        for (int i = tid; i < 1024; i += 256) { int r = i >> 3, kv = (i & 7) * 4;
            cpa(ab + (r * SA + kv) * 4, Ab + (size_t)r * K + kv); }
        uint32_t b1 = sb + (2 * 128 * SA) * 4;
        uint32_t b2 = sb + (2 * 128 * SA + 2 * 64 * SA) * 4;
        #pragma unroll
        for (int i = tid; i < 512; i += 256) { int r = i >> 3, kv = (i & 7) * 4;
            cpa(b1 + (r * SA + kv) * 4, B1b + (size_t)r * K + kv);
            cpa(b2 + (r * SA + kv) * 4, B2b + (size_t)r * K + kv); }
        cpcommit();
    }
    int nk = K >> 5;
    for (int it = 0; it < nk; it++) {
        int cur = it & 1;
        if (it + 1 < nk) {
            int k0 = (it + 1) << 5, nxt = cur ^ 1;
            uint32_t ab = sb + (nxt * 128 * SA) * 4;
            #pragma unroll
            for (int i = tid; i < 1024; i += 256) { int r = i >> 3, kv = (i & 7) * 4;
                cpa(ab + (r * SA + kv) * 4, Ab + (size_t)r * K + k0 + kv); }
            uint32_t b1 = sb + (2 * 128 * SA + nxt * 64 * SA) * 4;
            uint32_t b2 = sb + (2 * 128 * SA + 2 * 64 * SA + nxt * 64 * SA) * 4;
            #pragma unroll
            for (int i = tid; i < 512; i += 256) { int r = i >> 3, kv = (i & 7) * 4;
                cpa(b1 + (r * SA + kv) * 4, B1b + (size_t)r * K + k0 + kv);
                cpa(b2 + (r * SA + kv) * 4, B2b + (size_t)r * K + k0 + kv); }
            cpcommit();
            cpwait<1>();
        } else cpwait<0>();
        __syncthreads();
        const uint32_t* Ac = As + cur * 128 * SA;
        const uint32_t* B1c = B1s + cur * 64 * SA;
        const uint32_t* B2c = B2s + cur * 64 * SA;
        #pragma unroll
        for (int kk = 0; kk < 4; kk++) {
            int kb = kk * 8;
            uint32_t af[2][4], bf1[4][2], bf2[4][2];
            #pragma unroll
            for (int mt = 0; mt < 2; mt++) {
                int r0 = wm + mt * 16 + g;
                af[mt][0] = Ac[r0 * SA + kb + t];
                af[mt][1] = Ac[(r0 + 8) * SA + kb + t];
                af[mt][2] = Ac[r0 * SA + kb + t + 4];
                af[mt][3] = Ac[(r0 + 8) * SA + kb + t + 4];
            }
            #pragma unroll
            for (int nt = 0; nt < 4; nt++) {
                int c0 = wn + nt * 8 + g;
                bf1[nt][0] = B1c[c0 * SA + kb + t];
                bf1[nt][1] = B1c[c0 * SA + kb + t + 4];
                bf2[nt][0] = B2c[c0 * SA + kb + t];
                bf2[nt][1] = B2c[c0 * SA + kb + t + 4];
            }
            #pragma unroll
            for (int mt = 0; mt < 2; mt++)
                #pragma unroll
                for (int nt = 0; nt < 4; nt++) {
                    mma8(acc1[mt][nt], af[mt], bf1[nt]);
                    mma8(acc2[mt][nt], af[mt], bf2[nt]);
                }
        }
        __syncthreads();
    }
    #pragma unroll
    for (int mt = 0; mt < 2; mt++)
        #pragma unroll
        for (int nt = 0; nt < 4; nt++) {
            int c = bn + wn + nt * 8 + 2 * t;
            #pragma unroll
            for (int half = 0; half < 2; half++) {
                int r = bm + wm + mt * 16 + g + half * 8;
                *(float2*)(C + (size_t)r * N + c) =
                    make_float2(acc1[mt][nt][half * 2] * acc2[mt][nt][half * 2],
                                acc1[mt][nt][half * 2 + 1] * acc2[mt][nt][half * 2 + 1]);
            }
        }
}

// ---------------- RoPE ----------------
__global__ void rope_kernel(float* __restrict__ q, float* __restrict__ k,
                            float* __restrict__ q2, float* __restrict__ k2) {
    int idx = blockIdx.x * blockDim.x + threadIdx.x;
    if (idx >= TT * 32) return;
    int t = idx >> 5, i = idx & 31;
    float inv = powf(10000.f, -(float)(2 * i) / 64.f);
    float ang = (float)t * inv;
    float c = cosf(ang), s = sinf(ang);
    #pragma unroll
    for (int h = 0; h < NH; h++) {
        int base = t * DM + h * DH;
        { float a = q[base + i],  b = q[base + 32 + i];  q[base + i]  = a*c + b*s; q[base + 32 + i]  = -a*s + b*c; }
        { float a = k[base + i],  b = k[base + 32 + i];  k[base + i]  = a*c + b*s; k[base + 32 + i]  = -a*s + b*c; }
        { float a = q2[base + i], b = q2[base + 32 + i]; q2[base + i] = a*c + b*s; q2[base + 32 + i] = -a*s + b*c; }
        { float a = k2[base + i], b = k2[base + 32 + i]; k2[base + i] = a*c + b*s; k2[base + 32 + i] = -a*s + b*c; }
    }
}

// ---------------- attention v2 (tf32 mma, Q hoisted, cp.async, 2 CTAs/SM) ----------------
#define AST 76
#define VST 72
#define ATT_SMEM ((4 * 64 * AST + 64 * VST) * 4)
__global__ __launch_bounds__(256, 2) void attn_tf32(
    const float* __restrict__ q, const float* __restrict__ k,
    const float* __restrict__ q2, const float* __restrict__ k2,
    const float* __restrict__ v, float* __restrict__ z) {
    extern __shared__ uint32_t sm[];
    uint32_t* Q2s = sm;                       // 64 x AST (persistent)
    uint32_t* Ks  = Q2s + 64 * AST;
    uint32_t* K2s = Ks + 64 * AST;
    uint32_t* Ps  = K2s + 64 * AST;           // staging for Q, then P
    uint32_t* Vs  = Ps + 64 * AST;            // 64 x VST
    uint32_t sb = (uint32_t)__cvta_generic_to_shared(sm);
    const uint32_t offQ2 = 0, offK = 64 * AST, offK2 = 2 * 64 * AST,
                   offP = 3 * 64 * AST, offV = 4 * 64 * AST;

    int hd = blockIdx.y;
    int qt = (int)gridDim.x - 1 - (int)blockIdx.x;  // big tiles first
    int tid = threadIdx.x, wid = tid >> 5, lane = tid & 31;
    int g = lane >> 2, t = lane & 3;
    int wm = (wid & 3) * 16;
    int wn = (wid >> 2) * 32;
    int r0 = wm + g;

    // stage Q -> Ps, Q2 -> Q2s
    #pragma unroll
    for (int i = tid; i < 1024; i += 256) {
        int r = i >> 4, dv = (i & 15) * 4;
        size_t gofs = (size_t)(qt * 64 + r) * DM + hd * DH + dv;
        cpa(sb + (offP + r * AST + dv) * 4, q + gofs);
        cpa(sb + (offQ2 + r * AST + dv) * 4, q2 + gofs);
    }
    cpcommit();
    cpwait<0>();
    __syncthreads();

    // hoist Q fragments into registers
    uint32_t aq[8][4];
    #pragma unroll
    for (int kk = 0; kk < 8; kk++) {
        int kb = kk * 8;
        aq[kk][0] = Ps[r0 * AST + kb + t];
        aq[kk][1] = Ps[(r0 + 8) * AST + kb + t];
        aq[kk][2] = Ps[r0 * AST + kb + t + 4];
        aq[kk][3] = Ps[(r0 + 8) * AST + kb + t + 4];
    }

    float zacc[4][4] = {};
    for (int st = 0; st <= qt; st++) {
        // load K, K2, V tile
        #pragma unroll
        for (int i = tid; i < 1024; i += 256) {
            int r = i >> 4, dv = (i & 15) * 4;
            size_t gofs = (size_t)(st * 64 + r) * DM + hd * DH + dv;
            cpa(sb + (offK + r * AST + dv) * 4, k + gofs);
            cpa(sb + (offK2 + r * AST + dv) * 4, k2 + gofs);
            cpa(sb + (offV + r * VST + dv) * 4, v + gofs);
        }
        cpcommit();
        cpwait<0>();
        __syncthreads();

        float s1[4][4] = {}, s2[4][4] = {};
        #pragma unroll
        for (int kk = 0; kk < 8; kk++) {
            int kb = kk * 8;
            uint32_t aq2[4];
            aq2[0] = Q2s[r0 * AST + kb + t];
            aq2[1] = Q2s[(r0 + 8) * AST + kb + t];
            aq2[2] = Q2s[r0 * AST + kb + t + 4];
            aq2[3] = Q2s[(r0 + 8) * AST + kb + t + 4];
            #pragma unroll
            for (int nt = 0; nt < 4; nt++) {
                int c0 = wn + nt * 8 + g;
                uint32_t bk[2], bk2[2];
                bk[0]  = Ks[c0 * AST + kb + t];
                bk[1]  = Ks[c0 * AST + kb + t + 4];
                bk2[0] = K2s[c0 * AST + kb + t];
                bk2[1] = K2s[c0 * AST + kb + t + 4];
                mma8(s1[nt], aq[kk], bk);
                mma8(s2[nt], aq2, bk2);
            }
        }
        #pragma unroll
        for (int nt = 0; nt < 4; nt++)
            #pragma unroll
            for (int rg = 0; rg < 4; rg++) {
                int qr = wm + g + ((rg >= 2) ? 8 : 0);
                int sc = wn + nt * 8 + 2 * t + (rg & 1);
                float p = s1[nt][rg] * s2[nt][rg] * (1.f / 4096.f);
                if (st == qt && sc > qr) p = 0.f;
                Ps[qr * AST + sc] = __float_as_uint(p);
            }
        __syncthreads();
        #pragma unroll
        for (int kk = 0; kk < 8; kk++) {
            int kb = kk * 8;
            uint32_t ap[4];
            ap[0] = Ps[r0 * AST + kb + t];
            ap[1] = Ps[(r0 + 8) * AST + kb + t];
            ap[2] = Ps[r0 * AST + kb + t + 4];
            ap[3] = Ps[(r0 + 8) * AST + kb + t + 4];
            #pragma unroll
            for (int nt = 0; nt < 4; nt++) {
                int c = wn + nt * 8 + g;
                uint32_t bv[2];
                bv[0] = Vs[(kb + t) * VST + c];
                bv[1] = Vs[(kb + t + 4) * VST + c];
                mma8(zacc[nt], ap, bv);
            }
        }
        __syncthreads();
    }
    #pragma unroll
    for (int nt = 0; nt < 4; nt++) {
        int c = hd * DH + wn + nt * 8 + 2 * t;
        #pragma unroll
        for (int half = 0; half < 2; half++) {
            int r = qt * 64 + wm + g + half * 8;
            *(float2*)(z + (size_t)r * DM + c) =
                make_float2(zacc[nt][half * 2], zacc[nt][half * 2 + 1]);
        }
    }
}

// ---------------- launch ----------------
extern "C" void kernel_launch(void* const* d_in, const int* in_sizes, int n_in,
                              void* d_out, int out_size) {
    const float* x = (const float*)d_in[0];
    const float* Wq = (const float*)d_in[1];
    const float* Wk = (const float*)d_in[2];
    const float* Wq2 = (const float*)d_in[3];
    const float* Wk2 = (const float*)d_in[4];
    const float* Wv = (const float*)d_in[5];
    const float* Wo = (const float*)d_in[6];
    const float* Wp1 = (const float*)d_in[7];
    const float* Wp2 = (const float*)d_in[8];
    const float* Wd = (const float*)d_in[9];
    const float* bd = (const float*)d_in[10];

    float *h, *q, *k, *q2, *k2, *v, *z, *x1, *h2, *hidden;
    cudaGetSymbolAddress((void**)&h, g_h);
    cudaGetSymbolAddress((void**)&q, g_q);
    cudaGetSymbolAddress((void**)&k, g_k);
    cudaGetSymbolAddress((void**)&q2, g_q2);
    cudaGetSymbolAddress((void**)&k2, g_k2);
    cudaGetSymbolAddress((void**)&v, g_v);
    cudaGetSymbolAddress((void**)&z, g_z);
    cudaGetSymbolAddress((void**)&x1, g_x1);
    cudaGetSymbolAddress((void**)&h2, g_h2);
    cudaGetSymbolAddress((void**)&hidden, g_hidden);

    cudaFuncSetAttribute(gemm_pipe, cudaFuncAttributeMaxDynamicSharedMemorySize, GEMM_SMEM);
    cudaFuncSetAttribute(gemm_proj, cudaFuncAttributeMaxDynamicSharedMemorySize, GEMM_SMEM);
    cudaFuncSetAttribute(gemm_dual, cudaFuncAttributeMaxDynamicSharedMemorySize, DUAL_SMEM);
    cudaFuncSetAttribute(attn_tf32, cudaFuncAttributeMaxDynamicSharedMemorySize, ATT_SMEM);

    // 1. rmsnorm
    rmsnorm_kernel<<<TT, 256>>>(x, h);

    // 2. fused 5 projections
    P5 p5;
    p5.B[0] = Wq; p5.B[1] = Wk; p5.B[2] = Wq2; p5.B[3] = Wk2; p5.B[4] = Wv;
    p5.C[0] = q;  p5.C[1] = k;  p5.C[2] = q2;  p5.C[3] = k2;  p5.C[4] = v;
    gemm_proj<<<dim3(60, TT / 128), 256, GEMM_SMEM>>>(h, p5);

    // 3. rope
    rope_kernel<<<(TT * 32 + 255) / 256, 256>>>(q, k, q2, k2);

    // 4. attention
    attn_tf32<<<dim3(TT / 64, NH), 256, ATT_SMEM>>>(q, k, q2, k2, v, z);

    // 5. Wo + residual
    gemm_pipe<<<dim3(DM / 64, TT / 128), 256, GEMM_SMEM>>>(z, Wo, x1, TT, DM, DM, x, nullptr);

    // 6. rmsnorm 2
    rmsnorm_kernel<<<TT, 256>>>(x1, h2);

    // 7. gated MLP up
    gemm_dual<<<dim3(DHID / 64, TT / 128), 256, DUAL_SMEM>>>(h2, Wp1, Wp2, hidden, TT, DHID, DM);

    // 8. down proj + residual + bias
    gemm_pipe<<<dim3(DM / 64, TT / 128), 256, GEMM_SMEM>>>(hidden, Wd, (float*)d_out, TT, DM, DHID, x1, bd);
}

// round 5
// speedup vs baseline: 7.6444x; 1.6268x over previous
#include <cuda_runtime.h>
#include <cuda_fp16.h>
#include <cstdint>
#include <math.h>

#define TT 2048
#define DM 768
#define NH 12
#define DH 64
#define DHID 3072
#define SH 36            // smem row stride in uint32 words (32 data pairs + 4 pad; 36 mod 32 = 4 -> conflict-free)

// ---------------- scratch (device globals; no allocation) ----------------
__device__ __half g_h[TT * DM];
__device__ __half g_q[TT * DM];
__device__ __half g_k[TT * DM];
__device__ __half g_q2[TT * DM];
__device__ __half g_k2[TT * DM];
__device__ __half g_vT[DM * TT];     // per-head transposed V: vT[dim][token]
__device__ __half g_z[TT * DM];
__device__ float  g_x1[TT * DM];
__device__ __half g_h2[TT * DM];
__device__ __half g_hidden[TT * DHID];

// fp16 weights
__device__ __half hWq[DM * DM];
__device__ __half hWk[DM * DM];
__device__ __half hWq2[DM * DM];
__device__ __half hWk2[DM * DM];
__device__ __half hWv[DM * DM];
__device__ __half hWo[DM * DM];
__device__ __half hWp1[DHID * DM];
__device__ __half hWp2[DHID * DM];
__device__ __half hWd[DM * DHID];

// ---------------- helpers ----------------
__device__ __forceinline__ void cpa(uint32_t dst, const void* src) {
    asm volatile("cp.async.ca.shared.global [%0], [%1], 16;" :: "r"(dst), "l"(src));
}
__device__ __forceinline__ void cpcommit() { asm volatile("cp.async.commit_group;"); }
template <int N> __device__ __forceinline__ void cpwait() {
    asm volatile("cp.async.wait_group %0;" :: "n"(N));
}
__device__ __forceinline__ void mma16(float* d, const uint32_t* a, const uint32_t* b) {
    asm volatile(
        "mma.sync.aligned.m16n8k16.row.col.f32.f16.f16.f32 "
        "{%0,%1,%2,%3},{%4,%5,%6,%7},{%8,%9},{%0,%1,%2,%3};\n"
        : "+f"(d[0]), "+f"(d[1]), "+f"(d[2]), "+f"(d[3])
        : "r"(a[0]), "r"(a[1]), "r"(a[2]), "r"(a[3]), "r"(b[0]), "r"(b[1]));
}
__device__ __forceinline__ uint32_t packh(float a, float b) {
    __half2 h = __floats2half2_rn(a, b);
    return *(uint32_t*)&h;
}

// ---------------- weight convert fp32 -> fp16 (rn) ----------------
struct W9 { const float* s[9]; };
__device__ __forceinline__ __half* wdst(int wi) {
    switch (wi) {
        case 0: return hWq;  case 1: return hWk;  case 2: return hWq2;
        case 3: return hWk2; case 4: return hWv;  case 5: return hWo;
        case 6: return hWp1; case 7: return hWp2; default: return hWd;
    }
}
#define NF4 2654208  // total float4 count across 9 weights
__global__ void cvtw_all(W9 w) {
    int i = blockIdx.x * 256 + threadIdx.x;
    if (i >= NF4) return;
    int wi; int off;
    if (i < 884736) { wi = i / 147456; off = i % 147456; }
    else { int j = i - 884736; wi = 6 + j / 589824; off = j % 589824; }
    float4 v = ((const float4*)w.s[wi])[off];
    __half2* d = (__half2*)wdst(wi);
    d[2 * off]     = __floats2half2_rn(v.x, v.y);
    d[2 * off + 1] = __floats2half2_rn(v.z, v.w);
}

// ---------------- RMSNorm (fp32 in -> fp16 out) ----------------
__global__ void rmsnorm_kernel(const float* __restrict__ x, __half* __restrict__ o) {
    int row = blockIdx.x;
    const float* xr = x + row * DM;
    float s = 0.f;
    for (int i = threadIdx.x; i < DM; i += blockDim.x) { float v = xr[i]; s += v * v; }
    __shared__ float red[32];
    for (int off = 16; off; off >>= 1) s += __shfl_down_sync(0xffffffffu, s, off);
    if ((threadIdx.x & 31) == 0) red[threadIdx.x >> 5] = s;
    __syncthreads();
    if (threadIdx.x < 32) {
        s = (threadIdx.x < (blockDim.x >> 5)) ? red[threadIdx.x] : 0.f;
        for (int off = 16; off; off >>= 1) s += __shfl_down_sync(0xffffffffu, s, off);
        if (threadIdx.x == 0) red[0] = rsqrtf(s / (float)DM + 1e-6f);
    }
    __syncthreads();
    float scale = red[0];
    for (int i = threadIdx.x; i < DM; i += blockDim.x)
        o[row * DM + i] = __float2half_rn(xr[i] * scale);
}

// ================= fp16 GEMM common geometry =================
#define AW (128 * SH)
#define BW (64 * SH)
#define GEMM_SMEM ((2 * AW + 2 * BW) * 4)
#define DUAL_SMEM ((2 * AW + 4 * BW) * 4)

#define GEMM_FRAG_COMPUTE(Ac, Bc, accv)                                        \
    _Pragma("unroll")                                                          \
    for (int kk = 0; kk < 4; kk++) {                                           \
        int kb = kk * 8;                                                       \
        uint32_t af[2][4], bf[4][2];                                           \
        _Pragma("unroll")                                                      \
        for (int mt = 0; mt < 2; mt++) {                                       \
            int r0 = wm + mt * 16 + g;                                         \
            af[mt][0] = (Ac)[r0 * SH + kb + t];                                \
            af[mt][1] = (Ac)[(r0 + 8) * SH + kb + t];                          \
            af[mt][2] = (Ac)[r0 * SH + kb + 4 + t];                            \
            af[mt][3] = (Ac)[(r0 + 8) * SH + kb + 4 + t];                      \
        }                                                                      \
        _Pragma("unroll")                                                      \
        for (int nt = 0; nt < 4; nt++) {                                       \
            int c0 = wn + nt * 8 + g;                                          \
            bf[nt][0] = (Bc)[c0 * SH + kb + t];                                \
            bf[nt][1] = (Bc)[c0 * SH + kb + 4 + t];                            \
        }                                                                      \
        _Pragma("unroll")                                                      \
        for (int mt = 0; mt < 2; mt++)                                         \
            _Pragma("unroll")                                                  \
            for (int nt = 0; nt < 4; nt++) mma16(accv[mt][nt], af[mt], bf[nt]);\
    }

// ---------------- fused 5-projection GEMM (h @ W^T), fp16 out (V transposed) ----------------
__global__ __launch_bounds__(256, 2) void gemm_proj() {
    extern __shared__ uint32_t sm[];
    uint32_t sb = (uint32_t)__cvta_generic_to_shared(sm);
    int widx = blockIdx.x / 12;
    int bn = (blockIdx.x % 12) * 64;
    int bm = blockIdx.y * 128;
    const __half* Bw = (widx == 0) ? hWq : (widx == 1) ? hWk : (widx == 2) ? hWq2
                       : (widx == 3) ? hWk2 : hWv;
    int tid = threadIdx.x, wid = tid >> 5, lane = tid & 31;
    int g = lane >> 2, t = lane & 3;
    int wm = (wid & 3) * 32, wn = (wid >> 2) * 32;
    const __half* Ab = g_h + (size_t)bm * DM;
    const __half* Bb = Bw + (size_t)bn * DM;
    float acc[2][4][4] = {};
    {
        #pragma unroll
        for (int i = tid; i < 1024; i += 256) { int r = i >> 3, c = i & 7;
            cpa(sb + (r * SH + c * 4) * 4, Ab + (size_t)r * DM + c * 8); }
        #pragma unroll
        for (int i = tid; i < 512; i += 256) { int r = i >> 3, c = i & 7;
            cpa(sb + (2 * AW + r * SH + c * 4) * 4, Bb + (size_t)r * DM + c * 8); }
        cpcommit();
    }
    const int nk = DM / 64;
    for (int it = 0; it < nk; it++) {
        int cur = it & 1;
        if (it + 1 < nk) {
            int k0 = (it + 1) * 64, nxt = cur ^ 1;
            #pragma unroll
            for (int i = tid; i < 1024; i += 256) { int r = i >> 3, c = i & 7;
                cpa(sb + (nxt * AW + r * SH + c * 4) * 4, Ab + (size_t)r * DM + k0 + c * 8); }
            #pragma unroll
            for (int i = tid; i < 512; i += 256) { int r = i >> 3, c = i & 7;
                cpa(sb + (2 * AW + nxt * BW + r * SH + c * 4) * 4, Bb + (size_t)r * DM + k0 + c * 8); }
            cpcommit();
            cpwait<1>();
        } else cpwait<0>();
        __syncthreads();
        const uint32_t* Ac = sm + cur * AW;
        const uint32_t* Bc = sm + 2 * AW + cur * BW;
        GEMM_FRAG_COMPUTE(Ac, Bc, acc)
        __syncthreads();
    }
    if (widx < 4) {
        __half* C = (widx == 0) ? g_q : (widx == 1) ? g_k : (widx == 2) ? g_q2 : g_k2;
        #pragma unroll
        for (int mt = 0; mt < 2; mt++)
            #pragma unroll
            for (int nt = 0; nt < 4; nt++) {
                int c = bn + wn + nt * 8 + 2 * t;
                #pragma unroll
                for (int half = 0; half < 2; half++) {
                    int r = bm + wm + mt * 16 + g + half * 8;
                    *(uint32_t*)(C + (size_t)r * DM + c) =
                        packh(acc[mt][nt][half * 2], acc[mt][nt][half * 2 + 1]);
                }
            }
    } else {
        #pragma unroll
        for (int mt = 0; mt < 2; mt++)
            #pragma unroll
            for (int nt = 0; nt < 4; nt++) {
                int c = bn + wn + nt * 8 + 2 * t;
                #pragma unroll
                for (int half = 0; half < 2; half++) {
                    int r = bm + wm + mt * 16 + g + half * 8;
                    g_vT[(size_t)c * TT + r]       = __float2half_rn(acc[mt][nt][half * 2]);
                    g_vT[(size_t)(c + 1) * TT + r] = __float2half_rn(acc[mt][nt][half * 2 + 1]);
                }
            }
    }
}

// ---------------- generic fp16 GEMM NT, fp32 out (+res +bias); M=TT, N=DM ----------------
__global__ __launch_bounds__(256, 2) void gemm_hf(
    const __half* __restrict__ A, const __half* __restrict__ B, float* __restrict__ C,
    int K, const float* __restrict__ res, const float* __restrict__ bias) {
    extern __shared__ uint32_t sm[];
    uint32_t sb = (uint32_t)__cvta_generic_to_shared(sm);
    int bm = blockIdx.y * 128, bn = blockIdx.x * 64;
    int tid = threadIdx.x, wid = tid >> 5, lane = tid & 31;
    int g = lane >> 2, t = lane & 3;
    int wm = (wid & 3) * 32, wn = (wid >> 2) * 32;
    const __half* Ab = A + (size_t)bm * K;
    const __half* Bb = B + (size_t)bn * K;
    float acc[2][4][4] = {};
    {
        #pragma unroll
        for (int i = tid; i < 1024; i += 256) { int r = i >> 3, c = i & 7;
            cpa(sb + (r * SH + c * 4) * 4, Ab + (size_t)r * K + c * 8); }
        #pragma unroll
        for (int i = tid; i < 512; i += 256) { int r = i >> 3, c = i & 7;
            cpa(sb + (2 * AW + r * SH + c * 4) * 4, Bb + (size_t)r * K + c * 8); }
        cpcommit();
    }
    int nk = K >> 6;
    for (int it = 0; it < nk; it++) {
        int cur = it & 1;
        if (it + 1 < nk) {
            int k0 = (it + 1) << 6, nxt = cur ^ 1;
            #pragma unroll
            for (int i = tid; i < 1024; i += 256) { int r = i >> 3, c = i & 7;
                cpa(sb + (nxt * AW + r * SH + c * 4) * 4, Ab + (size_t)r * K + k0 + c * 8); }
            #pragma unroll
            for (int i = tid; i < 512; i += 256) { int r = i >> 3, c = i & 7;
                cpa(sb + (2 * AW + nxt * BW + r * SH + c * 4) * 4, Bb + (size_t)r * K + k0 + c * 8); }
            cpcommit();
            cpwait<1>();
        } else cpwait<0>();
        __syncthreads();
        const uint32_t* Ac = sm + cur * AW;
        const uint32_t* Bc = sm + 2 * AW + cur * BW;
        GEMM_FRAG_COMPUTE(Ac, Bc, acc)
        __syncthreads();
    }
    #pragma unroll
    for (int mt = 0; mt < 2; mt++)
        #pragma unroll
        for (int nt = 0; nt < 4; nt++) {
            int c = bn + wn + nt * 8 + 2 * t;
            #pragma unroll
            for (int half = 0; half < 2; half++) {
                int r = bm + wm + mt * 16 + g + half * 8;
                float2 v = make_float2(acc[mt][nt][half * 2], acc[mt][nt][half * 2 + 1]);
                if (res) { float2 rr = *(const float2*)(res + (size_t)r * DM + c); v.x += rr.x; v.y += rr.y; }
                if (bias) { v.x += bias[c]; v.y += bias[c + 1]; }
                *(float2*)(C + (size_t)r * DM + c) = v;
            }
        }
}

// ---------------- dual gated GEMM: hidden = (h2@Wp1^T)*(h2@Wp2^T), fp16 out ----------------
__global__ __launch_bounds__(256, 2) void gemm_dual() {
    extern __shared__ uint32_t sm[];
    uint32_t sb = (uint32_t)__cvta_generic_to_shared(sm);
    int bm = blockIdx.y * 128, bn = blockIdx.x * 64;
    int tid = threadIdx.x, wid = tid >> 5, lane = tid & 31;
    int g = lane >> 2, t = lane & 3;
    int wm = (wid & 3) * 32, wn = (wid >> 2) * 32;
    const __half* Ab = g_h2 + (size_t)bm * DM;
    const __half* B1b = hWp1 + (size_t)bn * DM;
    const __half* B2b = hWp2 + (size_t)bn * DM;
    float acc1[2][4][4] = {};
    float acc2[2][4][4] = {};
    {
        #pragma unroll
        for (int i = tid; i < 1024; i += 256) { int r = i >> 3, c = i & 7;
            cpa(sb + (r * SH + c * 4) * 4, Ab + (size_t)r * DM + c * 8); }
        #pragma unroll
        for (int i = tid; i < 512; i += 256) { int r = i >> 3, c = i & 7;
            cpa(sb + (2 * AW + r * SH + c * 4) * 4, B1b + (size_t)r * DM + c * 8);
            cpa(sb + (2 * AW + 2 * BW + r * SH + c * 4) * 4, B2b + (size_t)r * DM + c * 8); }
        cpcommit();
    }
    const int nk = DM / 64;
    for (int it = 0; it < nk; it++) {
        int cur = it & 1;
        if (it + 1 < nk) {
            int k0 = (it + 1) * 64, nxt = cur ^ 1;
            #pragma unroll
            for (int i = tid; i < 1024; i += 256) { int r = i >> 3, c = i & 7;
                cpa(sb + (nxt * AW + r * SH + c * 4) * 4, Ab + (size_t)r * DM + k0 + c * 8); }
            #pragma unroll
            for (int i = tid; i < 512; i += 256) { int r = i >> 3, c = i & 7;
                cpa(sb + (2 * AW + nxt * BW + r * SH + c * 4) * 4, B1b + (size_t)r * DM + k0 + c * 8);
                cpa(sb + (2 * AW + 2 * BW + nxt * BW + r * SH + c * 4) * 4, B2b + (size_t)r * DM + k0 + c * 8); }
            cpcommit();
            cpwait<1>();
        } else cpwait<0>();
        __syncthreads();
        const uint32_t* Ac = sm + cur * AW;
        const uint32_t* B1c = sm + 2 * AW + cur * BW;
        const uint32_t* B2c = sm + 2 * AW + 2 * BW + cur * BW;
        #pragma unroll
        for (int kk = 0; kk < 4; kk++) {
            int kb = kk * 8;
            uint32_t af[2][4], bf1[4][2], bf2[4][2];
            #pragma unroll
            for (int mt = 0; mt < 2; mt++) {
                int r0 = wm + mt * 16 + g;
                af[mt][0] = Ac[r0 * SH + kb + t];
                af[mt][1] = Ac[(r0 + 8) * SH + kb + t];
                af[mt][2] = Ac[r0 * SH + kb + 4 + t];
                af[mt][3] = Ac[(r0 + 8) * SH + kb + 4 + t];
            }
            #pragma unroll
            for (int nt = 0; nt < 4; nt++) {
                int c0 = wn + nt * 8 + g;
                bf1[nt][0] = B1c[c0 * SH + kb + t];
                bf1[nt][1] = B1c[c0 * SH + kb + 4 + t];
                bf2[nt][0] = B2c[c0 * SH + kb + t];
                bf2[nt][1] = B2c[c0 * SH + kb + 4 + t];
            }
            #pragma unroll
            for (int mt = 0; mt < 2; mt++)
                #pragma unroll
                for (int nt = 0; nt < 4; nt++) {
                    mma16(acc1[mt][nt], af[mt], bf1[nt]);
                    mma16(acc2[mt][nt], af[mt], bf2[nt]);
                }
        }
        __syncthreads();
    }
    #pragma unroll
    for (int mt = 0; mt < 2; mt++)
        #pragma unroll
        for (int nt = 0; nt < 4; nt++) {
            int c = bn + wn + nt * 8 + 2 * t;
            #pragma unroll
            for (int half = 0; half < 2; half++) {
                int r = bm + wm + mt * 16 + g + half * 8;
                *(uint32_t*)(g_hidden + (size_t)r * DHID + c) =
                    packh(acc1[mt][nt][half * 2] * acc2[mt][nt][half * 2],
                          acc1[mt][nt][half * 2 + 1] * acc2[mt][nt][half * 2 + 1]);
            }
        }
}

// ---------------- RoPE (fp16 in-place) ----------------
__global__ void rope_kernel() {
    int idx = blockIdx.x * blockDim.x + threadIdx.x;
    if (idx >= TT * 32) return;
    int tok = idx >> 5, i = idx & 31;
    float inv = powf(10000.f, -(float)(2 * i) / 64.f);
    float ang = (float)tok * inv;
    float c = cosf(ang), s = sinf(ang);
    #pragma unroll
    for (int h = 0; h < NH; h++) {
        int base = tok * DM + h * DH;
        {
            float a = __half2float(g_q[base + i]), b = __half2float(g_q[base + 32 + i]);
            g_q[base + i] = __float2half_rn(a * c + b * s);
            g_q[base + 32 + i] = __float2half_rn(-a * s + b * c);
        }
        {
            float a = __half2float(g_k[base + i]), b = __half2float(g_k[base + 32 + i]);
            g_k[base + i] = __float2half_rn(a * c + b * s);
            g_k[base + 32 + i] = __float2half_rn(-a * s + b * c);
        }
        {
            float a = __half2float(g_q2[base + i]), b = __half2float(g_q2[base + 32 + i]);
            g_q2[base + i] = __float2half_rn(a * c + b * s);
            g_q2[base + 32 + i] = __float2half_rn(-a * s + b * c);
        }
        {
            float a = __half2float(g_k2[base + i]), b = __half2float(g_k2[base + 32 + i]);
            g_k2[base + i] = __float2half_rn(a * c + b * s);
            g_k2[base + 32 + i] = __float2half_rn(-a * s + b * c);
        }
    }
}

// ---------------- attention (fp16 mma, double-buffered K/V, 2 CTAs/SM) ----------------
#define ATW 2304
#define ATT_SMEM (8 * ATW * 4)
__global__ __launch_bounds__(256, 2) void attn_h() {
    extern __shared__ uint32_t sm[];
    uint32_t sb = (uint32_t)__cvta_generic_to_shared(sm);
    int hd = blockIdx.y;
    int qt = (int)gridDim.x - 1 - (int)blockIdx.x;
    int tid = threadIdx.x, wid = tid >> 5, lane = tid & 31;
    int g = lane >> 2, t = lane & 3;
    int wm = (wid & 3) * 16, wn = (wid >> 2) * 32;
    int r0 = wm + g;
    int hoff = hd * DH;

    #pragma unroll
    for (int i = tid; i < 512; i += 256) {
        int r = i >> 3, c = i & 7;
        size_t go = (size_t)(qt * 64 + r) * DM + hoff + c * 8;
        cpa(sb + (7 * ATW + r * SH + c * 4) * 4, g_q + go);
        cpa(sb + (r * SH + c * 4) * 4, g_q2 + go);
    }
    cpcommit();
    #pragma unroll
    for (int i = tid; i < 512; i += 256) {
        int r = i >> 3, c = i & 7;
        size_t go = (size_t)r * DM + hoff + c * 8;
        cpa(sb + (1 * ATW + r * SH + c * 4) * 4, g_k + go);
        cpa(sb + (3 * ATW + r * SH + c * 4) * 4, g_k2 + go);
        cpa(sb + (5 * ATW + r * SH + c * 4) * 4, g_vT + (size_t)(hoff + r) * TT + c * 8);
    }
    cpcommit();
    cpwait<1>();
    __syncthreads();

    uint32_t aq[4][4];
    {
        const uint32_t* Ps = sm + 7 * ATW;
        #pragma unroll
        for (int kk = 0; kk < 4; kk++) {
            int kb = kk * 8;
            aq[kk][0] = Ps[r0 * SH + kb + t];
            aq[kk][1] = Ps[(r0 + 8) * SH + kb + t];
            aq[kk][2] = Ps[r0 * SH + kb + 4 + t];
            aq[kk][3] = Ps[(r0 + 8) * SH + kb + 4 + t];
        }
    }

    float zacc[4][4] = {};
    const uint32_t* Q2s = sm;
    uint32_t* Pw = sm + 7 * ATW;
    int wnp = wn >> 1;
    for (int st = 0; st <= qt; st++) {
        int buf = st & 1;
        if (st < qt) {
            int sn = st + 1, nb = buf ^ 1;
            #pragma unroll
            for (int i = tid; i < 512; i += 256) {
                int r = i >> 3, c = i & 7;
                size_t go = (size_t)(sn * 64 + r) * DM + hoff + c * 8;
                cpa(sb + ((1 + nb) * ATW + r * SH + c * 4) * 4, g_k + go);
                cpa(sb + ((3 + nb) * ATW + r * SH + c * 4) * 4, g_k2 + go);
                cpa(sb + ((5 + nb) * ATW + r * SH + c * 4) * 4,
                    g_vT + (size_t)(hoff + r) * TT + sn * 64 + c * 8);
            }
            cpcommit();
            cpwait<1>();
        } else cpwait<0>();
        __syncthreads();
        const uint32_t* Ks  = sm + (1 + buf) * ATW;
        const uint32_t* K2s = sm + (3 + buf) * ATW;
        const uint32_t* Vs  = sm + (5 + buf) * ATW;

        float s1[4][4] = {}, s2[4][4] = {};
        #pragma unroll
        for (int kk = 0; kk < 4; kk++) {
            int kb = kk * 8;
            uint32_t aq2[4];
            aq2[0] = Q2s[r0 * SH + kb + t];
            aq2[1] = Q2s[(r0 + 8) * SH + kb + t];
            aq2[2] = Q2s[r0 * SH + kb + 4 + t];
            aq2[3] = Q2s[(r0 + 8) * SH + kb + 4 + t];
            #pragma unroll
            for (int nt = 0; nt < 4; nt++) {
                int c0 = wn + nt * 8 + g;
                uint32_t bk[2], bk2[2];
                bk[0]  = Ks[c0 * SH + kb + t];
                bk[1]  = Ks[c0 * SH + kb + 4 + t];
                bk2[0] = K2s[c0 * SH + kb + t];
                bk2[1] = K2s[c0 * SH + kb + 4 + t];
                mma16(s1[nt], aq[kk], bk);
                mma16(s2[nt], aq2, bk2);
            }
        }
        #pragma unroll
        for (int nt = 0; nt < 4; nt++)
            #pragma unroll
            for (int half = 0; half < 2; half++) {
                int qr = wm + g + half * 8;
                int sc = wn + nt * 8 + 2 * t;
                float p0 = s1[nt][half * 2] * s2[nt][half * 2] * (1.f / 4096.f);
                float p1 = s1[nt][half * 2 + 1] * s2[nt][half * 2 + 1] * (1.f / 4096.f);
                if (st == qt) { if (sc > qr) p0 = 0.f; if (sc + 1 > qr) p1 = 0.f; }
                Pw[qr * SH + wnp + nt * 4 + t] = packh(p0, p1);
            }
        __syncthreads();
        #pragma unroll
        for (int kc = 0; kc < 4; kc++) {
            int kb = kc * 8;
            uint32_t ap[4];
            ap[0] = Pw[r0 * SH + kb + t];
            ap[1] = Pw[(r0 + 8) * SH + kb + t];
            ap[2] = Pw[r0 * SH + kb + 4 + t];
            ap[3] = Pw[(r0 + 8) * SH + kb + 4 + t];
            #pragma unroll
            for (int nt = 0; nt < 4; nt++) {
                int n = wn + nt * 8 + g;
                uint32_t bv[2];
                bv[0] = Vs[n * SH + kb + t];
                bv[1] = Vs[n * SH + kb + 4 + t];
                mma16(zacc[nt], ap, bv);
            }
        }
        __syncthreads();
    }
    #pragma unroll
    for (int nt = 0; nt < 4; nt++) {
        int c = hoff + wn + nt * 8 + 2 * t;
        #pragma unroll
        for (int half = 0; half < 2; half++) {
            int r = qt * 64 + wm + g + half * 8;
            *(uint32_t*)(g_z + (size_t)r * DM + c) =
                packh(zacc[nt][half * 2], zacc[nt][half * 2 + 1]);
        }
    }
}

// ---------------- launch ----------------
extern "C" void kernel_launch(void* const* d_in, const int* in_sizes, int n_in,
                              void* d_out, int out_size) {
    const float* x = (const float*)d_in[0];
    const float* bd = (const float*)d_in[10];

    __half *z_p, *hWo_p, *hidden_p, *hWd_p, *h_p, *h2_p;
    float* x1_p;
    cudaGetSymbolAddress((void**)&z_p, g_z);
    cudaGetSymbolAddress((void**)&hWo_p, hWo);
    cudaGetSymbolAddress((void**)&hidden_p, g_hidden);
    cudaGetSymbolAddress((void**)&hWd_p, hWd);
    cudaGetSymbolAddress((void**)&x1_p, g_x1);
    cudaGetSymbolAddress((void**)&h_p, g_h);
    cudaGetSymbolAddress((void**)&h2_p, g_h2);

    cudaFuncSetAttribute(gemm_proj, cudaFuncAttributeMaxDynamicSharedMemorySize, GEMM_SMEM);
    cudaFuncSetAttribute(gemm_hf, cudaFuncAttributeMaxDynamicSharedMemorySize, GEMM_SMEM);
    cudaFuncSetAttribute(gemm_dual, cudaFuncAttributeMaxDynamicSharedMemorySize, DUAL_SMEM);
    cudaFuncSetAttribute(attn_h, cudaFuncAttributeMaxDynamicSharedMemorySize, ATT_SMEM);

    W9 w;
    for (int i = 0; i < 9; i++) w.s[i] = (const float*)d_in[1 + i];
    cvtw_all<<<(NF4 + 255) / 256, 256>>>(w);

    rmsnorm_kernel<<<TT, 256>>>(x, h_p);
    gemm_proj<<<dim3(60, TT / 128), 256, GEMM_SMEM>>>();
    rope_kernel<<<TT * 32 / 256, 256>>>();
    attn_h<<<dim3(TT / 64, NH), 256, ATT_SMEM>>>();
    gemm_hf<<<dim3(DM / 64, TT / 128), 256, GEMM_SMEM>>>(z_p, hWo_p, x1_p, DM, x, nullptr);
    rmsnorm_kernel<<<TT, 256>>>(x1_p, h2_p);
    gemm_dual<<<dim3(DHID / 64, TT / 128), 256, DUAL_SMEM>>>();
    gemm_hf<<<dim3(DM / 64, TT / 128), 256, GEMM_SMEM>>>(hidden_p, hWd_p, (float*)d_out, DHID, x1_p, bd);
}

// round 6
// speedup vs baseline: 8.2324x; 1.0769x over previous
#include <cuda_runtime.h>
#include <cuda_fp16.h>
#include <cstdint>
#include <math.h>

#define TT 2048
#define DM 768
#define NH 12
#define DH 64
#define DHID 3072
#define SH 36            // smem row stride in uint32 words (32 data pairs + 4 pad)

// ---------------- scratch (device globals; no allocation) ----------------
__device__ __half g_h[TT * DM];
__device__ __half g_q[TT * DM];
__device__ __half g_k[TT * DM];
__device__ __half g_q2[TT * DM];
__device__ __half g_k2[TT * DM];
__device__ __half g_vT[DM * TT];     // per-head transposed V: vT[dim][token]
__device__ __half g_z[TT * DM];
__device__ float  g_x1[TT * DM];
__device__ __half g_h2[TT * DM];
__device__ __half g_hidden[TT * DHID];

// fp16 weights
__device__ __half hWq[DM * DM];
__device__ __half hWk[DM * DM];
__device__ __half hWq2[DM * DM];
__device__ __half hWk2[DM * DM];
__device__ __half hWv[DM * DM];
__device__ __half hWo[DM * DM];
__device__ __half hWp1[DHID * DM];
__device__ __half hWp2[DHID * DM];
__device__ __half hWd[DM * DHID];

// ---------------- helpers ----------------
__device__ __forceinline__ void cpa(uint32_t dst, const void* src) {
    asm volatile("cp.async.ca.shared.global [%0], [%1], 16;" :: "r"(dst), "l"(src));
}
__device__ __forceinline__ void cpcommit() { asm volatile("cp.async.commit_group;"); }
template <int N> __device__ __forceinline__ void cpwait() {
    asm volatile("cp.async.wait_group %0;" :: "n"(N));
}
__device__ __forceinline__ void mma16(float* d, const uint32_t* a, const uint32_t* b) {
    asm volatile(
        "mma.sync.aligned.m16n8k16.row.col.f32.f16.f16.f32 "
        "{%0,%1,%2,%3},{%4,%5,%6,%7},{%8,%9},{%0,%1,%2,%3};\n"
        : "+f"(d[0]), "+f"(d[1]), "+f"(d[2]), "+f"(d[3])
        : "r"(a[0]), "r"(a[1]), "r"(a[2]), "r"(a[3]), "r"(b[0]), "r"(b[1]));
}
__device__ __forceinline__ uint32_t packh(float a, float b) {
    __half2 h = __floats2half2_rn(a, b);
    return *(uint32_t*)&h;
}

// ---------------- weight convert fp32 -> fp16 (rn) ----------------
struct W9 { const float* s[9]; };
__device__ __forceinline__ __half* wdst(int wi) {
    switch (wi) {
        case 0: return hWq;  case 1: return hWk;  case 2: return hWq2;
        case 3: return hWk2; case 4: return hWv;  case 5: return hWo;
        case 6: return hWp1; case 7: return hWp2; default: return hWd;
    }
}
#define NF4 2654208
__global__ void cvtw_all(W9 w) {
    int i = blockIdx.x * 256 + threadIdx.x;
    if (i >= NF4) return;
    int wi; int off;
    if (i < 884736) { wi = i / 147456; off = i % 147456; }
    else { int j = i - 884736; wi = 6 + j / 589824; off = j % 589824; }
    float4 v = ((const float4*)w.s[wi])[off];
    __half2* d = (__half2*)wdst(wi);
    d[2 * off]     = __floats2half2_rn(v.x, v.y);
    d[2 * off + 1] = __floats2half2_rn(v.z, v.w);
}

// ---------------- RMSNorm (fp32 in -> fp16 out) ----------------
__global__ void rmsnorm_kernel(const float* __restrict__ x, __half* __restrict__ o) {
    int row = blockIdx.x;
    const float* xr = x + row * DM;
    float s = 0.f;
    for (int i = threadIdx.x; i < DM; i += blockDim.x) { float v = xr[i]; s += v * v; }
    __shared__ float red[32];
    for (int off = 16; off; off >>= 1) s += __shfl_down_sync(0xffffffffu, s, off);
    if ((threadIdx.x & 31) == 0) red[threadIdx.x >> 5] = s;
    __syncthreads();
    if (threadIdx.x < 32) {
        s = (threadIdx.x < (blockDim.x >> 5)) ? red[threadIdx.x] : 0.f;
        for (int off = 16; off; off >>= 1) s += __shfl_down_sync(0xffffffffu, s, off);
        if (threadIdx.x == 0) red[0] = rsqrtf(s / (float)DM + 1e-6f);
    }
    __syncthreads();
    float scale = red[0];
    for (int i = threadIdx.x; i < DM; i += blockDim.x)
        o[row * DM + i] = __float2half_rn(xr[i] * scale);
}

// ================= geometry =================
#define AW (128 * SH)
#define BW (64 * SH)
#define GEMM_SMEM ((2 * AW + 2 * BW) * 4)
#define DUAL_SMEM ((2 * AW + 4 * BW) * 4)
#define GEMM64_SMEM (4 * BW * 4)

#define GEMM_FRAG_COMPUTE(Ac, Bc, accv)                                        \
    _Pragma("unroll")                                                          \
    for (int kk = 0; kk < 4; kk++) {                                           \
        int kb = kk * 8;                                                       \
        uint32_t af[2][4], bf[4][2];                                           \
        _Pragma("unroll")                                                      \
        for (int mt = 0; mt < 2; mt++) {                                       \
            int r0 = wm + mt * 16 + g;                                         \
            af[mt][0] = (Ac)[r0 * SH + kb + t];                                \
            af[mt][1] = (Ac)[(r0 + 8) * SH + kb + t];                          \
            af[mt][2] = (Ac)[r0 * SH + kb + 4 + t];                            \
            af[mt][3] = (Ac)[(r0 + 8) * SH + kb + 4 + t];                      \
        }                                                                      \
        _Pragma("unroll")                                                      \
        for (int nt = 0; nt < 4; nt++) {                                       \
            int c0 = wn + nt * 8 + g;                                          \
            bf[nt][0] = (Bc)[c0 * SH + kb + t];                                \
            bf[nt][1] = (Bc)[c0 * SH + kb + 4 + t];                            \
        }                                                                      \
        _Pragma("unroll")                                                      \
        for (int mt = 0; mt < 2; mt++)                                         \
            _Pragma("unroll")                                                  \
            for (int nt = 0; nt < 4; nt++) mma16(accv[mt][nt], af[mt], bf[nt]);\
    }

// ---------------- fused 5-projection GEMM + RoPE epilogue ----------------
__global__ __launch_bounds__(256, 2) void gemm_proj() {
    extern __shared__ uint32_t sm[];
    uint32_t sb = (uint32_t)__cvta_generic_to_shared(sm);
    int widx = blockIdx.x / 12;
    int bn = (blockIdx.x % 12) * 64;
    int bm = blockIdx.y * 128;
    const __half* Bw = (widx == 0) ? hWq : (widx == 1) ? hWk : (widx == 2) ? hWq2
                       : (widx == 3) ? hWk2 : hWv;
    int tid = threadIdx.x, wid = tid >> 5, lane = tid & 31;
    int g = lane >> 2, t = lane & 3;
    int wm = (wid & 3) * 32, wn = (wid >> 2) * 32;
    const __half* Ab = g_h + (size_t)bm * DM;
    const __half* Bb = Bw + (size_t)bn * DM;
    float acc[2][4][4] = {};
    {
        #pragma unroll
        for (int i = tid; i < 1024; i += 256) { int r = i >> 3, c = i & 7;
            cpa(sb + (r * SH + c * 4) * 4, Ab + (size_t)r * DM + c * 8); }
        #pragma unroll
        for (int i = tid; i < 512; i += 256) { int r = i >> 3, c = i & 7;
            cpa(sb + (2 * AW + r * SH + c * 4) * 4, Bb + (size_t)r * DM + c * 8); }
        cpcommit();
    }
    const int nk = DM / 64;
    for (int it = 0; it < nk; it++) {
        int cur = it & 1;
        if (it + 1 < nk) {
            int k0 = (it + 1) * 64, nxt = cur ^ 1;
            #pragma unroll
            for (int i = tid; i < 1024; i += 256) { int r = i >> 3, c = i & 7;
                cpa(sb + (nxt * AW + r * SH + c * 4) * 4, Ab + (size_t)r * DM + k0 + c * 8); }
            #pragma unroll
            for (int i = tid; i < 512; i += 256) { int r = i >> 3, c = i & 7;
                cpa(sb + (2 * AW + nxt * BW + r * SH + c * 4) * 4, Bb + (size_t)r * DM + k0 + c * 8); }
            cpcommit();
            cpwait<1>();
        } else cpwait<0>();
        __syncthreads();
        const uint32_t* Ac = sm + cur * AW;
        const uint32_t* Bc = sm + 2 * AW + cur * BW;
        GEMM_FRAG_COMPUTE(Ac, Bc, acc)
        __syncthreads();
    }
    if (widx < 4) {
        // ---- RoPE fused epilogue ----
        __half* C = (widx == 0) ? g_q : (widx == 1) ? g_k : (widx == 2) ? g_q2 : g_k2;
        float* Sg = (float*)sm;  // 128 x 64, stride 68 floats (34816 B <= GEMM_SMEM)
        #pragma unroll
        for (int mt = 0; mt < 2; mt++)
            #pragma unroll
            for (int nt = 0; nt < 4; nt++) {
                int c = wn + nt * 8 + 2 * t;
                #pragma unroll
                for (int half = 0; half < 2; half++) {
                    int r = wm + mt * 16 + g + half * 8;
                    *(float2*)(Sg + r * 68 + c) =
                        make_float2(acc[mt][nt][half * 2], acc[mt][nt][half * 2 + 1]);
                }
            }
        __syncthreads();
        #pragma unroll
        for (int i = tid; i < 1024; i += 256) {
            int r = i >> 3, u = (i & 7) * 4;
            int token = bm + r;
            float4 a4 = *(float4*)(Sg + r * 68 + u);
            float4 b4 = *(float4*)(Sg + r * 68 + u + 32);
            float oa[4], ob[4];
            #pragma unroll
            for (int d = 0; d < 4; d++) {
                float inv = powf(10000.f, -(float)(u + d) / 32.f);
                float ang = (float)token * inv;
                float sn, cs;
                sincosf(ang, &sn, &cs);
                float av = (&a4.x)[d], bv = (&b4.x)[d];
                oa[d] = av * cs + bv * sn;
                ob[d] = -av * sn + bv * cs;
            }
            uint2 va, vb;
            va.x = packh(oa[0], oa[1]); va.y = packh(oa[2], oa[3]);
            vb.x = packh(ob[0], ob[1]); vb.y = packh(ob[2], ob[3]);
            *(uint2*)(C + (size_t)token * DM + bn + u) = va;
            *(uint2*)(C + (size_t)token * DM + bn + u + 32) = vb;
        }
    } else {
        // V: write transposed vT[col][row]
        #pragma unroll
        for (int mt = 0; mt < 2; mt++)
            #pragma unroll
            for (int nt = 0; nt < 4; nt++) {
                int c = bn + wn + nt * 8 + 2 * t;
                #pragma unroll
                for (int half = 0; half < 2; half++) {
                    int r = bm + wm + mt * 16 + g + half * 8;
                    g_vT[(size_t)c * TT + r]       = __float2half_rn(acc[mt][nt][half * 2]);
                    g_vT[(size_t)(c + 1) * TT + r] = __float2half_rn(acc[mt][nt][half * 2 + 1]);
                }
            }
    }
}

// ---------------- BM=64 fp16 GEMM NT, fp32 out (+res +bias), N=DM ----------------
// 256 threads, 8 warps: warp tile 16x32 (wm 4x16, wn 2x32). 3 CTAs/SM.
__global__ __launch_bounds__(256, 3) void gemm_hf64(
    const __half* __restrict__ A, const __half* __restrict__ B, float* __restrict__ C,
    int K, const float* __restrict__ res, const float* __restrict__ bias) {
    extern __shared__ uint32_t sm[];
    uint32_t sb = (uint32_t)__cvta_generic_to_shared(sm);
    int bm = blockIdx.y * 64, bn = blockIdx.x * 64;
    int tid = threadIdx.x, wid = tid >> 5, lane = tid & 31;
    int g = lane >> 2, t = lane & 3;
    int wm = (wid & 3) * 16, wn = (wid >> 2) * 32;
    const __half* Ab = A + (size_t)bm * K;
    const __half* Bb = B + (size_t)bn * K;
    float acc[4][4] = {};
    {
        #pragma unroll
        for (int i = tid; i < 512; i += 256) { int r = i >> 3, c = i & 7;
            cpa(sb + (r * SH + c * 4) * 4, Ab + (size_t)r * K + c * 8);
            cpa(sb + (2 * BW + r * SH + c * 4) * 4, Bb + (size_t)r * K + c * 8); }
        cpcommit();
    }
    int nk = K >> 6;
    for (int it = 0; it < nk; it++) {
        int cur = it & 1;
        if (it + 1 < nk) {
            int k0 = (it + 1) << 6, nxt = cur ^ 1;
            #pragma unroll
            for (int i = tid; i < 512; i += 256) { int r = i >> 3, c = i & 7;
                cpa(sb + (nxt * BW + r * SH + c * 4) * 4, Ab + (size_t)r * K + k0 + c * 8);
                cpa(sb + (2 * BW + nxt * BW + r * SH + c * 4) * 4, Bb + (size_t)r * K + k0 + c * 8); }
            cpcommit();
            cpwait<1>();
        } else cpwait<0>();
        __syncthreads();
        const uint32_t* Ac = sm + cur * BW;
        const uint32_t* Bc = sm + 2 * BW + cur * BW;
        #pragma unroll
        for (int kk = 0; kk < 4; kk++) {
            int kb = kk * 8;
            uint32_t af[4], bf[4][2];
            int r0 = wm + g;
            af[0] = Ac[r0 * SH + kb + t];
            af[1] = Ac[(r0 + 8) * SH + kb + t];
            af[2] = Ac[r0 * SH + kb + 4 + t];
            af[3] = Ac[(r0 + 8) * SH + kb + 4 + t];
            #pragma unroll
            for (int nt = 0; nt < 4; nt++) {
                int c0 = wn + nt * 8 + g;
                bf[nt][0] = Bc[c0 * SH + kb + t];
                bf[nt][1] = Bc[c0 * SH + kb + 4 + t];
            }
            #pragma unroll
            for (int nt = 0; nt < 4; nt++) mma16(acc[nt], af, bf[nt]);
        }
        __syncthreads();
    }
    #pragma unroll
    for (int nt = 0; nt < 4; nt++) {
        int c = bn + wn + nt * 8 + 2 * t;
        #pragma unroll
        for (int half = 0; half < 2; half++) {
            int r = bm + wm + g + half * 8;
            float2 v = make_float2(acc[nt][half * 2], acc[nt][half * 2 + 1]);
            if (res) { float2 rr = *(const float2*)(res + (size_t)r * DM + c); v.x += rr.x; v.y += rr.y; }
            if (bias) { v.x += bias[c]; v.y += bias[c + 1]; }
            *(float2*)(C + (size_t)r * DM + c) = v;
        }
    }
}

// ---------------- dual gated GEMM: hidden = (h2@Wp1^T)*(h2@Wp2^T), fp16 out ----------------
__global__ __launch_bounds__(256, 2) void gemm_dual() {
    extern __shared__ uint32_t sm[];
    uint32_t sb = (uint32_t)__cvta_generic_to_shared(sm);
    int bm = blockIdx.y * 128, bn = blockIdx.x * 64;
    int tid = threadIdx.x, wid = tid >> 5, lane = tid & 31;
    int g = lane >> 2, t = lane & 3;
    int wm = (wid & 3) * 32, wn = (wid >> 2) * 32;
    const __half* Ab = g_h2 + (size_t)bm * DM;
    const __half* B1b = hWp1 + (size_t)bn * DM;
    const __half* B2b = hWp2 + (size_t)bn * DM;
    float acc1[2][4][4] = {};
    float acc2[2][4][4] = {};
    {
        #pragma unroll
        for (int i = tid; i < 1024; i += 256) { int r = i >> 3, c = i & 7;
            cpa(sb + (r * SH + c * 4) * 4, Ab + (size_t)r * DM + c * 8); }
        #pragma unroll
        for (int i = tid; i < 512; i += 256) { int r = i >> 3, c = i & 7;
            cpa(sb + (2 * AW + r * SH + c * 4) * 4, B1b + (size_t)r * DM + c * 8);
            cpa(sb + (2 * AW + 2 * BW + r * SH + c * 4) * 4, B2b + (size_t)r * DM + c * 8); }
        cpcommit();
    }
    const int nk = DM / 64;
    for (int it = 0; it < nk; it++) {
        int cur = it & 1;
        if (it + 1 < nk) {
            int k0 = (it + 1) * 64, nxt = cur ^ 1;
            #pragma unroll
            for (int i = tid; i < 1024; i += 256) { int r = i >> 3, c = i & 7;
                cpa(sb + (nxt * AW + r * SH + c * 4) * 4, Ab + (size_t)r * DM + k0 + c * 8); }
            #pragma unroll
            for (int i = tid; i < 512; i += 256) { int r = i >> 3, c = i & 7;
                cpa(sb + (2 * AW + nxt * BW + r * SH + c * 4) * 4, B1b + (size_t)r * DM + k0 + c * 8);
                cpa(sb + (2 * AW + 2 * BW + nxt * BW + r * SH + c * 4) * 4, B2b + (size_t)r * DM + k0 + c * 8); }
            cpcommit();
            cpwait<1>();
        } else cpwait<0>();
        __syncthreads();
        const uint32_t* Ac = sm + cur * AW;
        const uint32_t* B1c = sm + 2 * AW + cur * BW;
        const uint32_t* B2c = sm + 2 * AW + 2 * BW + cur * BW;
        #pragma unroll
        for (int kk = 0; kk < 4; kk++) {
            int kb = kk * 8;
            uint32_t af[2][4], bf1[4][2], bf2[4][2];
            #pragma unroll
            for (int mt = 0; mt < 2; mt++) {
                int r0 = wm + mt * 16 + g;
                af[mt][0] = Ac[r0 * SH + kb + t];
                af[mt][1] = Ac[(r0 + 8) * SH + kb + t];
                af[mt][2] = Ac[r0 * SH + kb + 4 + t];
                af[mt][3] = Ac[(r0 + 8) * SH + kb + 4 + t];
            }
            #pragma unroll
            for (int nt = 0; nt < 4; nt++) {
                int c0 = wn + nt * 8 + g;
                bf1[nt][0] = B1c[c0 * SH + kb + t];
                bf1[nt][1] = B1c[c0 * SH + kb + 4 + t];
                bf2[nt][0] = B2c[c0 * SH + kb + t];
                bf2[nt][1] = B2c[c0 * SH + kb + 4 + t];
            }
            #pragma unroll
            for (int mt = 0; mt < 2; mt++)
                #pragma unroll
                for (int nt = 0; nt < 4; nt++) {
                    mma16(acc1[mt][nt], af[mt], bf1[nt]);
                    mma16(acc2[mt][nt], af[mt], bf2[nt]);
                }
        }
        __syncthreads();
    }
    #pragma unroll
    for (int mt = 0; mt < 2; mt++)
        #pragma unroll
        for (int nt = 0; nt < 4; nt++) {
            int c = bn + wn + nt * 8 + 2 * t;
            #pragma unroll
            for (int half = 0; half < 2; half++) {
                int r = bm + wm + mt * 16 + g + half * 8;
                *(uint32_t*)(g_hidden + (size_t)r * DHID + c) =
                    packh(acc1[mt][nt][half * 2] * acc2[mt][nt][half * 2],
                          acc1[mt][nt][half * 2 + 1] * acc2[mt][nt][half * 2 + 1]);
            }
        }
}

// ---------------- attention (fp16 mma, double-buffered K/V, Q/Q2 in regs) ----------------
#define ATW 2304
#define ATT_SMEM (8 * ATW * 4)
__global__ __launch_bounds__(256, 2) void attn_h() {
    extern __shared__ uint32_t sm[];
    uint32_t sb = (uint32_t)__cvta_generic_to_shared(sm);
    int hd = blockIdx.y;
    int qt = (int)gridDim.x - 1 - (int)blockIdx.x;
    int tid = threadIdx.x, wid = tid >> 5, lane = tid & 31;
    int g = lane >> 2, t = lane & 3;
    int wm = (wid & 3) * 16, wn = (wid >> 2) * 32;
    int r0 = wm + g;
    int hoff = hd * DH;

    #pragma unroll
    for (int i = tid; i < 512; i += 256) {
        int r = i >> 3, c = i & 7;
        size_t go = (size_t)(qt * 64 + r) * DM + hoff + c * 8;
        cpa(sb + (7 * ATW + r * SH + c * 4) * 4, g_q + go);
        cpa(sb + (r * SH + c * 4) * 4, g_q2 + go);
    }
    cpcommit();
    #pragma unroll
    for (int i = tid; i < 512; i += 256) {
        int r = i >> 3, c = i & 7;
        size_t go = (size_t)r * DM + hoff + c * 8;
        cpa(sb + (1 * ATW + r * SH + c * 4) * 4, g_k + go);
        cpa(sb + (3 * ATW + r * SH + c * 4) * 4, g_k2 + go);
        cpa(sb + (5 * ATW + r * SH + c * 4) * 4, g_vT + (size_t)(hoff + r) * TT + c * 8);
    }
    cpcommit();
    cpwait<1>();
    __syncthreads();

    // hoist Q and Q2 fragments into registers
    uint32_t aq[4][4], aq2[4][4];
    {
        const uint32_t* Ps = sm + 7 * ATW;
        const uint32_t* Q2s = sm;
        #pragma unroll
        for (int kk = 0; kk < 4; kk++) {
            int kb = kk * 8;
            aq[kk][0] = Ps[r0 * SH + kb + t];
            aq[kk][1] = Ps[(r0 + 8) * SH + kb + t];
            aq[kk][2] = Ps[r0 * SH + kb + 4 + t];
            aq[kk][3] = Ps[(r0 + 8) * SH + kb + 4 + t];
            aq2[kk][0] = Q2s[r0 * SH + kb + t];
            aq2[kk][1] = Q2s[(r0 + 8) * SH + kb + t];
            aq2[kk][2] = Q2s[r0 * SH + kb + 4 + t];
            aq2[kk][3] = Q2s[(r0 + 8) * SH + kb + 4 + t];
        }
    }

    float zacc[4][4] = {};
    uint32_t* Pw = sm + 7 * ATW;
    int wnp = wn >> 1;
    for (int st = 0; st <= qt; st++) {
        int buf = st & 1;
        if (st < qt) {
            int sn = st + 1, nb = buf ^ 1;
            #pragma unroll
            for (int i = tid; i < 512; i += 256) {
                int r = i >> 3, c = i & 7;
                size_t go = (size_t)(sn * 64 + r) * DM + hoff + c * 8;
                cpa(sb + ((1 + nb) * ATW + r * SH + c * 4) * 4, g_k + go);
                cpa(sb + ((3 + nb) * ATW + r * SH + c * 4) * 4, g_k2 + go);
                cpa(sb + ((5 + nb) * ATW + r * SH + c * 4) * 4,
                    g_vT + (size_t)(hoff + r) * TT + sn * 64 + c * 8);
            }
            cpcommit();
            cpwait<1>();
        } else cpwait<0>();
        __syncthreads();
        const uint32_t* Ks  = sm + (1 + buf) * ATW;
        const uint32_t* K2s = sm + (3 + buf) * ATW;
        const uint32_t* Vs  = sm + (5 + buf) * ATW;

        float s1[4][4] = {}, s2[4][4] = {};
        #pragma unroll
        for (int kk = 0; kk < 4; kk++) {
            int kb = kk * 8;
            #pragma unroll
            for (int nt = 0; nt < 4; nt++) {
                int c0 = wn + nt * 8 + g;
                uint32_t bk[2], bk2[2];
                bk[0]  = Ks[c0 * SH + kb + t];
                bk[1]  = Ks[c0 * SH + kb + 4 + t];
                bk2[0] = K2s[c0 * SH + kb + t];
                bk2[1] = K2s[c0 * SH + kb + 4 + t];
                mma16(s1[nt], aq[kk], bk);
                mma16(s2[nt], aq2[kk], bk2);
            }
        }
        #pragma unroll
        for (int nt = 0; nt < 4; nt++)
            #pragma unroll
            for (int half = 0; half < 2; half++) {
                int qr = wm + g + half * 8;
                int sc = wn + nt * 8 + 2 * t;
                float p0 = s1[nt][half * 2] * s2[nt][half * 2] * (1.f / 4096.f);
                float p1 = s1[nt][half * 2 + 1] * s2[nt][half * 2 + 1] * (1.f / 4096.f);
                if (st == qt) { if (sc > qr) p0 = 0.f; if (sc + 1 > qr) p1 = 0.f; }
                Pw[qr * SH + wnp + nt * 4 + t] = packh(p0, p1);
            }
        __syncthreads();
        #pragma unroll
        for (int kc = 0; kc < 4; kc++) {
            int kb = kc * 8;
            uint32_t ap[4];
            ap[0] = Pw[r0 * SH + kb + t];
            ap[1] = Pw[(r0 + 8) * SH + kb + t];
            ap[2] = Pw[r0 * SH + kb + 4 + t];
            ap[3] = Pw[(r0 + 8) * SH + kb + 4 + t];
            #pragma unroll
            for (int nt = 0; nt < 4; nt++) {
                int n = wn + nt * 8 + g;
                uint32_t bv[2];
                bv[0] = Vs[n * SH + kb + t];
                bv[1] = Vs[n * SH + kb + 4 + t];
                mma16(zacc[nt], ap, bv);
            }
        }
        __syncthreads();
    }
    #pragma unroll
    for (int nt = 0; nt < 4; nt++) {
        int c = hoff + wn + nt * 8 + 2 * t;
        #pragma unroll
        for (int half = 0; half < 2; half++) {
            int r = qt * 64 + wm + g + half * 8;
            *(uint32_t*)(g_z + (size_t)r * DM + c) =
                packh(zacc[nt][half * 2], zacc[nt][half * 2 + 1]);
        }
    }
}

// ---------------- launch ----------------
extern "C" void kernel_launch(void* const* d_in, const int* in_sizes, int n_in,
                              void* d_out, int out_size) {
    const float* x = (const float*)d_in[0];
    const float* bd = (const float*)d_in[10];

    __half *z_p, *hWo_p, *hidden_p, *hWd_p, *h_p, *h2_p;
    float* x1_p;
    cudaGetSymbolAddress((void**)&z_p, g_z);
    cudaGetSymbolAddress((void**)&hWo_p, hWo);
    cudaGetSymbolAddress((void**)&hidden_p, g_hidden);
    cudaGetSymbolAddress((void**)&hWd_p, hWd);
    cudaGetSymbolAddress((void**)&x1_p, g_x1);
    cudaGetSymbolAddress((void**)&h_p, g_h);
    cudaGetSymbolAddress((void**)&h2_p, g_h2);

    cudaFuncSetAttribute(gemm_proj, cudaFuncAttributeMaxDynamicSharedMemorySize, GEMM_SMEM);
    cudaFuncSetAttribute(gemm_hf64, cudaFuncAttributeMaxDynamicSharedMemorySize, GEMM64_SMEM);
    cudaFuncSetAttribute(gemm_dual, cudaFuncAttributeMaxDynamicSharedMemorySize, DUAL_SMEM);
    cudaFuncSetAttribute(attn_h, cudaFuncAttributeMaxDynamicSharedMemorySize, ATT_SMEM);

    W9 w;
    for (int i = 0; i < 9; i++) w.s[i] = (const float*)d_in[1 + i];
    cvtw_all<<<(NF4 + 255) / 256, 256>>>(w);

    rmsnorm_kernel<<<TT, 256>>>(x, h_p);
    gemm_proj<<<dim3(60, TT / 128), 256, GEMM_SMEM>>>();          // projections + RoPE fused
    attn_h<<<dim3(TT / 64, NH), 256, ATT_SMEM>>>();
    gemm_hf64<<<dim3(DM / 64, TT / 64), 256, GEMM64_SMEM>>>(z_p, hWo_p, x1_p, DM, x, nullptr);
    rmsnorm_kernel<<<TT, 256>>>(x1_p, h2_p);
    gemm_dual<<<dim3(DHID / 64, TT / 128), 256, DUAL_SMEM>>>();
    gemm_hf64<<<dim3(DM / 64, TT / 64), 256, GEMM64_SMEM>>>(hidden_p, hWd_p, (float*)d_out, DHID, x1_p, bd);
}

// round 8
// speedup vs baseline: 8.2806x; 1.0059x over previous
#include <cuda_runtime.h>
#include <cuda_fp16.h>
#include <cstdint>
#include <math.h>

#define TT 2048
#define DM 768
#define NH 12
#define DH 64
#define DHID 3072
#define SH 36            // smem row stride in uint32 words (32 data pairs + 4 pad)

// ---------------- scratch (device globals; no allocation) ----------------
__device__ __half g_h[TT * DM];
__device__ __half g_q[TT * DM];
__device__ __half g_k[TT * DM];
__device__ __half g_q2[TT * DM];
__device__ __half g_k2[TT * DM];
__device__ __half g_vT[DM * TT];     // per-head transposed V: vT[dim][token]
__device__ __half g_z[TT * DM];
__device__ float  g_x1[TT * DM];
__device__ __half g_h2[TT * DM];
__device__ __half g_hidden[TT * DHID];

// fp16 weights
__device__ __half hWq[DM * DM];
__device__ __half hWk[DM * DM];
__device__ __half hWq2[DM * DM];
__device__ __half hWk2[DM * DM];
__device__ __half hWv[DM * DM];
__device__ __half hWo[DM * DM];
__device__ __half hWp1[DHID * DM];
__device__ __half hWp2[DHID * DM];
__device__ __half hWd[DM * DHID];

// ---------------- helpers ----------------
__device__ __forceinline__ void cpa(uint32_t dst, const void* src) {
    asm volatile("cp.async.ca.shared.global [%0], [%1], 16;" :: "r"(dst), "l"(src));
}
__device__ __forceinline__ void cpcommit() { asm volatile("cp.async.commit_group;"); }
template <int N> __device__ __forceinline__ void cpwait() {
    asm volatile("cp.async.wait_group %0;" :: "n"(N));
}
__device__ __forceinline__ void mma16(float* d, const uint32_t* a, const uint32_t* b) {
    asm volatile(
        "mma.sync.aligned.m16n8k16.row.col.f32.f16.f16.f32 "
        "{%0,%1,%2,%3},{%4,%5,%6,%7},{%8,%9},{%0,%1,%2,%3};\n"
        : "+f"(d[0]), "+f"(d[1]), "+f"(d[2]), "+f"(d[3])
        : "r"(a[0]), "r"(a[1]), "r"(a[2]), "r"(a[3]), "r"(b[0]), "r"(b[1]));
}
__device__ __forceinline__ uint32_t packh(float a, float b) {
    __half2 h = __floats2half2_rn(a, b);
    return *(uint32_t*)&h;
}

// ---------------- weight convert fp32 -> fp16 (rn) ----------------
struct W9 { const float* s[9]; };
__device__ __forceinline__ __half* wdst(int wi) {
    switch (wi) {
        case 0: return hWq;  case 1: return hWk;  case 2: return hWq2;
        case 3: return hWk2; case 4: return hWv;  case 5: return hWo;
        case 6: return hWp1; case 7: return hWp2; default: return hWd;
    }
}
#define NF4 2654208
__global__ void cvtw_all(W9 w) {
    int i = blockIdx.x * 256 + threadIdx.x;
    if (i >= NF4) return;
    int wi; int off;
    if (i < 884736) { wi = i / 147456; off = i % 147456; }
    else { int j = i - 884736; wi = 6 + j / 589824; off = j % 589824; }
    float4 v = ((const float4*)w.s[wi])[off];
    __half2* d = (__half2*)wdst(wi);
    d[2 * off]     = __floats2half2_rn(v.x, v.y);
    d[2 * off + 1] = __floats2half2_rn(v.z, v.w);
}

// ---------------- RMSNorm (fp32 in -> fp16 out) ----------------
__global__ void rmsnorm_kernel(const float* __restrict__ x, __half* __restrict__ o) {
    int row = blockIdx.x;
    const float* xr = x + row * DM;
    float s = 0.f;
    for (int i = threadIdx.x; i < DM; i += blockDim.x) { float v = xr[i]; s += v * v; }
    __shared__ float red[32];
    for (int off = 16; off; off >>= 1) s += __shfl_down_sync(0xffffffffu, s, off);
    if ((threadIdx.x & 31) == 0) red[threadIdx.x >> 5] = s;
    __syncthreads();
    if (threadIdx.x < 32) {
        s = (threadIdx.x < (blockDim.x >> 5)) ? red[threadIdx.x] : 0.f;
        for (int off = 16; off; off >>= 1) s += __shfl_down_sync(0xffffffffu, s, off);
        if (threadIdx.x == 0) red[0] = rsqrtf(s / (float)DM + 1e-6f);
    }
    __syncthreads();
    float scale = red[0];
    for (int i = threadIdx.x; i < DM; i += blockDim.x)
        o[row * DM + i] = __float2half_rn(xr[i] * scale);
}

// ================= geometry =================
#define AW (128 * SH)
#define BW (64 * SH)
#define GEMM_SMEM ((2 * AW + 2 * BW) * 4)
#define DUAL_SMEM ((2 * AW + 4 * BW) * 4)
#define GEMM64_SMEM (4 * BW * 4)

#define GEMM_FRAG_COMPUTE(Ac, Bc, accv)                                        \
    _Pragma("unroll")                                                          \
    for (int kk = 0; kk < 4; kk++) {                                           \
        int kb = kk * 8;                                                       \
        uint32_t af[2][4], bf[4][2];                                           \
        _Pragma("unroll")                                                      \
        for (int mt = 0; mt < 2; mt++) {                                       \
            int r0 = wm + mt * 16 + g;                                         \
            af[mt][0] = (Ac)[r0 * SH + kb + t];                                \
            af[mt][1] = (Ac)[(r0 + 8) * SH + kb + t];                          \
            af[mt][2] = (Ac)[r0 * SH + kb + 4 + t];                            \
            af[mt][3] = (Ac)[(r0 + 8) * SH + kb + 4 + t];                      \
        }                                                                      \
        _Pragma("unroll")                                                      \
        for (int nt = 0; nt < 4; nt++) {                                       \
            int c0 = wn + nt * 8 + g;                                          \
            bf[nt][0] = (Bc)[c0 * SH + kb + t];                                \
            bf[nt][1] = (Bc)[c0 * SH + kb + 4 + t];                            \
        }                                                                      \
        _Pragma("unroll")                                                      \
        for (int mt = 0; mt < 2; mt++)                                         \
            _Pragma("unroll")                                                  \
            for (int nt = 0; nt < 4; nt++) mma16(accv[mt][nt], af[mt], bf[nt]);\
    }

// ---------------- fused 5-projection GEMM + RoPE epilogue ----------------
__global__ __launch_bounds__(256, 2) void gemm_proj() {
    extern __shared__ uint32_t sm[];
    uint32_t sb = (uint32_t)__cvta_generic_to_shared(sm);
    int widx = blockIdx.x / 12;
    int bn = (blockIdx.x % 12) * 64;
    int bm = blockIdx.y * 128;
    const __half* Bw = (widx == 0) ? hWq : (widx == 1) ? hWk : (widx == 2) ? hWq2
                       : (widx == 3) ? hWk2 : hWv;
    int tid = threadIdx.x, wid = tid >> 5, lane = tid & 31;
    int g = lane >> 2, t = lane & 3;
    int wm = (wid & 3) * 32, wn = (wid >> 2) * 32;
    const __half* Ab = g_h + (size_t)bm * DM;
    const __half* Bb = Bw + (size_t)bn * DM;
    float acc[2][4][4] = {};
    {
        #pragma unroll
        for (int i = tid; i < 1024; i += 256) { int r = i >> 3, c = i & 7;
            cpa(sb + (r * SH + c * 4) * 4, Ab + (size_t)r * DM + c * 8); }
        #pragma unroll
        for (int i = tid; i < 512; i += 256) { int r = i >> 3, c = i & 7;
            cpa(sb + (2 * AW + r * SH + c * 4) * 4, Bb + (size_t)r * DM + c * 8); }
        cpcommit();
    }
    const int nk = DM / 64;
    for (int it = 0; it < nk; it++) {
        int cur = it & 1;
        if (it + 1 < nk) {
            int k0 = (it + 1) * 64, nxt = cur ^ 1;
            #pragma unroll
            for (int i = tid; i < 1024; i += 256) { int r = i >> 3, c = i & 7;
                cpa(sb + (nxt * AW + r * SH + c * 4) * 4, Ab + (size_t)r * DM + k0 + c * 8); }
            #pragma unroll
            for (int i = tid; i < 512; i += 256) { int r = i >> 3, c = i & 7;
                cpa(sb + (2 * AW + nxt * BW + r * SH + c * 4) * 4, Bb + (size_t)r * DM + k0 + c * 8); }
            cpcommit();
            cpwait<1>();
        } else cpwait<0>();
        __syncthreads();
        const uint32_t* Ac = sm + cur * AW;
        const uint32_t* Bc = sm + 2 * AW + cur * BW;
        GEMM_FRAG_COMPUTE(Ac, Bc, acc)
        __syncthreads();
    }
    if (widx < 4) {
        // ---- RoPE fused epilogue ----
        __half* C = (widx == 0) ? g_q : (widx == 1) ? g_k : (widx == 2) ? g_q2 : g_k2;
        float* Sg = (float*)sm;  // 128 x 64, stride 68 floats
        #pragma unroll
        for (int mt = 0; mt < 2; mt++)
            #pragma unroll
            for (int nt = 0; nt < 4; nt++) {
                int c = wn + nt * 8 + 2 * t;
                #pragma unroll
                for (int half = 0; half < 2; half++) {
                    int r = wm + mt * 16 + g + half * 8;
                    *(float2*)(Sg + r * 68 + c) =
                        make_float2(acc[mt][nt][half * 2], acc[mt][nt][half * 2 + 1]);
                }
            }
        __syncthreads();
        #pragma unroll
        for (int i = tid; i < 1024; i += 256) {
            int r = i >> 3, u = (i & 7) * 4;
            int token = bm + r;
            float4 a4 = *(float4*)(Sg + r * 68 + u);
            float4 b4 = *(float4*)(Sg + r * 68 + u + 32);
            float oa[4], ob[4];
            #pragma unroll
            for (int d = 0; d < 4; d++) {
                float inv = powf(10000.f, -(float)(u + d) / 32.f);
                float ang = (float)token * inv;
                float sn, cs;
                sincosf(ang, &sn, &cs);
                float av = (&a4.x)[d], bv = (&b4.x)[d];
                oa[d] = av * cs + bv * sn;
                ob[d] = -av * sn + bv * cs;
            }
            uint2 va, vb;
            va.x = packh(oa[0], oa[1]); va.y = packh(oa[2], oa[3]);
            vb.x = packh(ob[0], ob[1]); vb.y = packh(ob[2], ob[3]);
            *(uint2*)(C + (size_t)token * DM + bn + u) = va;
            *(uint2*)(C + (size_t)token * DM + bn + u + 32) = vb;
        }
    } else {
        // V: write transposed vT[col][row]
        #pragma unroll
        for (int mt = 0; mt < 2; mt++)
            #pragma unroll
            for (int nt = 0; nt < 4; nt++) {
                int c = bn + wn + nt * 8 + 2 * t;
                #pragma unroll
                for (int half = 0; half < 2; half++) {
                    int r = bm + wm + mt * 16 + g + half * 8;
                    g_vT[(size_t)c * TT + r]       = __float2half_rn(acc[mt][nt][half * 2]);
                    g_vT[(size_t)(c + 1) * TT + r] = __float2half_rn(acc[mt][nt][half * 2 + 1]);
                }
            }
    }
}

// ---------------- BM=64 fp16 GEMM NT, fp32 out (+res +bias), N=DM ----------------
__global__ __launch_bounds__(256, 3) void gemm_hf64(
    const __half* __restrict__ A, const __half* __restrict__ B, float* __restrict__ C,
    int K, const float* __restrict__ res, const float* __restrict__ bias) {
    extern __shared__ uint32_t sm[];
    uint32_t sb = (uint32_t)__cvta_generic_to_shared(sm);
    int bm = blockIdx.y * 64, bn = blockIdx.x * 64;
    int tid = threadIdx.x, wid = tid >> 5, lane = tid & 31;
    int g = lane >> 2, t = lane & 3;
    int wm = (wid & 3) * 16, wn = (wid >> 2) * 32;
    const __half* Ab = A + (size_t)bm * K;
    const __half* Bb = B + (size_t)bn * K;
    float acc[4][4] = {};
    {
        #pragma unroll
        for (int i = tid; i < 512; i += 256) { int r = i >> 3, c = i & 7;
            cpa(sb + (r * SH + c * 4) * 4, Ab + (size_t)r * K + c * 8);
            cpa(sb + (2 * BW + r * SH + c * 4) * 4, Bb + (size_t)r * K + c * 8); }
        cpcommit();
    }
    int nk = K >> 6;
    for (int it = 0; it < nk; it++) {
        int cur = it & 1;
        if (it + 1 < nk) {
            int k0 = (it + 1) << 6, nxt = cur ^ 1;
            #pragma unroll
            for (int i = tid; i < 512; i += 256) { int r = i >> 3, c = i & 7;
                cpa(sb + (nxt * BW + r * SH + c * 4) * 4, Ab + (size_t)r * K + k0 + c * 8);
                cpa(sb + (2 * BW + nxt * BW + r * SH + c * 4) * 4, Bb + (size_t)r * K + k0 + c * 8); }
            cpcommit();
            cpwait<1>();
        } else cpwait<0>();
        __syncthreads();
        const uint32_t* Ac = sm + cur * BW;
        const uint32_t* Bc = sm + 2 * BW + cur * BW;
        #pragma unroll
        for (int kk = 0; kk < 4; kk++) {
            int kb = kk * 8;
            uint32_t af[4], bf[4][2];
            int r0 = wm + g;
            af[0] = Ac[r0 * SH + kb + t];
            af[1] = Ac[(r0 + 8) * SH + kb + t];
            af[2] = Ac[r0 * SH + kb + 4 + t];
            af[3] = Ac[(r0 + 8) * SH + kb + 4 + t];
            #pragma unroll
            for (int nt = 0; nt < 4; nt++) {
                int c0 = wn + nt * 8 + g;
                bf[nt][0] = Bc[c0 * SH + kb + t];
                bf[nt][1] = Bc[c0 * SH + kb + 4 + t];
            }
            #pragma unroll
            for (int nt = 0; nt < 4; nt++) mma16(acc[nt], af, bf[nt]);
        }
        __syncthreads();
    }
    #pragma unroll
    for (int nt = 0; nt < 4; nt++) {
        int c = bn + wn + nt * 8 + 2 * t;
        #pragma unroll
        for (int half = 0; half < 2; half++) {
            int r = bm + wm + g + half * 8;
            float2 v = make_float2(acc[nt][half * 2], acc[nt][half * 2 + 1]);
            if (res) { float2 rr = *(const float2*)(res + (size_t)r * DM + c); v.x += rr.x; v.y += rr.y; }
            if (bias) { v.x += bias[c]; v.y += bias[c + 1]; }
            *(float2*)(C + (size_t)r * DM + c) = v;
        }
    }
}

// ---------------- dual gated GEMM: hidden = (h2@Wp1^T)*(h2@Wp2^T), fp16 out ----------------
__global__ __launch_bounds__(256, 2) void gemm_dual() {
    extern __shared__ uint32_t sm[];
    uint32_t sb = (uint32_t)__cvta_generic_to_shared(sm);
    int bm = blockIdx.y * 128, bn = blockIdx.x * 64;
    int tid = threadIdx.x, wid = tid >> 5, lane = tid & 31;
    int g = lane >> 2, t = lane & 3;
    int wm = (wid & 3) * 32, wn = (wid >> 2) * 32;
    const __half* Ab = g_h2 + (size_t)bm * DM;
    const __half* B1b = hWp1 + (size_t)bn * DM;
    const __half* B2b = hWp2 + (size_t)bn * DM;
    float acc1[2][4][4] = {};
    float acc2[2][4][4] = {};
    {
        #pragma unroll
        for (int i = tid; i < 1024; i += 256) { int r = i >> 3, c = i & 7;
            cpa(sb + (r * SH + c * 4) * 4, Ab + (size_t)r * DM + c * 8); }
        #pragma unroll
        for (int i = tid; i < 512; i += 256) { int r = i >> 3, c = i & 7;
            cpa(sb + (2 * AW + r * SH + c * 4) * 4, B1b + (size_t)r * DM + c * 8);
            cpa(sb + (2 * AW + 2 * BW + r * SH + c * 4) * 4, B2b + (size_t)r * DM + c * 8); }
        cpcommit();
    }
    const int nk = DM / 64;
    for (int it = 0; it < nk; it++) {
        int cur = it & 1;
        if (it + 1 < nk) {
            int k0 = (it + 1) * 64, nxt = cur ^ 1;
            #pragma unroll
            for (int i = tid; i < 1024; i += 256) { int r = i >> 3, c = i & 7;
                cpa(sb + (nxt * AW + r * SH + c * 4) * 4, Ab + (size_t)r * DM + k0 + c * 8); }
            #pragma unroll
            for (int i = tid; i < 512; i += 256) { int r = i >> 3, c = i & 7;
                cpa(sb + (2 * AW + nxt * BW + r * SH + c * 4) * 4, B1b + (size_t)r * DM + k0 + c * 8);
                cpa(sb + (2 * AW + 2 * BW + nxt * BW + r * SH + c * 4) * 4, B2b + (size_t)r * DM + k0 + c * 8); }
            cpcommit();
            cpwait<1>();
        } else cpwait<0>();
        __syncthreads();
        const uint32_t* Ac = sm + cur * AW;
        const uint32_t* B1c = sm + 2 * AW + cur * BW;
        const uint32_t* B2c = sm + 2 * AW + 2 * BW + cur * BW;
        #pragma unroll
        for (int kk = 0; kk < 4; kk++) {
            int kb = kk * 8;
            uint32_t af[2][4], bf1[4][2], bf2[4][2];
            #pragma unroll
            for (int mt = 0; mt < 2; mt++) {
                int r0 = wm + mt * 16 + g;
                af[mt][0] = Ac[r0 * SH + kb + t];
                af[mt][1] = Ac[(r0 + 8) * SH + kb + t];
                af[mt][2] = Ac[r0 * SH + kb + 4 + t];
                af[mt][3] = Ac[(r0 + 8) * SH + kb + 4 + t];
            }
            #pragma unroll
            for (int nt = 0; nt < 4; nt++) {
                int c0 = wn + nt * 8 + g;
                bf1[nt][0] = B1c[c0 * SH + kb + t];
                bf1[nt][1] = B1c[c0 * SH + kb + 4 + t];
                bf2[nt][0] = B2c[c0 * SH + kb + t];
                bf2[nt][1] = B2c[c0 * SH + kb + 4 + t];
            }
            #pragma unroll
            for (int mt = 0; mt < 2; mt++)
                #pragma unroll
                for (int nt = 0; nt < 4; nt++) {
                    mma16(acc1[mt][nt], af[mt], bf1[nt]);
                    mma16(acc2[mt][nt], af[mt], bf2[nt]);
                }
        }
        __syncthreads();
    }
    #pragma unroll
    for (int mt = 0; mt < 2; mt++)
        #pragma unroll
        for (int nt = 0; nt < 4; nt++) {
            int c = bn + wn + nt * 8 + 2 * t;
            #pragma unroll
            for (int half = 0; half < 2; half++) {
                int r = bm + wm + mt * 16 + g + half * 8;
                *(uint32_t*)(g_hidden + (size_t)r * DHID + c) =
                    packh(acc1[mt][nt][half * 2] * acc2[mt][nt][half * 2],
                          acc1[mt][nt][half * 2 + 1] * acc2[mt][nt][half * 2 + 1]);
            }
        }
}

// ---------------- attention v3: P kept in registers (C->A fragment repack) ----------------
// 8 warps = 4 row-groups (wm) x 2 key-halves (wh). Each warp: S over its 32-key
// slice, repack to A fragments, PV over all 64 dims. Final cross-wh reduce in smem.
#define ATW 2304
#define ATT_SMEM (8 * ATW * 4)
__global__ __launch_bounds__(256, 2) void attn_h() {
    extern __shared__ uint32_t sm[];
    uint32_t sb = (uint32_t)__cvta_generic_to_shared(sm);
    int hd = blockIdx.y;
    int qt = (int)gridDim.x - 1 - (int)blockIdx.x;
    int tid = threadIdx.x, wid = tid >> 5, lane = tid & 31;
    int g = lane >> 2, t = lane & 3;
    int wm = (wid & 3) * 16;
    int wh = wid >> 2;             // key half: 0 or 1
    int wn = wh * 32;              // key offset within tile
    int wnp = wh * 16;             // key offset in half2 words
    int r0 = wm + g;
    int hoff = hd * DH;

    // stage Q (region 7) + Q2 (region 0)
    #pragma unroll
    for (int i = tid; i < 512; i += 256) {
        int r = i >> 3, c = i & 7;
        size_t go = (size_t)(qt * 64 + r) * DM + hoff + c * 8;
        cpa(sb + (7 * ATW + r * SH + c * 4) * 4, g_q + go);
        cpa(sb + (r * SH + c * 4) * 4, g_q2 + go);
    }
    cpcommit();
    // K/K2/V tile 0 -> buffer 0
    #pragma unroll
    for (int i = tid; i < 512; i += 256) {
        int r = i >> 3, c = i & 7;
        size_t go = (size_t)r * DM + hoff + c * 8;
        cpa(sb + (1 * ATW + r * SH + c * 4) * 4, g_k + go);
        cpa(sb + (3 * ATW + r * SH + c * 4) * 4, g_k2 + go);
        cpa(sb + (5 * ATW + r * SH + c * 4) * 4, g_vT + (size_t)(hoff + r) * TT + c * 8);
    }
    cpcommit();
    cpwait<1>();
    __syncthreads();

    // hoist Q fragments (Q2 stays in smem)
    uint32_t aq[4][4];
    {
        const uint32_t* Qs = sm + 7 * ATW;
        #pragma unroll
        for (int kk = 0; kk < 4; kk++) {
            int kb = kk * 8;
            aq[kk][0] = Qs[r0 * SH + kb + t];
            aq[kk][1] = Qs[(r0 + 8) * SH + kb + t];
            aq[kk][2] = Qs[r0 * SH + kb + 4 + t];
            aq[kk][3] = Qs[(r0 + 8) * SH + kb + 4 + t];
        }
    }

    float zacc[8][4] = {};   // all 64 dims, partial over this warp's 32 keys
    const uint32_t* Q2s = sm;
    for (int st = 0; st <= qt; st++) {
        int buf = st & 1;
        if (st < qt) {
            int sn = st + 1, nb = buf ^ 1;
            #pragma unroll
            for (int i = tid; i < 512; i += 256) {
                int r = i >> 3, c = i & 7;
                size_t go = (size_t)(sn * 64 + r) * DM + hoff + c * 8;
                cpa(sb + ((1 + nb) * ATW + r * SH + c * 4) * 4, g_k + go);
                cpa(sb + ((3 + nb) * ATW + r * SH + c * 4) * 4, g_k2 + go);
                cpa(sb + ((5 + nb) * ATW + r * SH + c * 4) * 4,
                    g_vT + (size_t)(hoff + r) * TT + sn * 64 + c * 8);
            }
            cpcommit();
            cpwait<1>();
        } else cpwait<0>();
        __syncthreads();
        const uint32_t* Ks  = sm + (1 + buf) * ATW;
        const uint32_t* K2s = sm + (3 + buf) * ATW;
        const uint32_t* Vs  = sm + (5 + buf) * ATW;

        // ---- S phase: this warp's 32-key slice ----
        float s1[4][4] = {}, s2[4][4] = {};
        #pragma unroll
        for (int kk = 0; kk < 4; kk++) {
            int kb = kk * 8;
            uint32_t aq2[4];
            aq2[0] = Q2s[r0 * SH + kb + t];
            aq2[1] = Q2s[(r0 + 8) * SH + kb + t];
            aq2[2] = Q2s[r0 * SH + kb + 4 + t];
            aq2[3] = Q2s[(r0 + 8) * SH + kb + 4 + t];
            #pragma unroll
            for (int nt = 0; nt < 4; nt++) {
                int c0 = wn + nt * 8 + g;
                uint32_t bk[2], bk2[2];
                bk[0]  = Ks[c0 * SH + kb + t];
                bk[1]  = Ks[c0 * SH + kb + 4 + t];
                bk2[0] = K2s[c0 * SH + kb + t];
                bk2[1] = K2s[c0 * SH + kb + 4 + t];
                mma16(s1[nt], aq[kk], bk);
                mma16(s2[nt], aq2, bk2);
            }
        }

        // ---- mask + scale + repack C fragments into A fragments (P) ----
        uint32_t pa[2][4];
        #pragma unroll
        for (int kc = 0; kc < 2; kc++) {
            #pragma unroll
            for (int sub = 0; sub < 2; sub++) {          // sub: n8 tile within k16
                int nt = 2 * kc + sub;
                float p0 = s1[nt][0] * s2[nt][0] * (1.f / 4096.f);
                float p1 = s1[nt][1] * s2[nt][1] * (1.f / 4096.f);
                float p2 = s1[nt][2] * s2[nt][2] * (1.f / 4096.f);
                float p3 = s1[nt][3] * s2[nt][3] * (1.f / 4096.f);
                if (st == qt) {
                    int rlo = wm + g, rhi = rlo + 8;
                    int sc = wn + nt * 8 + 2 * t;
                    if (sc > rlo) p0 = 0.f;
                    if (sc + 1 > rlo) p1 = 0.f;
                    if (sc > rhi) p2 = 0.f;
                    if (sc + 1 > rhi) p3 = 0.f;
                }
                pa[kc][sub * 2]     = packh(p0, p1);     // row g
                pa[kc][sub * 2 + 1] = packh(p2, p3);     // row g+8
            }
            // reorder to A layout: {row g k-lo, row g+8 k-lo, row g k-hi, row g+8 k-hi}
            uint32_t tmp = pa[kc][1];
            pa[kc][1] = pa[kc][1];   // placeholder (already correct after swap below)
            // current order: [0]=g lo, [1]=g+8 lo, [2]=g hi, [3]=g+8 hi  -> already A order
            (void)tmp;
        }

        // ---- PV phase: z += P(regs) @ V, over this warp's key slice ----
        #pragma unroll
        for (int kc = 0; kc < 2; kc++) {
            int kw = wnp + kc * 8;
            #pragma unroll
            for (int nt = 0; nt < 8; nt++) {
                int d0 = nt * 8 + g;
                uint32_t bv[2];
                bv[0] = Vs[d0 * SH + kw + t];
                bv[1] = Vs[d0 * SH + kw + 4 + t];
                mma16(zacc[nt], pa[kc], bv);
            }
        }
        __syncthreads();
    }

    // ---- cross-warp (key-half) reduction through smem (reuse K buffers) ----
    float* Sg = (float*)(sm + 1 * ATW);   // 64 rows x stride 68 floats = 17408 B
    if (wh == 1) {
        #pragma unroll
        for (int nt = 0; nt < 8; nt++) {
            int c = nt * 8 + 2 * t;
            #pragma unroll
            for (int half = 0; half < 2; half++) {
                int r = wm + g + half * 8;
                *(float2*)(Sg + r * 68 + c) =
                    make_float2(zacc[nt][half * 2], zacc[nt][half * 2 + 1]);
            }
        }
    }
    __syncthreads();
    if (wh == 0) {
        #pragma unroll
        for (int nt = 0; nt < 8; nt++) {
            int c = nt * 8 + 2 * t;
            #pragma unroll
            for (int half = 0; half < 2; half++) {
                int rl = wm + g + half * 8;
                float2 o = *(float2*)(Sg + rl * 68 + c);
                int r = qt * 64 + rl;
                *(uint32_t*)(g_z + (size_t)r * DM + hoff + c) =
                    packh(zacc[nt][half * 2] + o.x, zacc[nt][half * 2 + 1] + o.y);
            }
        }
    }
}

// ---------------- launch ----------------
extern "C" void kernel_launch(void* const* d_in, const int* in_sizes, int n_in,
                              void* d_out, int out_size) {
    const float* x = (const float*)d_in[0];
    const float* bd = (const float*)d_in[10];

    __half *z_p, *hWo_p, *hidden_p, *hWd_p, *h_p, *h2_p;
    float* x1_p;
    cudaGetSymbolAddress((void**)&z_p, g_z);
    cudaGetSymbolAddress((void**)&hWo_p, hWo);
    cudaGetSymbolAddress((void**)&hidden_p, g_hidden);
    cudaGetSymbolAddress((void**)&hWd_p, hWd);
    cudaGetSymbolAddress((void**)&x1_p, g_x1);
    cudaGetSymbolAddress((void**)&h_p, g_h);
    cudaGetSymbolAddress((void**)&h2_p, g_h2);

    cudaFuncSetAttribute(gemm_proj, cudaFuncAttributeMaxDynamicSharedMemorySize, GEMM_SMEM);
    cudaFuncSetAttribute(gemm_hf64, cudaFuncAttributeMaxDynamicSharedMemorySize, GEMM64_SMEM);
    cudaFuncSetAttribute(gemm_dual, cudaFuncAttributeMaxDynamicSharedMemorySize, DUAL_SMEM);
    cudaFuncSetAttribute(attn_h, cudaFuncAttributeMaxDynamicSharedMemorySize, ATT_SMEM);

    W9 w;
    for (int i = 0; i < 9; i++) w.s[i] = (const float*)d_in[1 + i];
    cvtw_all<<<(NF4 + 255) / 256, 256>>>(w);

    rmsnorm_kernel<<<TT, 256>>>(x, h_p);
    gemm_proj<<<dim3(60, TT / 128), 256, GEMM_SMEM>>>();          // projections + RoPE fused
    attn_h<<<dim3(TT / 64, NH), 256, ATT_SMEM>>>();
    gemm_hf64<<<dim3(DM / 64, TT / 64), 256, GEMM64_SMEM>>>(z_p, hWo_p, x1_p, DM, x, nullptr);
    rmsnorm_kernel<<<TT, 256>>>(x1_p, h2_p);
    gemm_dual<<<dim3(DHID / 64, TT / 128), 256, DUAL_SMEM>>>();
    gemm_hf64<<<dim3(DM / 64, TT / 64), 256, GEMM64_SMEM>>>(hidden_p, hWd_p, (float*)d_out, DHID, x1_p, bd);
}

// round 9
// speedup vs baseline: 8.9070x; 1.0756x over previous
#include <cuda_runtime.h>
#include <cuda_fp16.h>
#include <cstdint>
#include <math.h>

#define TT 2048
#define DM 768
#define NH 12
#define DH 64
#define DHID 3072
#define SH 36            // smem row stride in uint32 words (32 data pairs + 4 pad)

// ---------------- scratch (device globals; no allocation) ----------------
__device__ __half g_h[TT * DM];
__device__ __half g_q[TT * DM];
__device__ __half g_k[TT * DM];
__device__ __half g_q2[TT * DM];
__device__ __half g_k2[TT * DM];
__device__ __half g_vT[DM * TT];     // per-head transposed V: vT[dim][token]
__device__ __half g_z[TT * DM];
__device__ float  g_x1[TT * DM];
__device__ __half g_h2[TT * DM];
__device__ __half g_hidden[TT * DHID];

// fp16 weights
__device__ __half hWq[DM * DM];
__device__ __half hWk[DM * DM];
__device__ __half hWq2[DM * DM];
__device__ __half hWk2[DM * DM];
__device__ __half hWv[DM * DM];
__device__ __half hWo[DM * DM];
__device__ __half hWp1[DHID * DM];
__device__ __half hWp2[DHID * DM];
__device__ __half hWd[DM * DHID];

// ---------------- helpers ----------------
__device__ __forceinline__ void cpa(uint32_t dst, const void* src) {
    asm volatile("cp.async.ca.shared.global [%0], [%1], 16;" :: "r"(dst), "l"(src));
}
__device__ __forceinline__ void cpcommit() { asm volatile("cp.async.commit_group;"); }
template <int N> __device__ __forceinline__ void cpwait() {
    asm volatile("cp.async.wait_group %0;" :: "n"(N));
}
__device__ __forceinline__ void mma16(float* d, const uint32_t* a, const uint32_t* b) {
    asm volatile(
        "mma.sync.aligned.m16n8k16.row.col.f32.f16.f16.f32 "
        "{%0,%1,%2,%3},{%4,%5,%6,%7},{%8,%9},{%0,%1,%2,%3};\n"
        : "+f"(d[0]), "+f"(d[1]), "+f"(d[2]), "+f"(d[3])
        : "r"(a[0]), "r"(a[1]), "r"(a[2]), "r"(a[3]), "r"(b[0]), "r"(b[1]));
}
__device__ __forceinline__ void ldsm4(uint32_t* r, uint32_t addr) {
    asm volatile("ldmatrix.sync.aligned.m8n8.x4.shared.b16 {%0,%1,%2,%3}, [%4];"
        : "=r"(r[0]), "=r"(r[1]), "=r"(r[2]), "=r"(r[3]) : "r"(addr));
}
__device__ __forceinline__ uint32_t packh(float a, float b) {
    __half2 h = __floats2half2_rn(a, b);
    return *(uint32_t*)&h;
}

// per-thread ldmatrix address offsets (in uint32 words, excluding region base / kb)
// A-fragment (m16k16): lanes 0-15 -> rows base+ (l&15), word 0; lanes 16-31 -> same rows, word +4
#define A_LDSM_OFF(wmv, lanev) (((wmv) + ((lanev) & 15)) * SH + (((lanev) & 16) ? 4 : 0))
// B-fragment pair (two n8k16 tiles): lanes 0-7 rows c0.., w0; 8-15 rows c0.., w+4; 16-23 rows c0+8.., w0; 24-31 rows c0+8.., w+4
#define B_LDSM_OFF(c0v, lanev) (((c0v) + ((lanev) & 7) + (((lanev) & 16) ? 8 : 0)) * SH + (((lanev) & 8) ? 4 : 0))

// ---------------- weight convert fp32 -> fp16 (rn) ----------------
struct W9 { const float* s[9]; };
__device__ __forceinline__ __half* wdst(int wi) {
    switch (wi) {
        case 0: return hWq;  case 1: return hWk;  case 2: return hWq2;
        case 3: return hWk2; case 4: return hWv;  case 5: return hWo;
        case 6: return hWp1; case 7: return hWp2; default: return hWd;
    }
}
#define NF4 2654208
__global__ void cvtw_all(W9 w) {
    int i = blockIdx.x * 256 + threadIdx.x;
    if (i >= NF4) return;
    int wi; int off;
    if (i < 884736) { wi = i / 147456; off = i % 147456; }
    else { int j = i - 884736; wi = 6 + j / 589824; off = j % 589824; }
    float4 v = ((const float4*)w.s[wi])[off];
    __half2* d = (__half2*)wdst(wi);
    d[2 * off]     = __floats2half2_rn(v.x, v.y);
    d[2 * off + 1] = __floats2half2_rn(v.z, v.w);
}

// ---------------- RMSNorm (fp32 in -> fp16 out) ----------------
__global__ void rmsnorm_kernel(const float* __restrict__ x, __half* __restrict__ o) {
    int row = blockIdx.x;
    const float* xr = x + row * DM;
    float s = 0.f;
    for (int i = threadIdx.x; i < DM; i += blockDim.x) { float v = xr[i]; s += v * v; }
    __shared__ float red[32];
    for (int off = 16; off; off >>= 1) s += __shfl_down_sync(0xffffffffu, s, off);
    if ((threadIdx.x & 31) == 0) red[threadIdx.x >> 5] = s;
    __syncthreads();
    if (threadIdx.x < 32) {
        s = (threadIdx.x < (blockDim.x >> 5)) ? red[threadIdx.x] : 0.f;
        for (int off = 16; off; off >>= 1) s += __shfl_down_sync(0xffffffffu, s, off);
        if (threadIdx.x == 0) red[0] = rsqrtf(s / (float)DM + 1e-6f);
    }
    __syncthreads();
    float scale = red[0];
    for (int i = threadIdx.x; i < DM; i += blockDim.x)
        o[row * DM + i] = __float2half_rn(xr[i] * scale);
}

// ================= geometry =================
#define AW (128 * SH)
#define BW (64 * SH)
#define GEMM_SMEM ((2 * AW + 2 * BW) * 4)
#define DUAL_SMEM ((2 * AW + 4 * BW) * 4)
#define GEMM64_SMEM (4 * BW * 4)

// ldmatrix-based 128x64 tile compute: regA/regB are region word offsets
#define GEMM_FRAG_LDSM(regA, regB, accv)                                          \
    _Pragma("unroll")                                                             \
    for (int kk = 0; kk < 4; kk++) {                                              \
        int kb = kk * 8;                                                          \
        uint32_t af0[4], af1[4], b01[4], b23[4];                                  \
        ldsm4(af0, sb + ((regA) + a_off + kb) * 4);                               \
        ldsm4(af1, sb + ((regA) + a_off + 16 * SH + kb) * 4);                     \
        ldsm4(b01, sb + ((regB) + b_off + kb) * 4);                               \
        ldsm4(b23, sb + ((regB) + b_off + 16 * SH + kb) * 4);                     \
        mma16(accv[0][0], af0, b01); mma16(accv[0][1], af0, b01 + 2);             \
        mma16(accv[0][2], af0, b23); mma16(accv[0][3], af0, b23 + 2);             \
        mma16(accv[1][0], af1, b01); mma16(accv[1][1], af1, b01 + 2);             \
        mma16(accv[1][2], af1, b23); mma16(accv[1][3], af1, b23 + 2);             \
    }

// ---------------- fused 5-projection GEMM + RoPE epilogue ----------------
__global__ __launch_bounds__(256, 2) void gemm_proj() {
    extern __shared__ uint32_t sm[];
    uint32_t sb = (uint32_t)__cvta_generic_to_shared(sm);
    int widx = blockIdx.x / 12;
    int bn = (blockIdx.x % 12) * 64;
    int bm = blockIdx.y * 128;
    const __half* Bw = (widx == 0) ? hWq : (widx == 1) ? hWk : (widx == 2) ? hWq2
                       : (widx == 3) ? hWk2 : hWv;
    int tid = threadIdx.x, wid = tid >> 5, lane = tid & 31;
    int g = lane >> 2, t = lane & 3;
    int wm = (wid & 3) * 32, wn = (wid >> 2) * 32;
    int a_off = A_LDSM_OFF(wm, lane);
    int b_off = B_LDSM_OFF(wn, lane);
    const __half* Ab = g_h + (size_t)bm * DM;
    const __half* Bb = Bw + (size_t)bn * DM;
    float acc[2][4][4] = {};
    {
        #pragma unroll
        for (int i = tid; i < 1024; i += 256) { int r = i >> 3, c = i & 7;
            cpa(sb + (r * SH + c * 4) * 4, Ab + (size_t)r * DM + c * 8); }
        #pragma unroll
        for (int i = tid; i < 512; i += 256) { int r = i >> 3, c = i & 7;
            cpa(sb + (2 * AW + r * SH + c * 4) * 4, Bb + (size_t)r * DM + c * 8); }
        cpcommit();
    }
    const int nk = DM / 64;
    for (int it = 0; it < nk; it++) {
        int cur = it & 1;
        if (it + 1 < nk) {
            int k0 = (it + 1) * 64, nxt = cur ^ 1;
            #pragma unroll
            for (int i = tid; i < 1024; i += 256) { int r = i >> 3, c = i & 7;
                cpa(sb + (nxt * AW + r * SH + c * 4) * 4, Ab + (size_t)r * DM + k0 + c * 8); }
            #pragma unroll
            for (int i = tid; i < 512; i += 256) { int r = i >> 3, c = i & 7;
                cpa(sb + (2 * AW + nxt * BW + r * SH + c * 4) * 4, Bb + (size_t)r * DM + k0 + c * 8); }
            cpcommit();
            cpwait<1>();
        } else cpwait<0>();
        __syncthreads();
        uint32_t regA = cur * AW;
        uint32_t regB = 2 * AW + cur * BW;
        GEMM_FRAG_LDSM(regA, regB, acc)
        __syncthreads();
    }
    if (widx < 4) {
        // ---- RoPE fused epilogue ----
        __half* C = (widx == 0) ? g_q : (widx == 1) ? g_k : (widx == 2) ? g_q2 : g_k2;
        float* Sg = (float*)sm;  // 128 x 64, stride 68 floats
        #pragma unroll
        for (int mt = 0; mt < 2; mt++)
            #pragma unroll
            for (int nt = 0; nt < 4; nt++) {
                int c = wn + nt * 8 + 2 * t;
                #pragma unroll
                for (int half = 0; half < 2; half++) {
                    int r = wm + mt * 16 + g + half * 8;
                    *(float2*)(Sg + r * 68 + c) =
                        make_float2(acc[mt][nt][half * 2], acc[mt][nt][half * 2 + 1]);
                }
            }
        __syncthreads();
        #pragma unroll
        for (int i = tid; i < 1024; i += 256) {
            int r = i >> 3, u = (i & 7) * 4;
            int token = bm + r;
            float4 a4 = *(float4*)(Sg + r * 68 + u);
            float4 b4 = *(float4*)(Sg + r * 68 + u + 32);
            float oa[4], ob[4];
            #pragma unroll
            for (int d = 0; d < 4; d++) {
                float inv = powf(10000.f, -(float)(u + d) / 32.f);
                float ang = (float)token * inv;
                float sn, cs;
                sincosf(ang, &sn, &cs);
                float av = (&a4.x)[d], bv = (&b4.x)[d];
                oa[d] = av * cs + bv * sn;
                ob[d] = -av * sn + bv * cs;
            }
            uint2 va, vb;
            va.x = packh(oa[0], oa[1]); va.y = packh(oa[2], oa[3]);
            vb.x = packh(ob[0], ob[1]); vb.y = packh(ob[2], ob[3]);
            *(uint2*)(C + (size_t)token * DM + bn + u) = va;
            *(uint2*)(C + (size_t)token * DM + bn + u + 32) = vb;
        }
    } else {
        // V: write transposed vT[col][row]
        #pragma unroll
        for (int mt = 0; mt < 2; mt++)
            #pragma unroll
            for (int nt = 0; nt < 4; nt++) {
                int c = bn + wn + nt * 8 + 2 * t;
                #pragma unroll
                for (int half = 0; half < 2; half++) {
                    int r = bm + wm + mt * 16 + g + half * 8;
                    g_vT[(size_t)c * TT + r]       = __float2half_rn(acc[mt][nt][half * 2]);
                    g_vT[(size_t)(c + 1) * TT + r] = __float2half_rn(acc[mt][nt][half * 2 + 1]);
                }
            }
    }
}

// ---------------- BM=64 fp16 GEMM NT, fp32 out (+res +bias), N=DM ----------------
__global__ __launch_bounds__(256, 3) void gemm_hf64(
    const __half* __restrict__ A, const __half* __restrict__ B, float* __restrict__ C,
    int K, const float* __restrict__ res, const float* __restrict__ bias) {
    extern __shared__ uint32_t sm[];
    uint32_t sb = (uint32_t)__cvta_generic_to_shared(sm);
    int bm = blockIdx.y * 64, bn = blockIdx.x * 64;
    int tid = threadIdx.x, wid = tid >> 5, lane = tid & 31;
    int g = lane >> 2, t = lane & 3;
    int wm = (wid & 3) * 16, wn = (wid >> 2) * 32;
    int a_off = A_LDSM_OFF(wm, lane);
    int b_off = B_LDSM_OFF(wn, lane);
    const __half* Ab = A + (size_t)bm * K;
    const __half* Bb = B + (size_t)bn * K;
    float acc[4][4] = {};
    {
        #pragma unroll
        for (int i = tid; i < 512; i += 256) { int r = i >> 3, c = i & 7;
            cpa(sb + (r * SH + c * 4) * 4, Ab + (size_t)r * K + c * 8);
            cpa(sb + (2 * BW + r * SH + c * 4) * 4, Bb + (size_t)r * K + c * 8); }
        cpcommit();
    }
    int nk = K >> 6;
    for (int it = 0; it < nk; it++) {
        int cur = it & 1;
        if (it + 1 < nk) {
            int k0 = (it + 1) << 6, nxt = cur ^ 1;
            #pragma unroll
            for (int i = tid; i < 512; i += 256) { int r = i >> 3, c = i & 7;
                cpa(sb + (nxt * BW + r * SH + c * 4) * 4, Ab + (size_t)r * K + k0 + c * 8);
                cpa(sb + (2 * BW + nxt * BW + r * SH + c * 4) * 4, Bb + (size_t)r * K + k0 + c * 8); }
            cpcommit();
            cpwait<1>();
        } else cpwait<0>();
        __syncthreads();
        uint32_t regA = cur * BW;
        uint32_t regB = 2 * BW + cur * BW;
        #pragma unroll
        for (int kk = 0; kk < 4; kk++) {
            int kb = kk * 8;
            uint32_t af[4], b01[4], b23[4];
            ldsm4(af, sb + (regA + a_off + kb) * 4);
            ldsm4(b01, sb + (regB + b_off + kb) * 4);
            ldsm4(b23, sb + (regB + b_off + 16 * SH + kb) * 4);
            mma16(acc[0], af, b01); mma16(acc[1], af, b01 + 2);
            mma16(acc[2], af, b23); mma16(acc[3], af, b23 + 2);
        }
        __syncthreads();
    }
    #pragma unroll
    for (int nt = 0; nt < 4; nt++) {
        int c = bn + wn + nt * 8 + 2 * t;
        #pragma unroll
        for (int half = 0; half < 2; half++) {
            int r = bm + wm + g + half * 8;
            float2 v = make_float2(acc[nt][half * 2], acc[nt][half * 2 + 1]);
            if (res) { float2 rr = *(const float2*)(res + (size_t)r * DM + c); v.x += rr.x; v.y += rr.y; }
            if (bias) { v.x += bias[c]; v.y += bias[c + 1]; }
            *(float2*)(C + (size_t)r * DM + c) = v;
        }
    }
}

// ---------------- dual gated GEMM: hidden = (h2@Wp1^T)*(h2@Wp2^T), fp16 out ----------------
__global__ __launch_bounds__(256, 2) void gemm_dual() {
    extern __shared__ uint32_t sm[];
    uint32_t sb = (uint32_t)__cvta_generic_to_shared(sm);
    int bm = blockIdx.y * 128, bn = blockIdx.x * 64;
    int tid = threadIdx.x, wid = tid >> 5, lane = tid & 31;
    int g = lane >> 2, t = lane & 3;
    int wm = (wid & 3) * 32, wn = (wid >> 2) * 32;
    int a_off = A_LDSM_OFF(wm, lane);
    int b_off = B_LDSM_OFF(wn, lane);
    const __half* Ab = g_h2 + (size_t)bm * DM;
    const __half* B1b = hWp1 + (size_t)bn * DM;
    const __half* B2b = hWp2 + (size_t)bn * DM;
    float acc1[2][4][4] = {};
    float acc2[2][4][4] = {};
    {
        #pragma unroll
        for (int i = tid; i < 1024; i += 256) { int r = i >> 3, c = i & 7;
            cpa(sb + (r * SH + c * 4) * 4, Ab + (size_t)r * DM + c * 8); }
        #pragma unroll
        for (int i = tid; i < 512; i += 256) { int r = i >> 3, c = i & 7;
            cpa(sb + (2 * AW + r * SH + c * 4) * 4, B1b + (size_t)r * DM + c * 8);
            cpa(sb + (2 * AW + 2 * BW + r * SH + c * 4) * 4, B2b + (size_t)r * DM + c * 8); }
        cpcommit();
    }
    const int nk = DM / 64;
    for (int it = 0; it < nk; it++) {
        int cur = it & 1;
        if (it + 1 < nk) {
            int k0 = (it + 1) * 64, nxt = cur ^ 1;
            #pragma unroll
            for (int i = tid; i < 1024; i += 256) { int r = i >> 3, c = i & 7;
                cpa(sb + (nxt * AW + r * SH + c * 4) * 4, Ab + (size_t)r * DM + k0 + c * 8); }
            #pragma unroll
            for (int i = tid; i < 512; i += 256) { int r = i >> 3, c = i & 7;
                cpa(sb + (2 * AW + nxt * BW + r * SH + c * 4) * 4, B1b + (size_t)r * DM + k0 + c * 8);
                cpa(sb + (2 * AW + 2 * BW + nxt * BW + r * SH + c * 4) * 4, B2b + (size_t)r * DM + k0 + c * 8); }
            cpcommit();
            cpwait<1>();
        } else cpwait<0>();
        __syncthreads();
        uint32_t regA = cur * AW;
        uint32_t regB1 = 2 * AW + cur * BW;
        uint32_t regB2 = 2 * AW + 2 * BW + cur * BW;
        #pragma unroll
        for (int kk = 0; kk < 4; kk++) {
            int kb = kk * 8;
            uint32_t af0[4], af1[4], c01[4], c23[4], d01[4], d23[4];
            ldsm4(af0, sb + (regA + a_off + kb) * 4);
            ldsm4(af1, sb + (regA + a_off + 16 * SH + kb) * 4);
            ldsm4(c01, sb + (regB1 + b_off + kb) * 4);
            ldsm4(c23, sb + (regB1 + b_off + 16 * SH + kb) * 4);
            ldsm4(d01, sb + (regB2 + b_off + kb) * 4);
            ldsm4(d23, sb + (regB2 + b_off + 16 * SH + kb) * 4);
            mma16(acc1[0][0], af0, c01); mma16(acc1[0][1], af0, c01 + 2);
            mma16(acc1[0][2], af0, c23); mma16(acc1[0][3], af0, c23 + 2);
            mma16(acc1[1][0], af1, c01); mma16(acc1[1][1], af1, c01 + 2);
            mma16(acc1[1][2], af1, c23); mma16(acc1[1][3], af1, c23 + 2);
            mma16(acc2[0][0], af0, d01); mma16(acc2[0][1], af0, d01 + 2);
            mma16(acc2[0][2], af0, d23); mma16(acc2[0][3], af0, d23 + 2);
            mma16(acc2[1][0], af1, d01); mma16(acc2[1][1], af1, d01 + 2);
            mma16(acc2[1][2], af1, d23); mma16(acc2[1][3], af1, d23 + 2);
        }
        __syncthreads();
    }
    #pragma unroll
    for (int mt = 0; mt < 2; mt++)
        #pragma unroll
        for (int nt = 0; nt < 4; nt++) {
            int c = bn + wn + nt * 8 + 2 * t;
            #pragma unroll
            for (int half = 0; half < 2; half++) {
                int r = bm + wm + mt * 16 + g + half * 8;
                *(uint32_t*)(g_hidden + (size_t)r * DHID + c) =
                    packh(acc1[mt][nt][half * 2] * acc2[mt][nt][half * 2],
                          acc1[mt][nt][half * 2 + 1] * acc2[mt][nt][half * 2 + 1]);
            }
        }
}

// ---------------- attention (ldmatrix fragments, P in regs, double-buffered) ----------------
#define ATW 2304
#define ATT_SMEM (8 * ATW * 4)
__global__ __launch_bounds__(256, 2) void attn_h() {
    extern __shared__ uint32_t sm[];
    uint32_t sb = (uint32_t)__cvta_generic_to_shared(sm);
    int hd = blockIdx.y;
    int qt = (int)gridDim.x - 1 - (int)blockIdx.x;
    int tid = threadIdx.x, wid = tid >> 5, lane = tid & 31;
    int g = lane >> 2, t = lane & 3;
    int wm = (wid & 3) * 16;
    int wh = wid >> 2;
    int wn = wh * 32;
    int wnp = wh * 16;
    int hoff = hd * DH;
    int a_off = A_LDSM_OFF(wm, lane);        // Q / Q2 A-fragments
    int bk_off = B_LDSM_OFF(wn, lane);       // K / K2 B-fragments (this warp's 32 keys)
    int v_off = B_LDSM_OFF(0, lane);         // V B-fragments (dim-major tiles)

    // stage Q (region 7) + Q2 (region 0)
    #pragma unroll
    for (int i = tid; i < 512; i += 256) {
        int r = i >> 3, c = i & 7;
        size_t go = (size_t)(qt * 64 + r) * DM + hoff + c * 8;
        cpa(sb + (7 * ATW + r * SH + c * 4) * 4, g_q + go);
        cpa(sb + (r * SH + c * 4) * 4, g_q2 + go);
    }
    cpcommit();
    // K/K2/V tile 0 -> buffer 0
    #pragma unroll
    for (int i = tid; i < 512; i += 256) {
        int r = i >> 3, c = i & 7;
        size_t go = (size_t)r * DM + hoff + c * 8;
        cpa(sb + (1 * ATW + r * SH + c * 4) * 4, g_k + go);
        cpa(sb + (3 * ATW + r * SH + c * 4) * 4, g_k2 + go);
        cpa(sb + (5 * ATW + r * SH + c * 4) * 4, g_vT + (size_t)(hoff + r) * TT + c * 8);
    }
    cpcommit();
    cpwait<1>();
    __syncthreads();

    // hoist Q fragments via ldmatrix (Q2 stays in smem)
    uint32_t aq[4][4];
    #pragma unroll
    for (int kk = 0; kk < 4; kk++)
        ldsm4(aq[kk], sb + (7 * ATW + a_off + kk * 8) * 4);

    float zacc[8][4] = {};   // all 64 dims, partial over this warp's 32 keys
    for (int st = 0; st <= qt; st++) {
        int buf = st & 1;
        if (st < qt) {
            int sn = st + 1, nb = buf ^ 1;
            #pragma unroll
            for (int i = tid; i < 512; i += 256) {
                int r = i >> 3, c = i & 7;
                size_t go = (size_t)(sn * 64 + r) * DM + hoff + c * 8;
                cpa(sb + ((1 + nb) * ATW + r * SH + c * 4) * 4, g_k + go);
                cpa(sb + ((3 + nb) * ATW + r * SH + c * 4) * 4, g_k2 + go);
                cpa(sb + ((5 + nb) * ATW + r * SH + c * 4) * 4,
                    g_vT + (size_t)(hoff + r) * TT + sn * 64 + c * 8);
            }
            cpcommit();
            cpwait<1>();
        } else cpwait<0>();
        __syncthreads();
        uint32_t regK  = (1 + buf) * ATW;
        uint32_t regK2 = (3 + buf) * ATW;
        uint32_t regV  = (5 + buf) * ATW;

        // ---- S phase: this warp's 32-key slice ----
        float s1[4][4] = {}, s2[4][4] = {};
        #pragma unroll
        for (int kk = 0; kk < 4; kk++) {
            int kb = kk * 8;
            uint32_t aq2[4], k01[4], k23[4], l01[4], l23[4];
            ldsm4(aq2, sb + (0 + a_off + kb) * 4);
            ldsm4(k01, sb + (regK + bk_off + kb) * 4);
            ldsm4(k23, sb + (regK + bk_off + 16 * SH + kb) * 4);
            ldsm4(l01, sb + (regK2 + bk_off + kb) * 4);
            ldsm4(l23, sb + (regK2 + bk_off + 16 * SH + kb) * 4);
            mma16(s1[0], aq[kk], k01); mma16(s1[1], aq[kk], k01 + 2);
            mma16(s1[2], aq[kk], k23); mma16(s1[3], aq[kk], k23 + 2);
            mma16(s2[0], aq2, l01); mma16(s2[1], aq2, l01 + 2);
            mma16(s2[2], aq2, l23); mma16(s2[3], aq2, l23 + 2);
        }

        // ---- mask + scale + repack C fragments into P A-fragments ----
        uint32_t pa[2][4];
        #pragma unroll
        for (int kc = 0; kc < 2; kc++) {
            #pragma unroll
            for (int sub = 0; sub < 2; sub++) {
                int nt = 2 * kc + sub;
                float p0 = s1[nt][0] * s2[nt][0] * (1.f / 4096.f);
                float p1 = s1[nt][1] * s2[nt][1] * (1.f / 4096.f);
                float p2 = s1[nt][2] * s2[nt][2] * (1.f / 4096.f);
                float p3 = s1[nt][3] * s2[nt][3] * (1.f / 4096.f);
                if (st == qt) {
                    int rlo = wm + g, rhi = rlo + 8;
                    int sc = wn + nt * 8 + 2 * t;
                    if (sc > rlo) p0 = 0.f;
                    if (sc + 1 > rlo) p1 = 0.f;
                    if (sc > rhi) p2 = 0.f;
                    if (sc + 1 > rhi) p3 = 0.f;
                }
                pa[kc][sub * 2]     = packh(p0, p1);
                pa[kc][sub * 2 + 1] = packh(p2, p3);
            }
        }

        // ---- PV phase: z += P(regs) @ V over this warp's key slice ----
        #pragma unroll
        for (int kc = 0; kc < 2; kc++) {
            int kw = wnp + kc * 8;
            uint32_t v01[4], v23[4], v45[4], v67[4];
            ldsm4(v01, sb + (regV + v_off + kw) * 4);
            ldsm4(v23, sb + (regV + v_off + 16 * SH + kw) * 4);
            ldsm4(v45, sb + (regV + v_off + 32 * SH + kw) * 4);
            ldsm4(v67, sb + (regV + v_off + 48 * SH + kw) * 4);
            mma16(zacc[0], pa[kc], v01); mma16(zacc[1], pa[kc], v01 + 2);
            mma16(zacc[2], pa[kc], v23); mma16(zacc[3], pa[kc], v23 + 2);
            mma16(zacc[4], pa[kc], v45); mma16(zacc[5], pa[kc], v45 + 2);
            mma16(zacc[6], pa[kc], v67); mma16(zacc[7], pa[kc], v67 + 2);
        }
        __syncthreads();
    }

    // ---- cross-warp (key-half) reduction through smem (reuse K buffers) ----
    float* Sg = (float*)(sm + 1 * ATW);
    if (wh == 1) {
        #pragma unroll
        for (int nt = 0; nt < 8; nt++) {
            int c = nt * 8 + 2 * t;
            #pragma unroll
            for (int half = 0; half < 2; half++) {
                int r = wm + g + half * 8;
                *(float2*)(Sg + r * 68 + c) =
                    make_float2(zacc[nt][half * 2], zacc[nt][half * 2 + 1]);
            }
        }
    }
    __syncthreads();
    if (wh == 0) {
        #pragma unroll
        for (int nt = 0; nt < 8; nt++) {
            int c = nt * 8 + 2 * t;
            #pragma unroll
            for (int half = 0; half < 2; half++) {
                int rl = wm + g + half * 8;
                float2 o = *(float2*)(Sg + rl * 68 + c);
                int r = qt * 64 + rl;
                *(uint32_t*)(g_z + (size_t)r * DM + hoff + c) =
                    packh(zacc[nt][half * 2] + o.x, zacc[nt][half * 2 + 1] + o.y);
            }
        }
    }
}

// ---------------- launch ----------------
extern "C" void kernel_launch(void* const* d_in, const int* in_sizes, int n_in,
                              void* d_out, int out_size) {
    const float* x = (const float*)d_in[0];
    const float* bd = (const float*)d_in[10];

    __half *z_p, *hWo_p, *hidden_p, *hWd_p, *h_p, *h2_p;
    float* x1_p;
    cudaGetSymbolAddress((void**)&z_p, g_z);
    cudaGetSymbolAddress((void**)&hWo_p, hWo);
    cudaGetSymbolAddress((void**)&hidden_p, g_hidden);
    cudaGetSymbolAddress((void**)&hWd_p, hWd);
    cudaGetSymbolAddress((void**)&x1_p, g_x1);
    cudaGetSymbolAddress((void**)&h_p, g_h);
    cudaGetSymbolAddress((void**)&h2_p, g_h2);

    cudaFuncSetAttribute(gemm_proj, cudaFuncAttributeMaxDynamicSharedMemorySize, GEMM_SMEM);
    cudaFuncSetAttribute(gemm_hf64, cudaFuncAttributeMaxDynamicSharedMemorySize, GEMM64_SMEM);
    cudaFuncSetAttribute(gemm_dual, cudaFuncAttributeMaxDynamicSharedMemorySize, DUAL_SMEM);
    cudaFuncSetAttribute(attn_h, cudaFuncAttributeMaxDynamicSharedMemorySize, ATT_SMEM);

    W9 w;
    for (int i = 0; i < 9; i++) w.s[i] = (const float*)d_in[1 + i];
    cvtw_all<<<(NF4 + 255) / 256, 256>>>(w);

    rmsnorm_kernel<<<TT, 256>>>(x, h_p);
    gemm_proj<<<dim3(60, TT / 128), 256, GEMM_SMEM>>>();          // projections + RoPE fused
    attn_h<<<dim3(TT / 64, NH), 256, ATT_SMEM>>>();
    gemm_hf64<<<dim3(DM / 64, TT / 64), 256, GEMM64_SMEM>>>(z_p, hWo_p, x1_p, DM, x, nullptr);
    rmsnorm_kernel<<<TT, 256>>>(x1_p, h2_p);
    gemm_dual<<<dim3(DHID / 64, TT / 128), 256, DUAL_SMEM>>>();
    gemm_hf64<<<dim3(DM / 64, TT / 64), 256, GEMM64_SMEM>>>(hidden_p, hWd_p, (float*)d_out, DHID, x1_p, bd);
}

// round 11
// speedup vs baseline: 9.3118x; 1.0455x over previous
#include <cuda_runtime.h>
#include <cuda_fp16.h>
#include <cstdint>
#include <math.h>

#define TT 2048
#define DM 768
#define NH 12
#define DH 64
#define DHID 3072
#define SH 36            // smem row stride in uint32 words (32 data pairs + 4 pad)

// ---------------- scratch (device globals; no allocation) ----------------
__device__ __half g_h[TT * DM];
__device__ __half g_q[TT * DM];
__device__ __half g_k[TT * DM];
__device__ __half g_q2[TT * DM];
__device__ __half g_k2[TT * DM];
__device__ __half g_vT[DM * TT];     // per-head transposed V: vT[dim][token]
__device__ __half g_z[TT * DM];
__device__ float  g_x1[TT * DM];
__device__ __half g_h2[TT * DM];
__device__ __half g_hidden[TT * DHID];

// fp16 weights
__device__ __half hWq[DM * DM];
__device__ __half hWk[DM * DM];
__device__ __half hWq2[DM * DM];
__device__ __half hWk2[DM * DM];
__device__ __half hWv[DM * DM];
__device__ __half hWo[DM * DM];
__device__ __half hWp1[DHID * DM];
__device__ __half hWp2[DHID * DM];
__device__ __half hWd[DM * DHID];

// ---------------- helpers ----------------
__device__ __forceinline__ void cpa(uint32_t dst, const void* src) {
    asm volatile("cp.async.ca.shared.global [%0], [%1], 16;" :: "r"(dst), "l"(src));
}
__device__ __forceinline__ void cpcommit() { asm volatile("cp.async.commit_group;"); }
template <int N> __device__ __forceinline__ void cpwait() {
    asm volatile("cp.async.wait_group %0;" :: "n"(N));
}
__device__ __forceinline__ void mma16(float* d, const uint32_t* a, const uint32_t* b) {
    asm volatile(
        "mma.sync.aligned.m16n8k16.row.col.f32.f16.f16.f32 "
        "{%0,%1,%2,%3},{%4,%5,%6,%7},{%8,%9},{%0,%1,%2,%3};\n"
        : "+f"(d[0]), "+f"(d[1]), "+f"(d[2]), "+f"(d[3])
        : "r"(a[0]), "r"(a[1]), "r"(a[2]), "r"(a[3]), "r"(b[0]), "r"(b[1]));
}
__device__ __forceinline__ void ldsm4(uint32_t* r, uint32_t addr) {
    asm volatile("ldmatrix.sync.aligned.m8n8.x4.shared.b16 {%0,%1,%2,%3}, [%4];"
        : "=r"(r[0]), "=r"(r[1]), "=r"(r[2]), "=r"(r[3]) : "r"(addr));
}
__device__ __forceinline__ uint32_t packh(float a, float b) {
    __half2 h = __floats2half2_rn(a, b);
    return *(uint32_t*)&h;
}

#define A_LDSM_OFF(wmv, lanev) (((wmv) + ((lanev) & 15)) * SH + (((lanev) & 16) ? 4 : 0))
#define B_LDSM_OFF(c0v, lanev) (((c0v) + ((lanev) & 7) + (((lanev) & 16) ? 8 : 0)) * SH + (((lanev) & 8) ? 4 : 0))

// ---------------- weight convert fp32 -> fp16 (rn) ----------------
struct W9 { const float* s[9]; };
__device__ __forceinline__ __half* wdst(int wi) {
    switch (wi) {
        case 0: return hWq;  case 1: return hWk;  case 2: return hWq2;
        case 3: return hWk2; case 4: return hWv;  case 5: return hWo;
        case 6: return hWp1; case 7: return hWp2; default: return hWd;
    }
}
#define NF4 2654208
__global__ void cvtw_all(W9 w) {
    int i = blockIdx.x * 256 + threadIdx.x;
    if (i >= NF4) return;
    int wi; int off;
    if (i < 884736) { wi = i / 147456; off = i % 147456; }
    else { int j = i - 884736; wi = 6 + j / 589824; off = j % 589824; }
    float4 v = ((const float4*)w.s[wi])[off];
    __half2* d = (__half2*)wdst(wi);
    d[2 * off]     = __floats2half2_rn(v.x, v.y);
    d[2 * off + 1] = __floats2half2_rn(v.z, v.w);
}

// ---------------- RMSNorm: warp per row, 8 rows/CTA ----------------
__global__ __launch_bounds__(256) void rmsnorm_w(const float* __restrict__ x,
                                                 __half* __restrict__ o) {
    int row = blockIdx.x * 8 + (threadIdx.x >> 5);
    int lane = threadIdx.x & 31;
    const float4* xr = (const float4*)(x + (size_t)row * DM);
    float4 v[6];
    float s = 0.f;
    #pragma unroll
    for (int i = 0; i < 6; i++) {
        v[i] = xr[lane + 32 * i];
        s += v[i].x * v[i].x + v[i].y * v[i].y + v[i].z * v[i].z + v[i].w * v[i].w;
    }
    #pragma unroll
    for (int off = 16; off; off >>= 1) s += __shfl_xor_sync(0xffffffffu, s, off);
    float scale = rsqrtf(s / (float)DM + 1e-6f);
    uint2* orow = (uint2*)(o + (size_t)row * DM);
    #pragma unroll
    for (int i = 0; i < 6; i++) {
        uint2 u;
        u.x = packh(v[i].x * scale, v[i].y * scale);
        u.y = packh(v[i].z * scale, v[i].w * scale);
        orow[lane + 32 * i] = u;
    }
}

// ================= geometry =================
#define AW (128 * SH)
#define BW (64 * SH)
#define BW2 (128 * SH)
#define GEMM2_SMEM ((2 * AW + 2 * BW2) * 4)    // proj: BM=128, BN=128
#define DUAL_SMEM ((2 * AW + 4 * BW) * 4)
#define GEMM64_SMEM (4 * BW * 4)

// ---------------- fused 5-projection GEMM (BM=128,BN=128) + RoPE epilogue ----------------
// 8 warps = 4(m:32) x 2(n:64). grid (30, 16).
__global__ __launch_bounds__(256, 2) void gemm_proj() {
    extern __shared__ uint32_t sm[];
    uint32_t sb = (uint32_t)__cvta_generic_to_shared(sm);
    int widx = blockIdx.x / 6;
    int bn = (blockIdx.x % 6) * 128;
    int bm = blockIdx.y * 128;
    const __half* Bw = (widx == 0) ? hWq : (widx == 1) ? hWk : (widx == 2) ? hWq2
                       : (widx == 3) ? hWk2 : hWv;
    int tid = threadIdx.x, wid = tid >> 5, lane = tid & 31;
    int g = lane >> 2, t = lane & 3;
    int wm = (wid & 3) * 32, wn = (wid >> 2) * 64;
    int a_off = A_LDSM_OFF(wm, lane);
    int b_off = B_LDSM_OFF(wn, lane);
    const __half* Ab = g_h + (size_t)bm * DM;
    const __half* Bb = Bw + (size_t)bn * DM;
    float acc[2][8][4] = {};
    {
        #pragma unroll
        for (int i = tid; i < 1024; i += 256) { int r = i >> 3, c = i & 7;
            cpa(sb + (r * SH + c * 4) * 4, Ab + (size_t)r * DM + c * 8);
            cpa(sb + (2 * AW + r * SH + c * 4) * 4, Bb + (size_t)r * DM + c * 8); }
        cpcommit();
    }
    const int nk = DM / 64;
    for (int it = 0; it < nk; it++) {
        int cur = it & 1;
        if (it + 1 < nk) {
            int k0 = (it + 1) * 64, nxt = cur ^ 1;
            #pragma unroll
            for (int i = tid; i < 1024; i += 256) { int r = i >> 3, c = i & 7;
                cpa(sb + (nxt * AW + r * SH + c * 4) * 4, Ab + (size_t)r * DM + k0 + c * 8);
                cpa(sb + (2 * AW + nxt * BW2 + r * SH + c * 4) * 4, Bb + (size_t)r * DM + k0 + c * 8); }
            cpcommit();
            cpwait<1>();
        } else cpwait<0>();
        __syncthreads();
        uint32_t regA = cur * AW;
        uint32_t regB = 2 * AW + cur * BW2;
        #pragma unroll
        for (int kk = 0; kk < 4; kk++) {
            int kb = kk * 8;
            uint32_t af0[4], af1[4], b01[4], b23[4], b45[4], b67[4];
            ldsm4(af0, sb + (regA + a_off + kb) * 4);
            ldsm4(af1, sb + (regA + a_off + 16 * SH + kb) * 4);
            ldsm4(b01, sb + (regB + b_off + kb) * 4);
            ldsm4(b23, sb + (regB + b_off + 16 * SH + kb) * 4);
            ldsm4(b45, sb + (regB + b_off + 32 * SH + kb) * 4);
            ldsm4(b67, sb + (regB + b_off + 48 * SH + kb) * 4);
            mma16(acc[0][0], af0, b01); mma16(acc[0][1], af0, b01 + 2);
            mma16(acc[0][2], af0, b23); mma16(acc[0][3], af0, b23 + 2);
            mma16(acc[0][4], af0, b45); mma16(acc[0][5], af0, b45 + 2);
            mma16(acc[0][6], af0, b67); mma16(acc[0][7], af0, b67 + 2);
            mma16(acc[1][0], af1, b01); mma16(acc[1][1], af1, b01 + 2);
            mma16(acc[1][2], af1, b23); mma16(acc[1][3], af1, b23 + 2);
            mma16(acc[1][4], af1, b45); mma16(acc[1][5], af1, b45 + 2);
            mma16(acc[1][6], af1, b67); mma16(acc[1][7], af1, b67 + 2);
        }
        __syncthreads();
    }
    if (widx < 4) {
        // ---- RoPE fused epilogue (tile spans 2 heads of 64 cols each) ----
        __half* C = (widx == 0) ? g_q : (widx == 1) ? g_k : (widx == 2) ? g_q2 : g_k2;
        float* Sg = (float*)sm;  // 128 x 128, stride 132 floats (67584 B <= 73728)
        #pragma unroll
        for (int mt = 0; mt < 2; mt++)
            #pragma unroll
            for (int nt = 0; nt < 8; nt++) {
                int c = wn + nt * 8 + 2 * t;
                #pragma unroll
                for (int half = 0; half < 2; half++) {
                    int r = wm + mt * 16 + g + half * 8;
                    *(float2*)(Sg + r * 132 + c) =
                        make_float2(acc[mt][nt][half * 2], acc[mt][nt][half * 2 + 1]);
                }
            }
        __syncthreads();
        #pragma unroll
        for (int i = tid; i < 2048; i += 256) {
            int r = i >> 4, j = i & 15;
            int head = j >> 3;
            int f = (j & 7) * 4;          // head-local dim 0..28
            int u0 = head * 64 + f;
            int token = bm + r;
            float4 a4 = *(float4*)(Sg + r * 132 + u0);
            float4 b4 = *(float4*)(Sg + r * 132 + u0 + 32);
            float oa[4], ob[4];
            #pragma unroll
            for (int d = 0; d < 4; d++) {
                float inv = powf(10000.f, -(float)(f + d) / 32.f);
                float ang = (float)token * inv;
                float sn, cs;
                sincosf(ang, &sn, &cs);
                float av = (&a4.x)[d], bv = (&b4.x)[d];
                oa[d] = av * cs + bv * sn;
                ob[d] = -av * sn + bv * cs;
            }
            uint2 va, vb;
            va.x = packh(oa[0], oa[1]); va.y = packh(oa[2], oa[3]);
            vb.x = packh(ob[0], ob[1]); vb.y = packh(ob[2], ob[3]);
            *(uint2*)(C + (size_t)token * DM + bn + u0) = va;
            *(uint2*)(C + (size_t)token * DM + bn + u0 + 32) = vb;
        }
    } else {
        // V: write transposed vT[col][row]
        #pragma unroll
        for (int mt = 0; mt < 2; mt++)
            #pragma unroll
            for (int nt = 0; nt < 8; nt++) {
                int c = bn + wn + nt * 8 + 2 * t;
                #pragma unroll
                for (int half = 0; half < 2; half++) {
                    int r = bm + wm + mt * 16 + g + half * 8;
                    g_vT[(size_t)c * TT + r]       = __float2half_rn(acc[mt][nt][half * 2]);
                    g_vT[(size_t)(c + 1) * TT + r] = __float2half_rn(acc[mt][nt][half * 2 + 1]);
                }
            }
    }
}

// ---------------- BM=64 fp16 GEMM NT, fp32 out (+res +bias), N=DM ----------------
__global__ __launch_bounds__(256, 3) void gemm_hf64(
    const __half* __restrict__ A, const __half* __restrict__ B, float* __restrict__ C,
    int K, const float* __restrict__ res, const float* __restrict__ bias) {
    extern __shared__ uint32_t sm[];
    uint32_t sb = (uint32_t)__cvta_generic_to_shared(sm);
    int bm = blockIdx.y * 64, bn = blockIdx.x * 64;
    int tid = threadIdx.x, wid = tid >> 5, lane = tid & 31;
    int g = lane >> 2, t = lane & 3;
    int wm = (wid & 3) * 16, wn = (wid >> 2) * 32;
    int a_off = A_LDSM_OFF(wm, lane);
    int b_off = B_LDSM_OFF(wn, lane);
    const __half* Ab = A + (size_t)bm * K;
    const __half* Bb = B + (size_t)bn * K;
    float acc[4][4] = {};
    {
        #pragma unroll
        for (int i = tid; i < 512; i += 256) { int r = i >> 3, c = i & 7;
            cpa(sb + (r * SH + c * 4) * 4, Ab + (size_t)r * K + c * 8);
            cpa(sb + (2 * BW + r * SH + c * 4) * 4, Bb + (size_t)r * K + c * 8); }
        cpcommit();
    }
    int nk = K >> 6;
    for (int it = 0; it < nk; it++) {
        int cur = it & 1;
        if (it + 1 < nk) {
            int k0 = (it + 1) << 6, nxt = cur ^ 1;
            #pragma unroll
            for (int i = tid; i < 512; i += 256) { int r = i >> 3, c = i & 7;
                cpa(sb + (nxt * BW + r * SH + c * 4) * 4, Ab + (size_t)r * K + k0 + c * 8);
                cpa(sb + (2 * BW + nxt * BW + r * SH + c * 4) * 4, Bb + (size_t)r * K + k0 + c * 8); }
            cpcommit();
            cpwait<1>();
        } else cpwait<0>();
        __syncthreads();
        uint32_t regA = cur * BW;
        uint32_t regB = 2 * BW + cur * BW;
        #pragma unroll
        for (int kk = 0; kk < 4; kk++) {
            int kb = kk * 8;
            uint32_t af[4], b01[4], b23[4];
            ldsm4(af, sb + (regA + a_off + kb) * 4);
            ldsm4(b01, sb + (regB + b_off + kb) * 4);
            ldsm4(b23, sb + (regB + b_off + 16 * SH + kb) * 4);
            mma16(acc[0], af, b01); mma16(acc[1], af, b01 + 2);
            mma16(acc[2], af, b23); mma16(acc[3], af, b23 + 2);
        }
        __syncthreads();
    }
    #pragma unroll
    for (int nt = 0; nt < 4; nt++) {
        int c = bn + wn + nt * 8 + 2 * t;
        #pragma unroll
        for (int half = 0; half < 2; half++) {
            int r = bm + wm + g + half * 8;
            float2 v = make_float2(acc[nt][half * 2], acc[nt][half * 2 + 1]);
            if (res) { float2 rr = *(const float2*)(res + (size_t)r * DM + c); v.x += rr.x; v.y += rr.y; }
            if (bias) { v.x += bias[c]; v.y += bias[c + 1]; }
            *(float2*)(C + (size_t)r * DM + c) = v;
        }
    }
}

// ---------------- dual gated GEMM: hidden = (h2@Wp1^T)*(h2@Wp2^T), fp16 out ----------------
__global__ __launch_bounds__(256, 2) void gemm_dual() {
    extern __shared__ uint32_t sm[];
    uint32_t sb = (uint32_t)__cvta_generic_to_shared(sm);
    int bm = blockIdx.y * 128, bn = blockIdx.x * 64;
    int tid = threadIdx.x, wid = tid >> 5, lane = tid & 31;
    int g = lane >> 2, t = lane & 3;
    int wm = (wid & 3) * 32, wn = (wid >> 2) * 32;
    int a_off = A_LDSM_OFF(wm, lane);
    int b_off = B_LDSM_OFF(wn, lane);
    const __half* Ab = g_h2 + (size_t)bm * DM;
    const __half* B1b = hWp1 + (size_t)bn * DM;
    const __half* B2b = hWp2 + (size_t)bn * DM;
    float acc1[2][4][4] = {};
    float acc2[2][4][4] = {};
    {
        #pragma unroll
        for (int i = tid; i < 1024; i += 256) { int r = i >> 3, c = i & 7;
            cpa(sb + (r * SH + c * 4) * 4, Ab + (size_t)r * DM + c * 8); }
        #pragma unroll
        for (int i = tid; i < 512; i += 256) { int r = i >> 3, c = i & 7;
            cpa(sb + (2 * AW + r * SH + c * 4) * 4, B1b + (size_t)r * DM + c * 8);
            cpa(sb + (2 * AW + 2 * BW + r * SH + c * 4) * 4, B2b + (size_t)r * DM + c * 8); }
        cpcommit();
    }
    const int nk = DM / 64;
    for (int it = 0; it < nk; it++) {
        int cur = it & 1;
        if (it + 1 < nk) {
            int k0 = (it + 1) * 64, nxt = cur ^ 1;
            #pragma unroll
            for (int i = tid; i < 1024; i += 256) { int r = i >> 3, c = i & 7;
                cpa(sb + (nxt * AW + r * SH + c * 4) * 4, Ab + (size_t)r * DM + k0 + c * 8); }
            #pragma unroll
            for (int i = tid; i < 512; i += 256) { int r = i >> 3, c = i & 7;
                cpa(sb + (2 * AW + nxt * BW + r * SH + c * 4) * 4, B1b + (size_t)r * DM + k0 + c * 8);
                cpa(sb + (2 * AW + 2 * BW + nxt * BW + r * SH + c * 4) * 4, B2b + (size_t)r * DM + k0 + c * 8); }
            cpcommit();
            cpwait<1>();
        } else cpwait<0>();
        __syncthreads();
        uint32_t regA = cur * AW;
        uint32_t regB1 = 2 * AW + cur * BW;
        uint32_t regB2 = 2 * AW + 2 * BW + cur * BW;
        #pragma unroll
        for (int kk = 0; kk < 4; kk++) {
            int kb = kk * 8;
            uint32_t af0[4], af1[4], c01[4], c23[4], d01[4], d23[4];
            ldsm4(af0, sb + (regA + a_off + kb) * 4);
            ldsm4(af1, sb + (regA + a_off + 16 * SH + kb) * 4);
            ldsm4(c01, sb + (regB1 + b_off + kb) * 4);
            ldsm4(c23, sb + (regB1 + b_off + 16 * SH + kb) * 4);
            ldsm4(d01, sb + (regB2 + b_off + kb) * 4);
            ldsm4(d23, sb + (regB2 + b_off + 16 * SH + kb) * 4);
            mma16(acc1[0][0], af0, c01); mma16(acc1[0][1], af0, c01 + 2);
            mma16(acc1[0][2], af0, c23); mma16(acc1[0][3], af0, c23 + 2);
            mma16(acc1[1][0], af1, c01); mma16(acc1[1][1], af1, c01 + 2);
            mma16(acc1[1][2], af1, c23); mma16(acc1[1][3], af1, c23 + 2);
            mma16(acc2[0][0], af0, d01); mma16(acc2[0][1], af0, d01 + 2);
            mma16(acc2[0][2], af0, d23); mma16(acc2[0][3], af0, d23 + 2);
            mma16(acc2[1][0], af1, d01); mma16(acc2[1][1], af1, d01 + 2);
            mma16(acc2[1][2], af1, d23); mma16(acc2[1][3], af1, d23 + 2);
        }
        __syncthreads();
    }
    #pragma unroll
    for (int mt = 0; mt < 2; mt++)
        #pragma unroll
        for (int nt = 0; nt < 4; nt++) {
            int c = bn + wn + nt * 8 + 2 * t;
            #pragma unroll
            for (int half = 0; half < 2; half++) {
                int r = bm + wm + mt * 16 + g + half * 8;
                *(uint32_t*)(g_hidden + (size_t)r * DHID + c) =
                    packh(acc1[mt][nt][half * 2] * acc2[mt][nt][half * 2],
                          acc1[mt][nt][half * 2 + 1] * acc2[mt][nt][half * 2 + 1]);
            }
        }
}

// ---------------- attention (ldmatrix fragments, P in regs, double-buffered) ----------------
#define ATW 2304
#define ATT_SMEM (8 * ATW * 4)
__global__ __launch_bounds__(256, 2) void attn_h() {
    extern __shared__ uint32_t sm[];
    uint32_t sb = (uint32_t)__cvta_generic_to_shared(sm);
    int hd = blockIdx.y;
    int qt = (int)gridDim.x - 1 - (int)blockIdx.x;
    int tid = threadIdx.x, wid = tid >> 5, lane = tid & 31;
    int g = lane >> 2, t = lane & 3;
    int wm = (wid & 3) * 16;
    int wh = wid >> 2;
    int wn = wh * 32;
    int wnp = wh * 16;
    int hoff = hd * DH;
    int a_off = A_LDSM_OFF(wm, lane);
    int bk_off = B_LDSM_OFF(wn, lane);
    int v_off = B_LDSM_OFF(0, lane);

    #pragma unroll
    for (int i = tid; i < 512; i += 256) {
        int r = i >> 3, c = i & 7;
        size_t go = (size_t)(qt * 64 + r) * DM + hoff + c * 8;
        cpa(sb + (7 * ATW + r * SH + c * 4) * 4, g_q + go);
        cpa(sb + (r * SH + c * 4) * 4, g_q2 + go);
    }
    cpcommit();
    #pragma unroll
    for (int i = tid; i < 512; i += 256) {
        int r = i >> 3, c = i & 7;
        size_t go = (size_t)r * DM + hoff + c * 8;
        cpa(sb + (1 * ATW + r * SH + c * 4) * 4, g_k + go);
        cpa(sb + (3 * ATW + r * SH + c * 4) * 4, g_k2 + go);
        cpa(sb + (5 * ATW + r * SH + c * 4) * 4, g_vT + (size_t)(hoff + r) * TT + c * 8);
    }
    cpcommit();
    cpwait<1>();
    __syncthreads();

    uint32_t aq[4][4];
    #pragma unroll
    for (int kk = 0; kk < 4; kk++)
        ldsm4(aq[kk], sb + (7 * ATW + a_off + kk * 8) * 4);

    float zacc[8][4] = {};
    for (int st = 0; st <= qt; st++) {
        int buf = st & 1;
        if (st < qt) {
            int sn = st + 1, nb = buf ^ 1;
            #pragma unroll
            for (int i = tid; i < 512; i += 256) {
                int r = i >> 3, c = i & 7;
                size_t go = (size_t)(sn * 64 + r) * DM + hoff + c * 8;
                cpa(sb + ((1 + nb) * ATW + r * SH + c * 4) * 4, g_k + go);
                cpa(sb + ((3 + nb) * ATW + r * SH + c * 4) * 4, g_k2 + go);
                cpa(sb + ((5 + nb) * ATW + r * SH + c * 4) * 4,
                    g_vT + (size_t)(hoff + r) * TT + sn * 64 + c * 8);
            }
            cpcommit();
            cpwait<1>();
        } else cpwait<0>();
        __syncthreads();
        uint32_t regK  = (1 + buf) * ATW;
        uint32_t regK2 = (3 + buf) * ATW;
        uint32_t regV  = (5 + buf) * ATW;

        float s1[4][4] = {}, s2[4][4] = {};
        #pragma unroll
        for (int kk = 0; kk < 4; kk++) {
            int kb = kk * 8;
            uint32_t aq2[4], k01[4], k23[4], l01[4], l23[4];
            ldsm4(aq2, sb + (0 + a_off + kb) * 4);
            ldsm4(k01, sb + (regK + bk_off + kb) * 4);
            ldsm4(k23, sb + (regK + bk_off + 16 * SH + kb) * 4);
            ldsm4(l01, sb + (regK2 + bk_off + kb) * 4);
            ldsm4(l23, sb + (regK2 + bk_off + 16 * SH + kb) * 4);
            mma16(s1[0], aq[kk], k01); mma16(s1[1], aq[kk], k01 + 2);
            mma16(s1[2], aq[kk], k23); mma16(s1[3], aq[kk], k23 + 2);
            mma16(s2[0], aq2, l01); mma16(s2[1], aq2, l01 + 2);
            mma16(s2[2], aq2, l23); mma16(s2[3], aq2, l23 + 2);
        }

        uint32_t pa[2][4];
        #pragma unroll
        for (int kc = 0; kc < 2; kc++) {
            #pragma unroll
            for (int sub = 0; sub < 2; sub++) {
                int nt = 2 * kc + sub;
                float p0 = s1[nt][0] * s2[nt][0] * (1.f / 4096.f);
                float p1 = s1[nt][1] * s2[nt][1] * (1.f / 4096.f);
                float p2 = s1[nt][2] * s2[nt][2] * (1.f / 4096.f);
                float p3 = s1[nt][3] * s2[nt][3] * (1.f / 4096.f);
                if (st == qt) {
                    int rlo = wm + g, rhi = rlo + 8;
                    int sc = wn + nt * 8 + 2 * t;
                    if (sc > rlo) p0 = 0.f;
                    if (sc + 1 > rlo) p1 = 0.f;
                    if (sc > rhi) p2 = 0.f;
                    if (sc + 1 > rhi) p3 = 0.f;
                }
                pa[kc][sub * 2]     = packh(p0, p1);
                pa[kc][sub * 2 + 1] = packh(p2, p3);
            }
        }

        #pragma unroll
        for (int kc = 0; kc < 2; kc++) {
            int kw = wnp + kc * 8;
            uint32_t v01[4], v23[4], v45[4], v67[4];
            ldsm4(v01, sb + (regV + v_off + kw) * 4);
            ldsm4(v23, sb + (regV + v_off + 16 * SH + kw) * 4);
            ldsm4(v45, sb + (regV + v_off + 32 * SH + kw) * 4);
            ldsm4(v67, sb + (regV + v_off + 48 * SH + kw) * 4);
            mma16(zacc[0], pa[kc], v01); mma16(zacc[1], pa[kc], v01 + 2);
            mma16(zacc[2], pa[kc], v23); mma16(zacc[3], pa[kc], v23 + 2);
            mma16(zacc[4], pa[kc], v45); mma16(zacc[5], pa[kc], v45 + 2);
            mma16(zacc[6], pa[kc], v67); mma16(zacc[7], pa[kc], v67 + 2);
        }
        __syncthreads();
    }

    float* Sg = (float*)(sm + 1 * ATW);
    if (wh == 1) {
        #pragma unroll
        for (int nt = 0; nt < 8; nt++) {
            int c = nt * 8 + 2 * t;
            #pragma unroll
            for (int half = 0; half < 2; half++) {
                int r = wm + g + half * 8;
                *(float2*)(Sg + r * 68 + c) =
                    make_float2(zacc[nt][half * 2], zacc[nt][half * 2 + 1]);
            }
        }
    }
    __syncthreads();
    if (wh == 0) {
        #pragma unroll
        for (int nt = 0; nt < 8; nt++) {
            int c = nt * 8 + 2 * t;
            #pragma unroll
            for (int half = 0; half < 2; half++) {
                int rl = wm + g + half * 8;
                float2 o = *(float2*)(Sg + rl * 68 + c);
                int r = qt * 64 + rl;
                *(uint32_t*)(g_z + (size_t)r * DM + hoff + c) =
                    packh(zacc[nt][half * 2] + o.x, zacc[nt][half * 2 + 1] + o.y);
            }
        }
    }
}

// ---------------- launch ----------------
extern "C" void kernel_launch(void* const* d_in, const int* in_sizes, int n_in,
                              void* d_out, int out_size) {
    const float* x = (const float*)d_in[0];
    const float* bd = (const float*)d_in[10];

    __half *z_p, *hWo_p, *hidden_p, *hWd_p, *h_p, *h2_p;
    float* x1_p;
    cudaGetSymbolAddress((void**)&z_p, g_z);
    cudaGetSymbolAddress((void**)&hWo_p, hWo);
    cudaGetSymbolAddress((void**)&hidden_p, g_hidden);
    cudaGetSymbolAddress((void**)&hWd_p, hWd);
    cudaGetSymbolAddress((void**)&x1_p, g_x1);
    cudaGetSymbolAddress((void**)&h_p, g_h);
    cudaGetSymbolAddress((void**)&h2_p, g_h2);

    cudaFuncSetAttribute(gemm_proj, cudaFuncAttributeMaxDynamicSharedMemorySize, GEMM2_SMEM);
    cudaFuncSetAttribute(gemm_hf64, cudaFuncAttributeMaxDynamicSharedMemorySize, GEMM64_SMEM);
    cudaFuncSetAttribute(gemm_dual, cudaFuncAttributeMaxDynamicSharedMemorySize, DUAL_SMEM);
    cudaFuncSetAttribute(attn_h, cudaFuncAttributeMaxDynamicSharedMemorySize, ATT_SMEM);

    W9 w;
    for (int i = 0; i < 9; i++) w.s[i] = (const float*)d_in[1 + i];
    cvtw_all<<<(NF4 + 255) / 256, 256>>>(w);

    rmsnorm_w<<<TT / 8, 256>>>(x, h_p);
    gemm_proj<<<dim3(30, TT / 128), 256, GEMM2_SMEM>>>();         // projections + RoPE fused
    attn_h<<<dim3(TT / 64, NH), 256, ATT_SMEM>>>();
    gemm_hf64<<<dim3(DM / 64, TT / 64), 256, GEMM64_SMEM>>>(z_p, hWo_p, x1_p, DM, x, nullptr);
    rmsnorm_w<<<TT / 8, 256>>>(x1_p, h2_p);
    gemm_dual<<<dim3(DHID / 64, TT / 128), 256, DUAL_SMEM>>>();
    gemm_hf64<<<dim3(DM / 64, TT / 64), 256, GEMM64_SMEM>>>(hidden_p, hWd_p, (float*)d_out, DHID, x1_p, bd);
}